// round 1
// baseline (speedup 1.0000x reference)
#include <cuda_runtime.h>

#define M_TOK 8192
#define DMODEL 768
#define DINNER 1536
#define CONVD  1792
#define NH     24
#define HD     64
#define DST    128
#define NPROJ  3352
#define LSEQ   2048

// scratch (device globals: no allocation allowed in kernel_launch)
__device__ float g_zx[M_TOK * NPROJ];    // in_proj output (z | xBC | dt)
__device__ float g_xc[M_TOK * CONVD];    // conv+silu output (xh | B | C)
__device__ float g_dt[M_TOK * NH];
__device__ float g_dA[M_TOK * NH];
__device__ float g_y [M_TOK * DINNER];   // scan output + D skip
__device__ float g_yn[M_TOK * DINNER];   // gated + normalized

typedef unsigned long long ull;

__device__ __forceinline__ ull pk2(float x, float y) {
    ull r; asm("mov.b64 %0,{%1,%2};" : "=l"(r) : "f"(x), "f"(y)); return r;
}
__device__ __forceinline__ float2 upk2(ull v) {
    float2 r; asm("mov.b64 {%0,%1},%2;" : "=f"(r.x), "=f"(r.y) : "l"(v)); return r;
}
__device__ __forceinline__ ull f2fma(ull a, ull b, ull c) {
    ull d; asm("fma.rn.f32x2 %0,%1,%2,%3;" : "=l"(d) : "l"(a), "l"(b), "l"(c)); return d;
}
__device__ __forceinline__ ull f2mul(ull a, ull b) {
    ull d; asm("mul.rn.f32x2 %0,%1,%2;" : "=l"(d) : "l"(a), "l"(b)); return d;
}

// ---------------------------------------------------------------------------
// SGEMM (NT): C[m,n] = sum_k A[m,k] * W[n,k]  (+ R[m,n] if ADD)
// 128x128x16 tile, 256 threads, 8x8 microtile, f32x2 packed accumulation.
// M multiple of 128, K multiple of 16; N guarded.
// ---------------------------------------------------------------------------
template<bool ADD>
__global__ __launch_bounds__(256, 2)
void sgemm_nt(const float* __restrict__ A, const float* __restrict__ W,
              const float* __restrict__ R, float* __restrict__ C,
              int M, int N, int K)
{
    __shared__ __align__(16) float As[16][128];
    __shared__ __align__(16) float Ws[16][128];

    int tid = threadIdx.x;
    int tx = tid & 15, ty = tid >> 4;
    int n0 = blockIdx.x * 128, m0 = blockIdx.y * 128;

    ull acc[8][4];
#pragma unroll
    for (int r = 0; r < 8; r++)
#pragma unroll
        for (int c = 0; c < 4; c++) acc[r][c] = 0ull;

    for (int k0 = 0; k0 < K; k0 += 16) {
#pragma unroll
        for (int i = 0; i < 2; i++) {
            int idx = tid + i * 256;
            int row = idx >> 2, kq = idx & 3;
            float4 v = *(const float4*)&A[(size_t)(m0 + row) * K + k0 + kq * 4];
            As[kq * 4 + 0][row] = v.x; As[kq * 4 + 1][row] = v.y;
            As[kq * 4 + 2][row] = v.z; As[kq * 4 + 3][row] = v.w;
        }
#pragma unroll
        for (int i = 0; i < 2; i++) {
            int idx = tid + i * 256;
            int row = idx >> 2, kq = idx & 3;
            int n = n0 + row;
            float4 v = make_float4(0.f, 0.f, 0.f, 0.f);
            if (n < N) v = *(const float4*)&W[(size_t)n * K + k0 + kq * 4];
            Ws[kq * 4 + 0][row] = v.x; Ws[kq * 4 + 1][row] = v.y;
            Ws[kq * 4 + 2][row] = v.z; Ws[kq * 4 + 3][row] = v.w;
        }
        __syncthreads();

#pragma unroll
        for (int k = 0; k < 16; k++) {
            float a[8];
            *(float4*)&a[0] = *(const float4*)&As[k][ty * 8];
            *(float4*)&a[4] = *(const float4*)&As[k][ty * 8 + 4];
            ull b[4];
            const ull* wp = (const ull*)&Ws[k][tx * 8];
            b[0] = wp[0]; b[1] = wp[1]; b[2] = wp[2]; b[3] = wp[3];
#pragma unroll
            for (int r = 0; r < 8; r++) {
                ull a2 = pk2(a[r], a[r]);
#pragma unroll
                for (int c = 0; c < 4; c++) acc[r][c] = f2fma(a2, b[c], acc[r][c]);
            }
        }
        __syncthreads();
    }

#pragma unroll
    for (int r = 0; r < 8; r++) {
        int gm = m0 + ty * 8 + r;
#pragma unroll
        for (int c = 0; c < 4; c++) {
            float2 v = upk2(acc[r][c]);
            int gn = n0 + tx * 8 + c * 2;
            if (gn < N) {
                size_t o = (size_t)gm * N + gn;
                C[o] = ADD ? (v.x + R[o]) : v.x;
            }
            if (gn + 1 < N) {
                size_t o = (size_t)gm * N + gn + 1;
                C[o] = ADD ? (v.y + R[o]) : v.y;
            }
        }
    }
}

// ---------------------------------------------------------------------------
// Causal depthwise conv1d (kernel 4) + SiLU over xBC channels of g_zx
// ---------------------------------------------------------------------------
__global__ void conv_silu(const float* __restrict__ cw, const float* __restrict__ cb)
{
    int idx = blockIdx.x * blockDim.x + threadIdx.x;
    if (idx >= M_TOK * CONVD) return;
    int c = idx % CONVD, m = idx / CONVD;
    int l = m & (LSEQ - 1);
    float acc = cb[c];
#pragma unroll
    for (int k = 0; k < 4; k++) {
        int ll = l - 3 + k;
        if (ll >= 0)
            acc = fmaf(g_zx[(size_t)(m - 3 + k) * NPROJ + DINNER + c], cw[c * 4 + k], acc);
    }
    float s = 1.f / (1.f + __expf(-acc));
    g_xc[idx] = acc * s;
}

// ---------------------------------------------------------------------------
// dt = softplus(dt_raw + dt_bias); dA = exp(dt * (-exp(A_log)))
// ---------------------------------------------------------------------------
__global__ void dt_dA(const float* __restrict__ dtb, const float* __restrict__ alog)
{
    int idx = blockIdx.x * blockDim.x + threadIdx.x;
    if (idx >= M_TOK * NH) return;
    int h = idx % NH, m = idx / NH;
    float v = g_zx[(size_t)m * NPROJ + DINNER + CONVD + h] + dtb[h];
    float sp = fmaxf(v, 0.f) + log1pf(expf(-fabsf(v)));   // stable softplus
    float A = -expf(alog[h]);
    g_dt[idx] = sp;
    g_dA[idx] = expf(sp * A);
}

// ---------------------------------------------------------------------------
// Selective SSM scan. One CTA per (b,h). 512 threads; thread owns
// (p = tid>>3, n in [nb*16, nb*16+16)) -> 8 f32x2 state regs.
// Double-buffered SMEM staging of (x[64] | B[128] | C[128] | dt | dA).
// ---------------------------------------------------------------------------
__global__ __launch_bounds__(512, 1)
void scan_kernel(const float* __restrict__ Dv)
{
    __shared__ __align__(16) float sh[2][336];
    int bh = blockIdx.x;          // 0..95
    int b = bh / NH, h = bh % NH;
    int tid = threadIdx.x;
    int p = tid >> 3, nb = tid & 7;
    float Dh = Dv[h];

    ull s[8];
#pragma unroll
    for (int i = 0; i < 8; i++) s[i] = 0ull;

    auto load = [&](int buf, int l) {
        int m = b * LSEQ + l;
        if (tid < 64)        sh[buf][tid] = g_xc[(size_t)m * CONVD + h * HD + tid];
        else if (tid < 192)  sh[buf][tid] = g_xc[(size_t)m * CONVD + DINNER + (tid - 64)];
        else if (tid < 320)  sh[buf][tid] = g_xc[(size_t)m * CONVD + DINNER + DST + (tid - 192)];
        else if (tid == 320) sh[buf][320] = g_dt[(size_t)m * NH + h];
        else if (tid == 321) sh[buf][321] = g_dA[(size_t)m * NH + h];
    };

    load(0, 0);
    __syncthreads();

    for (int l = 0; l < LSEQ; l++) {
        int cur = l & 1;
        if (l + 1 < LSEQ) load(cur ^ 1, l + 1);   // prefetch next step

        const float* bp = sh[cur];
        float xp  = bp[p];
        float dt  = bp[320], dA = bp[321];
        float dtx = dt * xp;
        ull dA2  = pk2(dA, dA);
        ull dtx2 = pk2(dtx, dtx);
        const ull* B2 = (const ull*)(bp + 64  + nb * 16);
        const ull* C2 = (const ull*)(bp + 192 + nb * 16);

        ull acc2 = 0ull;
#pragma unroll
        for (int i = 0; i < 8; i++) {
            s[i]  = f2fma(s[i], dA2, f2mul(dtx2, B2[i]));
            acc2  = f2fma(s[i], C2[i], acc2);
        }
        float2 av = upk2(acc2);
        float acc = av.x + av.y;
        acc += __shfl_xor_sync(0xffffffffu, acc, 1);
        acc += __shfl_xor_sync(0xffffffffu, acc, 2);
        acc += __shfl_xor_sync(0xffffffffu, acc, 4);
        if (nb == 0) {
            int m = b * LSEQ + l;
            g_y[(size_t)m * DINNER + h * HD + p] = acc + Dh * xp;
        }
        __syncthreads();
    }
}

// ---------------------------------------------------------------------------
// y = y * silu(z); rmsnorm over 1536; * norm_w
// ---------------------------------------------------------------------------
__global__ __launch_bounds__(256)
void gate_norm(const float* __restrict__ nw)
{
    __shared__ float warpsum[8];
    __shared__ float stot;
    int m = blockIdx.x;
    int tid = threadIdx.x;
    float vals[6];
    float ss = 0.f;
#pragma unroll
    for (int j = 0; j < 6; j++) {
        int i = tid + j * 256;
        float yv = g_y[(size_t)m * DINNER + i];
        float zv = g_zx[(size_t)m * NPROJ + i];
        float g = zv / (1.f + __expf(-zv));
        float v = yv * g;
        vals[j] = v;
        ss = fmaf(v, v, ss);
    }
#pragma unroll
    for (int o = 16; o > 0; o >>= 1) ss += __shfl_xor_sync(0xffffffffu, ss, o);
    if ((tid & 31) == 0) warpsum[tid >> 5] = ss;
    __syncthreads();
    if (tid == 0) {
        float t = 0.f;
#pragma unroll
        for (int w = 0; w < 8; w++) t += warpsum[w];
        stot = t;
    }
    __syncthreads();
    float scale = rsqrtf(stot / (float)DINNER + 1e-5f);
#pragma unroll
    for (int j = 0; j < 6; j++) {
        int i = tid + j * 256;
        g_yn[(size_t)m * DINNER + i] = vals[j] * scale * nw[i];
    }
}

// ---------------------------------------------------------------------------
extern "C" void kernel_launch(void* const* d_in, const int* in_sizes, int n_in,
                              void* d_out, int out_size)
{
    const float* x    = (const float*)d_in[0];
    const float* wi   = (const float*)d_in[1];
    const float* cw   = (const float*)d_in[2];
    const float* cb   = (const float*)d_in[3];
    const float* dtb  = (const float*)d_in[4];
    const float* alog = (const float*)d_in[5];
    const float* Dv   = (const float*)d_in[6];
    const float* nw   = (const float*)d_in[7];
    const float* wo   = (const float*)d_in[8];
    float* out = (float*)d_out;

    float *zx, *yn;
    cudaGetSymbolAddress((void**)&zx, g_zx);
    cudaGetSymbolAddress((void**)&yn, g_yn);

    dim3 blk(256);
    sgemm_nt<false><<<dim3((NPROJ + 127) / 128, M_TOK / 128), blk>>>(
        x, wi, nullptr, zx, M_TOK, NPROJ, DMODEL);
    conv_silu<<<(M_TOK * CONVD + 255) / 256, blk>>>(cw, cb);
    dt_dA<<<(M_TOK * NH + 255) / 256, blk>>>(dtb, alog);
    scan_kernel<<<96, 512>>>(Dv);
    gate_norm<<<M_TOK, blk>>>(nw);
    sgemm_nt<true><<<dim3(DMODEL / 128, M_TOK / 128), blk>>>(
        yn, wo, x, out, M_TOK, DMODEL, DINNER);
}

// round 3
// speedup vs baseline: 1.3171x; 1.3171x over previous
#include <cuda_runtime.h>
#include <cuda_bf16.h>
#include <cstdint>

#define M_TOK 8192
#define DMODEL 768
#define DINNER 1536
#define CONVD  1792
#define NH     24
#define HD     64
#define DST    128
#define NPROJ  3352
#define NPAD   3456            // 27 * 128
#define LSEQ   2048

// ---------------- device scratch (no allocation allowed) ----------------
__device__ float g_zx[M_TOK * NPROJ];    // in_proj output (z | xBC | dt)
__device__ float g_xc[M_TOK * CONVD];    // conv+silu output (xh | B | C)
__device__ float g_dt[M_TOK * NH];
__device__ float g_dA[M_TOK * NH];
__device__ float g_y [M_TOK * DINNER];   // scan output + D skip

__device__ __nv_bfloat16 g_Xhi[M_TOK * DMODEL];
__device__ __nv_bfloat16 g_Xlo[M_TOK * DMODEL];
__device__ __nv_bfloat16 g_Wihi[NPAD * DMODEL];
__device__ __nv_bfloat16 g_Wilo[NPAD * DMODEL];
__device__ __nv_bfloat16 g_Yhi[M_TOK * DINNER];
__device__ __nv_bfloat16 g_Ylo[M_TOK * DINNER];
__device__ __nv_bfloat16 g_Wohi[DMODEL * DINNER];
__device__ __nv_bfloat16 g_Wolo[DMODEL * DINNER];

typedef unsigned long long ull;

__device__ __forceinline__ uint32_t smem_u32(const void* p) {
    uint32_t a;
    asm("{ .reg .u64 t; cvta.to.shared.u64 t, %1; cvt.u32.u64 %0, t; }"
        : "=r"(a) : "l"(p));
    return a;
}

__device__ __forceinline__ void cp16(uint32_t dst, const void* src) {
    asm volatile("cp.async.cg.shared.global [%0], [%1], 16;"
                 :: "r"(dst), "l"(src) : "memory");
}
__device__ __forceinline__ void cp_commit() {
    asm volatile("cp.async.commit_group;" ::: "memory");
}
__device__ __forceinline__ void cp_wait0() {
    asm volatile("cp.async.wait_group 0;" ::: "memory");
}
__device__ __forceinline__ void cp_wait1() {
    asm volatile("cp.async.wait_group 1;" ::: "memory");
}

__device__ __forceinline__ void ldmx4(uint32_t* r, uint32_t addr) {
    asm volatile("ldmatrix.sync.aligned.m8n8.x4.shared.b16 {%0,%1,%2,%3}, [%4];"
                 : "=r"(r[0]), "=r"(r[1]), "=r"(r[2]), "=r"(r[3]) : "r"(addr));
}

__device__ __forceinline__ void mma16816(float* c, const uint32_t* a, const uint32_t* b) {
    asm volatile(
        "mma.sync.aligned.m16n8k16.row.col.f32.bf16.bf16.f32 "
        "{%0,%1,%2,%3}, {%4,%5,%6,%7}, {%8,%9}, {%0,%1,%2,%3};"
        : "+f"(c[0]), "+f"(c[1]), "+f"(c[2]), "+f"(c[3])
        : "r"(a[0]), "r"(a[1]), "r"(a[2]), "r"(a[3]), "r"(b[0]), "r"(b[1]));
}

// ---------------------------------------------------------------------------
// Tensor-core GEMM (NT): C[m,n] = sum_k A[m,k]*B[n,k] via bf16 hi/lo 3-pass.
// 128x128 tile, K-chunk 64, double-buffered cp.async, mma.sync m16n8k16.
// ---------------------------------------------------------------------------
#define BK     64
#define LDT_B  144                 // smem row stride bytes (64 bf16 + 8 pad)
#define TILE_B (128 * LDT_B)       // 18432
#define STAGE_B (4 * TILE_B)       // 73728

__global__ __launch_bounds__(256, 1)
void mma_gemm(const __nv_bfloat16* __restrict__ Ahi, const __nv_bfloat16* __restrict__ Alo,
              const __nv_bfloat16* __restrict__ Bhi, const __nv_bfloat16* __restrict__ Blo,
              const float* __restrict__ R, float* __restrict__ C,
              int Nact, int K)
{
    extern __shared__ char smem[];
    uint32_t sb = smem_u32(smem);
    int tid  = threadIdx.x;
    int wid  = tid >> 5, lane = tid & 31;
    int wm   = wid & 3, wn = wid >> 2;        // warp tile: rows wm*32, cols wn*64
    int m0   = blockIdx.y * 128, n0 = blockIdx.x * 128;

    const __nv_bfloat16* srcs[4] = {Ahi, Alo, Bhi, Blo};
    const size_t rowK = (size_t)K * 2;        // bytes per row

    auto load_stage = [&](int s, int k0) {
        uint32_t d0 = sb + s * STAGE_B;
#pragma unroll
        for (int t = 0; t < 4; t++) {
            const char* gb = (const char*)srcs[t] + (size_t)(t < 2 ? m0 : n0) * rowK + k0 * 2;
#pragma unroll
            for (int i = 0; i < 4; i++) {
                int idx = tid + i * 256;
                int row = idx >> 3, ch = idx & 7;
                cp16(d0 + t * TILE_B + row * LDT_B + ch * 16, gb + (size_t)row * rowK + ch * 16);
            }
        }
        cp_commit();
    };

    float acc[2][8][4];
#pragma unroll
    for (int mt = 0; mt < 2; mt++)
#pragma unroll
        for (int nt = 0; nt < 8; nt++)
#pragma unroll
            for (int j = 0; j < 4; j++) acc[mt][nt][j] = 0.f;

    int nch = K / BK;
    load_stage(0, 0);

    // ldmatrix lane-address components (constant across chunks)
    int a_row = wm * 32 + (lane & 7) + ((lane >> 3) & 1) * 8;
    int a_cb  = ((lane >> 4) & 1) * 16;                 // bytes: +8 bf16
    int b_row = wn * 64 + ((lane >> 4) & 1) * 8 + (lane & 7);
    int b_cb  = ((lane >> 3) & 1) * 16;

    for (int c = 0; c < nch; c++) {
        if (c + 1 < nch) { load_stage((c + 1) & 1, (c + 1) * BK); cp_wait1(); }
        else             { cp_wait0(); }
        __syncthreads();

        uint32_t st = sb + (c & 1) * STAGE_B;
        uint32_t Ah = st, Al = st + TILE_B, Bh = st + 2 * TILE_B, Bl = st + 3 * TILE_B;

#pragma unroll
        for (int kk = 0; kk < 4; kk++) {
            int kb = kk * 32;                            // bytes: kk*16 bf16
            uint32_t ah[2][4], al[2][4];
#pragma unroll
            for (int mt = 0; mt < 2; mt++) {
                uint32_t off = (uint32_t)((a_row + mt * 16) * LDT_B + kb + a_cb);
                ldmx4(ah[mt], Ah + off);
                ldmx4(al[mt], Al + off);
            }
            uint32_t bh[8][2], bl[8][2];
#pragma unroll
            for (int q = 0; q < 4; q++) {
                uint32_t off = (uint32_t)((b_row + q * 16) * LDT_B + kb + b_cb);
                uint32_t r[4];
                ldmx4(r, Bh + off);
                bh[2*q][0] = r[0]; bh[2*q][1] = r[1]; bh[2*q+1][0] = r[2]; bh[2*q+1][1] = r[3];
                ldmx4(r, Bl + off);
                bl[2*q][0] = r[0]; bl[2*q][1] = r[1]; bl[2*q+1][0] = r[2]; bl[2*q+1][1] = r[3];
            }
#pragma unroll
            for (int mt = 0; mt < 2; mt++)
#pragma unroll
                for (int nt = 0; nt < 8; nt++) {
                    mma16816(acc[mt][nt], ah[mt], bh[nt]);
                    mma16816(acc[mt][nt], ah[mt], bl[nt]);
                    mma16816(acc[mt][nt], al[mt], bh[nt]);
                }
        }
        __syncthreads();
    }

    // epilogue: c fragment rows l/4 and l/4+8, cols 2*(l&3)
    int l4 = lane >> 2, l2 = (lane & 3) * 2;
#pragma unroll
    for (int mt = 0; mt < 2; mt++) {
        int gm = m0 + wm * 32 + mt * 16 + l4;
#pragma unroll
        for (int nt = 0; nt < 8; nt++) {
            int gn = n0 + wn * 64 + nt * 8 + l2;
            if (gn < Nact) {
                size_t o0 = (size_t)gm * Nact + gn;
                size_t o1 = (size_t)(gm + 8) * Nact + gn;
                float2 v0 = make_float2(acc[mt][nt][0], acc[mt][nt][1]);
                float2 v1 = make_float2(acc[mt][nt][2], acc[mt][nt][3]);
                if (R) {
                    const float2 r0 = *(const float2*)&R[o0];
                    const float2 r1 = *(const float2*)&R[o1];
                    v0.x += r0.x; v0.y += r0.y; v1.x += r1.x; v1.y += r1.y;
                }
                *(float2*)&C[o0] = v0;
                *(float2*)&C[o1] = v1;
            }
        }
    }
}

// ---------------------------------------------------------------------------
// fp32 -> bf16 hi/lo split
// ---------------------------------------------------------------------------
__global__ void split_f32(const float* __restrict__ src,
                          __nv_bfloat16* __restrict__ hi, __nv_bfloat16* __restrict__ lo, int n)
{
    int i = blockIdx.x * blockDim.x + threadIdx.x;
    if (i >= n) return;
    float v = src[i];
    __nv_bfloat16 h = __float2bfloat16_rn(v);
    hi[i] = h;
    lo[i] = __float2bfloat16_rn(v - __bfloat162float(h));
}

__global__ void split_pad_w(const float* __restrict__ w,
                            __nv_bfloat16* __restrict__ hi, __nv_bfloat16* __restrict__ lo,
                            int nsrc, int ntot)
{
    int i = blockIdx.x * blockDim.x + threadIdx.x;
    if (i >= ntot) return;
    float v = (i < nsrc) ? w[i] : 0.f;
    __nv_bfloat16 h = __float2bfloat16_rn(v);
    hi[i] = h;
    lo[i] = __float2bfloat16_rn(v - __bfloat162float(h));
}

// ---------------------------------------------------------------------------
// f32x2 helpers for scan
// ---------------------------------------------------------------------------
__device__ __forceinline__ ull pk2(float x, float y) {
    ull r; asm("mov.b64 %0,{%1,%2};" : "=l"(r) : "f"(x), "f"(y)); return r;
}
__device__ __forceinline__ float2 upk2(ull v) {
    float2 r; asm("mov.b64 {%0,%1},%2;" : "=f"(r.x), "=f"(r.y) : "l"(v)); return r;
}
__device__ __forceinline__ ull f2fma(ull a, ull b, ull c) {
    ull d; asm("fma.rn.f32x2 %0,%1,%2,%3;" : "=l"(d) : "l"(a), "l"(b), "l"(c)); return d;
}
__device__ __forceinline__ ull f2mul(ull a, ull b) {
    ull d; asm("mul.rn.f32x2 %0,%1,%2;" : "=l"(d) : "l"(a), "l"(b)); return d;
}

// ---------------------------------------------------------------------------
// Causal depthwise conv1d (kernel 4) + SiLU over xBC channels of g_zx
// ---------------------------------------------------------------------------
__global__ void conv_silu(const float* __restrict__ cw, const float* __restrict__ cb)
{
    int idx = blockIdx.x * blockDim.x + threadIdx.x;
    if (idx >= M_TOK * CONVD) return;
    int c = idx % CONVD, m = idx / CONVD;
    int l = m & (LSEQ - 1);
    float acc = cb[c];
#pragma unroll
    for (int k = 0; k < 4; k++) {
        int ll = l - 3 + k;
        if (ll >= 0)
            acc = fmaf(g_zx[(size_t)(m - 3 + k) * NPROJ + DINNER + c], cw[c * 4 + k], acc);
    }
    float s = 1.f / (1.f + __expf(-acc));
    g_xc[idx] = acc * s;
}

// ---------------------------------------------------------------------------
__global__ void dt_dA(const float* __restrict__ dtb, const float* __restrict__ alog)
{
    int idx = blockIdx.x * blockDim.x + threadIdx.x;
    if (idx >= M_TOK * NH) return;
    int h = idx % NH, m = idx / NH;
    float v = g_zx[(size_t)m * NPROJ + DINNER + CONVD + h] + dtb[h];
    float sp = fmaxf(v, 0.f) + log1pf(expf(-fabsf(v)));
    float A = -expf(alog[h]);
    g_dt[idx] = sp;
    g_dA[idx] = expf(sp * A);
}

// ---------------------------------------------------------------------------
// Selective SSM scan. One CTA per (b,h).
// ---------------------------------------------------------------------------
__global__ __launch_bounds__(512, 1)
void scan_kernel(const float* __restrict__ Dv)
{
    __shared__ __align__(16) float sh[2][336];
    int bh = blockIdx.x;
    int b = bh / NH, h = bh % NH;
    int tid = threadIdx.x;
    int p = tid >> 3, nb = tid & 7;
    float Dh = Dv[h];

    ull s[8];
#pragma unroll
    for (int i = 0; i < 8; i++) s[i] = 0ull;

    auto load = [&](int buf, int l) {
        int m = b * LSEQ + l;
        if (tid < 64)        sh[buf][tid] = g_xc[(size_t)m * CONVD + h * HD + tid];
        else if (tid < 192)  sh[buf][tid] = g_xc[(size_t)m * CONVD + DINNER + (tid - 64)];
        else if (tid < 320)  sh[buf][tid] = g_xc[(size_t)m * CONVD + DINNER + DST + (tid - 192)];
        else if (tid == 320) sh[buf][320] = g_dt[(size_t)m * NH + h];
        else if (tid == 321) sh[buf][321] = g_dA[(size_t)m * NH + h];
    };

    load(0, 0);
    __syncthreads();

    for (int l = 0; l < LSEQ; l++) {
        int cur = l & 1;
        if (l + 1 < LSEQ) load(cur ^ 1, l + 1);

        const float* bp = sh[cur];
        float xp  = bp[p];
        float dt  = bp[320], dA = bp[321];
        float dtx = dt * xp;
        ull dA2  = pk2(dA, dA);
        ull dtx2 = pk2(dtx, dtx);
        const ull* B2 = (const ull*)(bp + 64  + nb * 16);
        const ull* C2 = (const ull*)(bp + 192 + nb * 16);

        ull acc2 = 0ull;
#pragma unroll
        for (int i = 0; i < 8; i++) {
            s[i] = f2fma(s[i], dA2, f2mul(dtx2, B2[i]));
            acc2 = f2fma(s[i], C2[i], acc2);
        }
        float2 av = upk2(acc2);
        float acc = av.x + av.y;
        acc += __shfl_xor_sync(0xffffffffu, acc, 1);
        acc += __shfl_xor_sync(0xffffffffu, acc, 2);
        acc += __shfl_xor_sync(0xffffffffu, acc, 4);
        if (nb == 0) {
            int m = b * LSEQ + l;
            g_y[(size_t)m * DINNER + h * HD + p] = acc + Dh * xp;
        }
        __syncthreads();
    }
}

// ---------------------------------------------------------------------------
// y = y * silu(z); rmsnorm; * norm_w; emit bf16 hi/lo for out_proj
// ---------------------------------------------------------------------------
__global__ __launch_bounds__(256)
void gate_norm(const float* __restrict__ nw)
{
    __shared__ float warpsum[8];
    __shared__ float stot;
    int m = blockIdx.x;
    int tid = threadIdx.x;
    float vals[6];
    float ss = 0.f;
#pragma unroll
    for (int j = 0; j < 6; j++) {
        int i = tid + j * 256;
        float yv = g_y[(size_t)m * DINNER + i];
        float zv = g_zx[(size_t)m * NPROJ + i];
        float g = zv / (1.f + __expf(-zv));
        float v = yv * g;
        vals[j] = v;
        ss = fmaf(v, v, ss);
    }
#pragma unroll
    for (int o = 16; o > 0; o >>= 1) ss += __shfl_xor_sync(0xffffffffu, ss, o);
    if ((tid & 31) == 0) warpsum[tid >> 5] = ss;
    __syncthreads();
    if (tid == 0) {
        float t = 0.f;
#pragma unroll
        for (int w = 0; w < 8; w++) t += warpsum[w];
        stot = t;
    }
    __syncthreads();
    float scale = rsqrtf(stot / (float)DINNER + 1e-5f);
#pragma unroll
    for (int j = 0; j < 6; j++) {
        int i = tid + j * 256;
        float v = vals[j] * scale * nw[i];
        __nv_bfloat16 hh = __float2bfloat16_rn(v);
        g_Yhi[(size_t)m * DINNER + i] = hh;
        g_Ylo[(size_t)m * DINNER + i] = __float2bfloat16_rn(v - __bfloat162float(hh));
    }
}

// ---------------------------------------------------------------------------
extern "C" void kernel_launch(void* const* d_in, const int* in_sizes, int n_in,
                              void* d_out, int out_size)
{
    const float* x    = (const float*)d_in[0];
    const float* wi   = (const float*)d_in[1];
    const float* cw   = (const float*)d_in[2];
    const float* cb   = (const float*)d_in[3];
    const float* dtb  = (const float*)d_in[4];
    const float* alog = (const float*)d_in[5];
    const float* Dv   = (const float*)d_in[6];
    const float* nw   = (const float*)d_in[7];
    const float* wo   = (const float*)d_in[8];
    float* out = (float*)d_out;

    float *zx;
    __nv_bfloat16 *xhi, *xlo, *wihi, *wilo, *yhi, *ylo, *wohi, *wolo;
    cudaGetSymbolAddress((void**)&zx,   g_zx);
    cudaGetSymbolAddress((void**)&xhi,  g_Xhi);
    cudaGetSymbolAddress((void**)&xlo,  g_Xlo);
    cudaGetSymbolAddress((void**)&wihi, g_Wihi);
    cudaGetSymbolAddress((void**)&wilo, g_Wilo);
    cudaGetSymbolAddress((void**)&yhi,  g_Yhi);
    cudaGetSymbolAddress((void**)&ylo,  g_Ylo);
    cudaGetSymbolAddress((void**)&wohi, g_Wohi);
    cudaGetSymbolAddress((void**)&wolo, g_Wolo);

    static const int smem_bytes = 2 * STAGE_B;  // 144 KB
    cudaFuncSetAttribute(mma_gemm, cudaFuncAttributeMaxDynamicSharedMemorySize, smem_bytes);

    dim3 blk(256);

    // splits
    split_f32<<<(M_TOK * DMODEL + 255) / 256, blk>>>(x, xhi, xlo, M_TOK * DMODEL);
    split_pad_w<<<(NPAD * DMODEL + 255) / 256, blk>>>(wi, wihi, wilo,
                                                      NPROJ * DMODEL, NPAD * DMODEL);
    split_f32<<<(DMODEL * DINNER + 255) / 256, blk>>>(wo, wohi, wolo, DMODEL * DINNER);

    // in_proj: [8192 x 3352] = X[8192x768] @ Wi^T
    mma_gemm<<<dim3(NPAD / 128, M_TOK / 128), blk, smem_bytes>>>(
        xhi, xlo, wihi, wilo, nullptr, zx, NPROJ, DMODEL);

    conv_silu<<<(M_TOK * CONVD + 255) / 256, blk>>>(cw, cb);
    dt_dA<<<(M_TOK * NH + 255) / 256, blk>>>(dtb, alog);
    scan_kernel<<<96, 512>>>(Dv);
    gate_norm<<<M_TOK, blk>>>(nw);

    // out_proj + residual: [8192 x 768] = Y[8192x1536] @ Wo^T + x
    mma_gemm<<<dim3(DMODEL / 128, M_TOK / 128), blk, smem_bytes>>>(
        yhi, ylo, wohi, wolo, x, out, DMODEL, DINNER);
}

// round 4
// speedup vs baseline: 1.3714x; 1.0412x over previous
#include <cuda_runtime.h>
#include <cuda_bf16.h>
#include <cstdint>

#define M_TOK 8192
#define DMODEL 768
#define DINNER 1536
#define CONVD  1792
#define NH     24
#define HD     64
#define DST    128
#define NPROJ  3352
#define NPAD   3456            // 27 * 128
#define LSEQ   2048

// ---------------- device scratch (no allocation allowed) ----------------
__device__ float g_zx[M_TOK * NPROJ];    // in_proj output (z | xBC | dt)
__device__ float g_xc[M_TOK * CONVD];    // conv+silu output (xh | B | C)
__device__ float2 g_dtdA[96 * LSEQ];     // packed (dt, dA) per (b*NH+h, l)
__device__ float g_y [M_TOK * DINNER];   // scan output + D skip

__device__ __nv_bfloat16 g_Xhi[M_TOK * DMODEL];
__device__ __nv_bfloat16 g_Xlo[M_TOK * DMODEL];
__device__ __nv_bfloat16 g_Wihi[NPAD * DMODEL];
__device__ __nv_bfloat16 g_Wilo[NPAD * DMODEL];
__device__ __nv_bfloat16 g_Yhi[M_TOK * DINNER];
__device__ __nv_bfloat16 g_Ylo[M_TOK * DINNER];
__device__ __nv_bfloat16 g_Wohi[DMODEL * DINNER];
__device__ __nv_bfloat16 g_Wolo[DMODEL * DINNER];

typedef unsigned long long ull;

__device__ __forceinline__ uint32_t smem_u32(const void* p) {
    uint32_t a;
    asm("{ .reg .u64 t; cvta.to.shared.u64 t, %1; cvt.u32.u64 %0, t; }"
        : "=r"(a) : "l"(p));
    return a;
}

__device__ __forceinline__ void cp16(uint32_t dst, const void* src) {
    asm volatile("cp.async.cg.shared.global [%0], [%1], 16;"
                 :: "r"(dst), "l"(src) : "memory");
}
__device__ __forceinline__ void cp8(uint32_t dst, const void* src) {
    asm volatile("cp.async.ca.shared.global [%0], [%1], 8;"
                 :: "r"(dst), "l"(src) : "memory");
}
__device__ __forceinline__ void cp_commit() {
    asm volatile("cp.async.commit_group;" ::: "memory");
}
__device__ __forceinline__ void cp_wait0() {
    asm volatile("cp.async.wait_group 0;" ::: "memory");
}
__device__ __forceinline__ void cp_wait1() {
    asm volatile("cp.async.wait_group 1;" ::: "memory");
}
__device__ __forceinline__ void cp_wait6() {
    asm volatile("cp.async.wait_group 6;" ::: "memory");
}

__device__ __forceinline__ void ldmx4(uint32_t* r, uint32_t addr) {
    asm volatile("ldmatrix.sync.aligned.m8n8.x4.shared.b16 {%0,%1,%2,%3}, [%4];"
                 : "=r"(r[0]), "=r"(r[1]), "=r"(r[2]), "=r"(r[3]) : "r"(addr));
}

__device__ __forceinline__ void mma16816(float* c, const uint32_t* a, const uint32_t* b) {
    asm volatile(
        "mma.sync.aligned.m16n8k16.row.col.f32.bf16.bf16.f32 "
        "{%0,%1,%2,%3}, {%4,%5,%6,%7}, {%8,%9}, {%0,%1,%2,%3};"
        : "+f"(c[0]), "+f"(c[1]), "+f"(c[2]), "+f"(c[3])
        : "r"(a[0]), "r"(a[1]), "r"(a[2]), "r"(a[3]), "r"(b[0]), "r"(b[1]));
}

// ---------------------------------------------------------------------------
// Tensor-core GEMM (NT): C[m,n] = sum_k A[m,k]*B[n,k] via bf16 hi/lo 3-pass.
// 128x128 tile, K-chunk 64, double-buffered cp.async, mma.sync m16n8k16.
// ---------------------------------------------------------------------------
#define BK     64
#define LDT_B  144                 // smem row stride bytes (64 bf16 + 8 pad)
#define TILE_B (128 * LDT_B)       // 18432
#define STAGE_B (4 * TILE_B)       // 73728

__global__ __launch_bounds__(256, 1)
void mma_gemm(const __nv_bfloat16* __restrict__ Ahi, const __nv_bfloat16* __restrict__ Alo,
              const __nv_bfloat16* __restrict__ Bhi, const __nv_bfloat16* __restrict__ Blo,
              const float* __restrict__ R, float* __restrict__ C,
              int Nact, int K)
{
    extern __shared__ char smem[];
    uint32_t sb = smem_u32(smem);
    int tid  = threadIdx.x;
    int wid  = tid >> 5, lane = tid & 31;
    int wm   = wid & 3, wn = wid >> 2;
    int m0   = blockIdx.y * 128, n0 = blockIdx.x * 128;

    const __nv_bfloat16* srcs[4] = {Ahi, Alo, Bhi, Blo};
    const size_t rowK = (size_t)K * 2;

    auto load_stage = [&](int s, int k0) {
        uint32_t d0 = sb + s * STAGE_B;
#pragma unroll
        for (int t = 0; t < 4; t++) {
            const char* gb = (const char*)srcs[t] + (size_t)(t < 2 ? m0 : n0) * rowK + k0 * 2;
#pragma unroll
            for (int i = 0; i < 4; i++) {
                int idx = tid + i * 256;
                int row = idx >> 3, ch = idx & 7;
                cp16(d0 + t * TILE_B + row * LDT_B + ch * 16, gb + (size_t)row * rowK + ch * 16);
            }
        }
        cp_commit();
    };

    float acc[2][8][4];
#pragma unroll
    for (int mt = 0; mt < 2; mt++)
#pragma unroll
        for (int nt = 0; nt < 8; nt++)
#pragma unroll
            for (int j = 0; j < 4; j++) acc[mt][nt][j] = 0.f;

    int nch = K / BK;
    load_stage(0, 0);

    int a_row = wm * 32 + (lane & 7) + ((lane >> 3) & 1) * 8;
    int a_cb  = ((lane >> 4) & 1) * 16;
    int b_row = wn * 64 + ((lane >> 4) & 1) * 8 + (lane & 7);
    int b_cb  = ((lane >> 3) & 1) * 16;

    for (int c = 0; c < nch; c++) {
        if (c + 1 < nch) { load_stage((c + 1) & 1, (c + 1) * BK); cp_wait1(); }
        else             { cp_wait0(); }
        __syncthreads();

        uint32_t st = sb + (c & 1) * STAGE_B;
        uint32_t Ah = st, Al = st + TILE_B, Bh = st + 2 * TILE_B, Bl = st + 3 * TILE_B;

#pragma unroll
        for (int kk = 0; kk < 4; kk++) {
            int kb = kk * 32;
            uint32_t ah[2][4], al[2][4];
#pragma unroll
            for (int mt = 0; mt < 2; mt++) {
                uint32_t off = (uint32_t)((a_row + mt * 16) * LDT_B + kb + a_cb);
                ldmx4(ah[mt], Ah + off);
                ldmx4(al[mt], Al + off);
            }
            uint32_t bh[8][2], bl[8][2];
#pragma unroll
            for (int q = 0; q < 4; q++) {
                uint32_t off = (uint32_t)((b_row + q * 16) * LDT_B + kb + b_cb);
                uint32_t r[4];
                ldmx4(r, Bh + off);
                bh[2*q][0] = r[0]; bh[2*q][1] = r[1]; bh[2*q+1][0] = r[2]; bh[2*q+1][1] = r[3];
                ldmx4(r, Bl + off);
                bl[2*q][0] = r[0]; bl[2*q][1] = r[1]; bl[2*q+1][0] = r[2]; bl[2*q+1][1] = r[3];
            }
#pragma unroll
            for (int mt = 0; mt < 2; mt++)
#pragma unroll
                for (int nt = 0; nt < 8; nt++) {
                    mma16816(acc[mt][nt], ah[mt], bh[nt]);
                    mma16816(acc[mt][nt], ah[mt], bl[nt]);
                    mma16816(acc[mt][nt], al[mt], bh[nt]);
                }
        }
        __syncthreads();
    }

    int l4 = lane >> 2, l2 = (lane & 3) * 2;
#pragma unroll
    for (int mt = 0; mt < 2; mt++) {
        int gm = m0 + wm * 32 + mt * 16 + l4;
#pragma unroll
        for (int nt = 0; nt < 8; nt++) {
            int gn = n0 + wn * 64 + nt * 8 + l2;
            if (gn < Nact) {
                size_t o0 = (size_t)gm * Nact + gn;
                size_t o1 = (size_t)(gm + 8) * Nact + gn;
                float2 v0 = make_float2(acc[mt][nt][0], acc[mt][nt][1]);
                float2 v1 = make_float2(acc[mt][nt][2], acc[mt][nt][3]);
                if (R) {
                    const float2 r0 = *(const float2*)&R[o0];
                    const float2 r1 = *(const float2*)&R[o1];
                    v0.x += r0.x; v0.y += r0.y; v1.x += r1.x; v1.y += r1.y;
                }
                *(float2*)&C[o0] = v0;
                *(float2*)&C[o1] = v1;
            }
        }
    }
}

// ---------------------------------------------------------------------------
// fp32 -> bf16 hi/lo split
// ---------------------------------------------------------------------------
__global__ void split_f32(const float* __restrict__ src,
                          __nv_bfloat16* __restrict__ hi, __nv_bfloat16* __restrict__ lo, int n)
{
    int i = blockIdx.x * blockDim.x + threadIdx.x;
    if (i >= n) return;
    float v = src[i];
    __nv_bfloat16 h = __float2bfloat16_rn(v);
    hi[i] = h;
    lo[i] = __float2bfloat16_rn(v - __bfloat162float(h));
}

__global__ void split_pad_w(const float* __restrict__ w,
                            __nv_bfloat16* __restrict__ hi, __nv_bfloat16* __restrict__ lo,
                            int nsrc, int ntot)
{
    int i = blockIdx.x * blockDim.x + threadIdx.x;
    if (i >= ntot) return;
    float v = (i < nsrc) ? w[i] : 0.f;
    __nv_bfloat16 h = __float2bfloat16_rn(v);
    hi[i] = h;
    lo[i] = __float2bfloat16_rn(v - __bfloat162float(h));
}

// ---------------------------------------------------------------------------
// f32x2 helpers
// ---------------------------------------------------------------------------
__device__ __forceinline__ ull pk2(float x, float y) {
    ull r; asm("mov.b64 %0,{%1,%2};" : "=l"(r) : "f"(x), "f"(y)); return r;
}
__device__ __forceinline__ float2 upk2(ull v) {
    float2 r; asm("mov.b64 {%0,%1},%2;" : "=f"(r.x), "=f"(r.y) : "l"(v)); return r;
}
__device__ __forceinline__ ull f2fma(ull a, ull b, ull c) {
    ull d; asm("fma.rn.f32x2 %0,%1,%2,%3;" : "=l"(d) : "l"(a), "l"(b), "l"(c)); return d;
}
__device__ __forceinline__ ull f2mul(ull a, ull b) {
    ull d; asm("mul.rn.f32x2 %0,%1,%2;" : "=l"(d) : "l"(a), "l"(b)); return d;
}

// ---------------------------------------------------------------------------
// Causal depthwise conv1d (kernel 4) + SiLU over xBC channels of g_zx
// ---------------------------------------------------------------------------
__global__ void conv_silu(const float* __restrict__ cw, const float* __restrict__ cb)
{
    int idx = blockIdx.x * blockDim.x + threadIdx.x;
    if (idx >= M_TOK * CONVD) return;
    int c = idx % CONVD, m = idx / CONVD;
    int l = m & (LSEQ - 1);
    float acc = cb[c];
#pragma unroll
    for (int k = 0; k < 4; k++) {
        int ll = l - 3 + k;
        if (ll >= 0)
            acc = fmaf(g_zx[(size_t)(m - 3 + k) * NPROJ + DINNER + c], cw[c * 4 + k], acc);
    }
    float s = 1.f / (1.f + __expf(-acc));
    g_xc[idx] = acc * s;
}

// ---------------------------------------------------------------------------
// dt = softplus(dt_raw + dt_bias); dA = exp(dt*A); packed (dt,dA) per (b,h,l)
// ---------------------------------------------------------------------------
__global__ void dt_dA(const float* __restrict__ dtb, const float* __restrict__ alog)
{
    int idx = blockIdx.x * blockDim.x + threadIdx.x;
    if (idx >= M_TOK * NH) return;
    int h = idx % NH, m = idx / NH;
    int b = m / LSEQ, l = m % LSEQ;
    float v = g_zx[(size_t)m * NPROJ + DINNER + CONVD + h] + dtb[h];
    float sp = fmaxf(v, 0.f) + log1pf(expf(-fabsf(v)));
    float A = -expf(alog[h]);
    g_dtdA[(size_t)(b * NH + h) * LSEQ + l] = make_float2(sp, expf(sp * A));
}

// ---------------------------------------------------------------------------
// Selective SSM scan. One CTA per (b,h). 8-stage cp.async ring, 1 bar/step.
// Stage layout (floats): x[0..63] | B[64..191] | C[192..319] | dt,dA[320,321]
// ---------------------------------------------------------------------------
#define NSTG 8
#define STGF 336                   // floats per stage (1344 B)

__global__ __launch_bounds__(512, 1)
void scan_kernel(const float* __restrict__ Dv)
{
    __shared__ __align__(16) float sh[NSTG][STGF];
    uint32_t sb = smem_u32(sh);
    int bh = blockIdx.x;
    int b = bh / NH, h = bh % NH;
    int tid = threadIdx.x;
    int p = tid >> 3, nb = tid & 7;
    float Dh = Dv[h];

    // per-thread loader setup
    const char* src = nullptr;
    uint32_t dsto = 0;
    size_t stride = (size_t)CONVD * 4;
    const char* xcb = (const char*)(g_xc + (size_t)b * LSEQ * CONVD);
    if (tid < 16)       { src = xcb + (size_t)h * HD * 4 + tid * 16;            dsto = tid * 16; }
    else if (tid < 48)  { src = xcb + (size_t)DINNER * 4 + (tid - 16) * 16;     dsto = 256 + (tid - 16) * 16; }
    else if (tid < 80)  { src = xcb + (size_t)(DINNER + DST) * 4 + (tid - 48) * 16; dsto = 768 + (tid - 48) * 16; }
    else if (tid == 80) { src = (const char*)(g_dtdA + (size_t)bh * LSEQ);      dsto = 1280; stride = 8; }

    auto issue = [&](int step) {
        if (step < LSEQ) {
            uint32_t d = sb + (uint32_t)((step & (NSTG - 1)) * (STGF * 4)) + dsto;
            if (tid < 80)       { cp16(d, src); src += stride; }
            else if (tid == 80) { cp8(d, src);  src += stride; }
        }
        cp_commit();
    };

#pragma unroll
    for (int s = 0; s < NSTG - 1; s++) issue(s);   // stages 0..6

    ull st[8];
#pragma unroll
    for (int i = 0; i < 8; i++) st[i] = 0ull;

    float* ybase = g_y + (size_t)b * LSEQ * DINNER + h * HD + p;

    for (int l = 0; l < LSEQ; l++) {
        cp_wait6();            // stage l complete (7 groups outstanding -> 6)
        __syncthreads();       // data visible to all; prev compute finished
        issue(l + NSTG - 1);   // overwrite slot consumed at iteration l-1

        const float* bp = sh[l & (NSTG - 1)];
        float xp  = bp[p];
        float dt  = bp[320], dA = bp[321];
        float dtx = dt * xp;
        ull dA2  = pk2(dA, dA);
        ull dtx2 = pk2(dtx, dtx);
        const ull* B2 = (const ull*)(bp + 64  + nb * 16);
        const ull* C2 = (const ull*)(bp + 192 + nb * 16);

        ull acc2 = 0ull;
#pragma unroll
        for (int i = 0; i < 8; i++) {
            st[i] = f2fma(st[i], dA2, f2mul(dtx2, B2[i]));
            acc2  = f2fma(st[i], C2[i], acc2);
        }
        float2 av = upk2(acc2);
        float acc = av.x + av.y;
        acc += __shfl_xor_sync(0xffffffffu, acc, 1);
        acc += __shfl_xor_sync(0xffffffffu, acc, 2);
        acc += __shfl_xor_sync(0xffffffffu, acc, 4);
        if (nb == 0)
            ybase[(size_t)l * DINNER] = acc + Dh * xp;
    }
}

// ---------------------------------------------------------------------------
// y = y * silu(z); rmsnorm; * norm_w; emit bf16 hi/lo for out_proj
// ---------------------------------------------------------------------------
__global__ __launch_bounds__(256)
void gate_norm(const float* __restrict__ nw)
{
    __shared__ float warpsum[8];
    __shared__ float stot;
    int m = blockIdx.x;
    int tid = threadIdx.x;
    float vals[6];
    float ss = 0.f;
#pragma unroll
    for (int j = 0; j < 6; j++) {
        int i = tid + j * 256;
        float yv = g_y[(size_t)m * DINNER + i];
        float zv = g_zx[(size_t)m * NPROJ + i];
        float g = zv / (1.f + __expf(-zv));
        float v = yv * g;
        vals[j] = v;
        ss = fmaf(v, v, ss);
    }
#pragma unroll
    for (int o = 16; o > 0; o >>= 1) ss += __shfl_xor_sync(0xffffffffu, ss, o);
    if ((tid & 31) == 0) warpsum[tid >> 5] = ss;
    __syncthreads();
    if (tid == 0) {
        float t = 0.f;
#pragma unroll
        for (int w = 0; w < 8; w++) t += warpsum[w];
        stot = t;
    }
    __syncthreads();
    float scale = rsqrtf(stot / (float)DINNER + 1e-5f);
#pragma unroll
    for (int j = 0; j < 6; j++) {
        int i = tid + j * 256;
        float v = vals[j] * scale * nw[i];
        __nv_bfloat16 hh = __float2bfloat16_rn(v);
        g_Yhi[(size_t)m * DINNER + i] = hh;
        g_Ylo[(size_t)m * DINNER + i] = __float2bfloat16_rn(v - __bfloat162float(hh));
    }
}

// ---------------------------------------------------------------------------
extern "C" void kernel_launch(void* const* d_in, const int* in_sizes, int n_in,
                              void* d_out, int out_size)
{
    const float* x    = (const float*)d_in[0];
    const float* wi   = (const float*)d_in[1];
    const float* cw   = (const float*)d_in[2];
    const float* cb   = (const float*)d_in[3];
    const float* dtb  = (const float*)d_in[4];
    const float* alog = (const float*)d_in[5];
    const float* Dv   = (const float*)d_in[6];
    const float* nw   = (const float*)d_in[7];
    const float* wo   = (const float*)d_in[8];
    float* out = (float*)d_out;

    float *zx;
    __nv_bfloat16 *xhi, *xlo, *wihi, *wilo, *yhi, *ylo, *wohi, *wolo;
    cudaGetSymbolAddress((void**)&zx,   g_zx);
    cudaGetSymbolAddress((void**)&xhi,  g_Xhi);
    cudaGetSymbolAddress((void**)&xlo,  g_Xlo);
    cudaGetSymbolAddress((void**)&wihi, g_Wihi);
    cudaGetSymbolAddress((void**)&wilo, g_Wilo);
    cudaGetSymbolAddress((void**)&yhi,  g_Yhi);
    cudaGetSymbolAddress((void**)&ylo,  g_Ylo);
    cudaGetSymbolAddress((void**)&wohi, g_Wohi);
    cudaGetSymbolAddress((void**)&wolo, g_Wolo);

    static const int smem_bytes = 2 * STAGE_B;  // 144 KB
    cudaFuncSetAttribute(mma_gemm, cudaFuncAttributeMaxDynamicSharedMemorySize, smem_bytes);

    dim3 blk(256);

    split_f32<<<(M_TOK * DMODEL + 255) / 256, blk>>>(x, xhi, xlo, M_TOK * DMODEL);
    split_pad_w<<<(NPAD * DMODEL + 255) / 256, blk>>>(wi, wihi, wilo,
                                                      NPROJ * DMODEL, NPAD * DMODEL);
    split_f32<<<(DMODEL * DINNER + 255) / 256, blk>>>(wo, wohi, wolo, DMODEL * DINNER);

    mma_gemm<<<dim3(NPAD / 128, M_TOK / 128), blk, smem_bytes>>>(
        xhi, xlo, wihi, wilo, nullptr, zx, NPROJ, DMODEL);

    conv_silu<<<(M_TOK * CONVD + 255) / 256, blk>>>(cw, cb);
    dt_dA<<<(M_TOK * NH + 255) / 256, blk>>>(dtb, alog);
    scan_kernel<<<96, 512>>>(Dv);
    gate_norm<<<M_TOK, blk>>>(nw);

    mma_gemm<<<dim3(DMODEL / 128, M_TOK / 128), blk, smem_bytes>>>(
        yhi, ylo, wohi, wolo, x, out, DMODEL, DINNER);
}

// round 5
// speedup vs baseline: 2.7105x; 1.9765x over previous
#include <cuda_runtime.h>
#include <cuda_bf16.h>
#include <cstdint>

#define M_TOK 8192
#define DMODEL 768
#define DINNER 1536
#define CONVD  1792
#define NH     24
#define HD     64
#define DST    128
#define NPROJ  3352
#define NPAD   3456            // 27 * 128
#define LSEQ   2048

// ---------------- device scratch (no allocation allowed) ----------------
__device__ float g_zx[M_TOK * NPROJ];    // in_proj output (z | xBC | dt)
__device__ float g_xc[M_TOK * CONVD];    // conv+silu output (xh | B | C)
__device__ float2 g_dtdA[96 * LSEQ];     // packed (dt, dA) per (b*NH+h, l)
__device__ float g_y [M_TOK * DINNER];   // scan output + D skip

__device__ __nv_bfloat16 g_Xhi[M_TOK * DMODEL];
__device__ __nv_bfloat16 g_Xlo[M_TOK * DMODEL];
__device__ __nv_bfloat16 g_Wihi[NPAD * DMODEL];
__device__ __nv_bfloat16 g_Wilo[NPAD * DMODEL];
__device__ __nv_bfloat16 g_Yhi[M_TOK * DINNER];
__device__ __nv_bfloat16 g_Ylo[M_TOK * DINNER];
__device__ __nv_bfloat16 g_Wohi[DMODEL * DINNER];
__device__ __nv_bfloat16 g_Wolo[DMODEL * DINNER];

typedef unsigned long long ull;

__device__ __forceinline__ uint32_t smem_u32(const void* p) {
    uint32_t a;
    asm("{ .reg .u64 t; cvta.to.shared.u64 t, %1; cvt.u32.u64 %0, t; }"
        : "=r"(a) : "l"(p));
    return a;
}

__device__ __forceinline__ void cp16(uint32_t dst, const void* src) {
    asm volatile("cp.async.cg.shared.global [%0], [%1], 16;"
                 :: "r"(dst), "l"(src) : "memory");
}
__device__ __forceinline__ void cp8(uint32_t dst, const void* src) {
    asm volatile("cp.async.ca.shared.global [%0], [%1], 8;"
                 :: "r"(dst), "l"(src) : "memory");
}
__device__ __forceinline__ void cp_commit() {
    asm volatile("cp.async.commit_group;" ::: "memory");
}
__device__ __forceinline__ void cp_wait0() {
    asm volatile("cp.async.wait_group 0;" ::: "memory");
}
__device__ __forceinline__ void cp_wait1() {
    asm volatile("cp.async.wait_group 1;" ::: "memory");
}
__device__ __forceinline__ void cp_wait6() {
    asm volatile("cp.async.wait_group 6;" ::: "memory");
}

__device__ __forceinline__ void ldmx4(uint32_t* r, uint32_t addr) {
    asm volatile("ldmatrix.sync.aligned.m8n8.x4.shared.b16 {%0,%1,%2,%3}, [%4];"
                 : "=r"(r[0]), "=r"(r[1]), "=r"(r[2]), "=r"(r[3]) : "r"(addr));
}

__device__ __forceinline__ void mma16816(float* c, const uint32_t* a, const uint32_t* b) {
    asm volatile(
        "mma.sync.aligned.m16n8k16.row.col.f32.bf16.bf16.f32 "
        "{%0,%1,%2,%3}, {%4,%5,%6,%7}, {%8,%9}, {%0,%1,%2,%3};"
        : "+f"(c[0]), "+f"(c[1]), "+f"(c[2]), "+f"(c[3])
        : "r"(a[0]), "r"(a[1]), "r"(a[2]), "r"(a[3]), "r"(b[0]), "r"(b[1]));
}

// ---------------------------------------------------------------------------
// Tensor-core GEMM (NT): C[m,n] = sum_k A[m,k]*B[n,k] via bf16 hi/lo 3-pass.
// 128x128 tile, K-chunk 64, double-buffered cp.async, mma.sync m16n8k16.
// ---------------------------------------------------------------------------
#define BK     64
#define LDT_B  144                 // smem row stride bytes (64 bf16 + 8 pad)
#define TILE_B (128 * LDT_B)       // 18432
#define STAGE_B (4 * TILE_B)       // 73728

__global__ __launch_bounds__(256, 1)
void mma_gemm(const __nv_bfloat16* __restrict__ Ahi, const __nv_bfloat16* __restrict__ Alo,
              const __nv_bfloat16* __restrict__ Bhi, const __nv_bfloat16* __restrict__ Blo,
              const float* __restrict__ R, float* __restrict__ C,
              int Nact, int K)
{
    extern __shared__ char smem[];
    uint32_t sb = smem_u32(smem);
    int tid  = threadIdx.x;
    int wid  = tid >> 5, lane = tid & 31;
    int wm   = wid & 3, wn = wid >> 2;
    int m0   = blockIdx.y * 128, n0 = blockIdx.x * 128;

    const __nv_bfloat16* srcs[4] = {Ahi, Alo, Bhi, Blo};
    const size_t rowK = (size_t)K * 2;

    auto load_stage = [&](int s, int k0) {
        uint32_t d0 = sb + s * STAGE_B;
#pragma unroll
        for (int t = 0; t < 4; t++) {
            const char* gb = (const char*)srcs[t] + (size_t)(t < 2 ? m0 : n0) * rowK + k0 * 2;
#pragma unroll
            for (int i = 0; i < 4; i++) {
                int idx = tid + i * 256;
                int row = idx >> 3, ch = idx & 7;
                cp16(d0 + t * TILE_B + row * LDT_B + ch * 16, gb + (size_t)row * rowK + ch * 16);
            }
        }
        cp_commit();
    };

    float acc[2][8][4];
#pragma unroll
    for (int mt = 0; mt < 2; mt++)
#pragma unroll
        for (int nt = 0; nt < 8; nt++)
#pragma unroll
            for (int j = 0; j < 4; j++) acc[mt][nt][j] = 0.f;

    int nch = K / BK;
    load_stage(0, 0);

    int a_row = wm * 32 + (lane & 7) + ((lane >> 3) & 1) * 8;
    int a_cb  = ((lane >> 4) & 1) * 16;
    int b_row = wn * 64 + ((lane >> 4) & 1) * 8 + (lane & 7);
    int b_cb  = ((lane >> 3) & 1) * 16;

    for (int c = 0; c < nch; c++) {
        if (c + 1 < nch) { load_stage((c + 1) & 1, (c + 1) * BK); cp_wait1(); }
        else             { cp_wait0(); }
        __syncthreads();

        uint32_t st = sb + (c & 1) * STAGE_B;
        uint32_t Ah = st, Al = st + TILE_B, Bh = st + 2 * TILE_B, Bl = st + 3 * TILE_B;

#pragma unroll
        for (int kk = 0; kk < 4; kk++) {
            int kb = kk * 32;
            uint32_t ah[2][4], al[2][4];
#pragma unroll
            for (int mt = 0; mt < 2; mt++) {
                uint32_t off = (uint32_t)((a_row + mt * 16) * LDT_B + kb + a_cb);
                ldmx4(ah[mt], Ah + off);
                ldmx4(al[mt], Al + off);
            }
            uint32_t bh[8][2], bl[8][2];
#pragma unroll
            for (int q = 0; q < 4; q++) {
                uint32_t off = (uint32_t)((b_row + q * 16) * LDT_B + kb + b_cb);
                uint32_t r[4];
                ldmx4(r, Bh + off);
                bh[2*q][0] = r[0]; bh[2*q][1] = r[1]; bh[2*q+1][0] = r[2]; bh[2*q+1][1] = r[3];
                ldmx4(r, Bl + off);
                bl[2*q][0] = r[0]; bl[2*q][1] = r[1]; bl[2*q+1][0] = r[2]; bl[2*q+1][1] = r[3];
            }
#pragma unroll
            for (int mt = 0; mt < 2; mt++)
#pragma unroll
                for (int nt = 0; nt < 8; nt++) {
                    mma16816(acc[mt][nt], ah[mt], bh[nt]);
                    mma16816(acc[mt][nt], ah[mt], bl[nt]);
                    mma16816(acc[mt][nt], al[mt], bh[nt]);
                }
        }
        __syncthreads();
    }

    int l4 = lane >> 2, l2 = (lane & 3) * 2;
#pragma unroll
    for (int mt = 0; mt < 2; mt++) {
        int gm = m0 + wm * 32 + mt * 16 + l4;
#pragma unroll
        for (int nt = 0; nt < 8; nt++) {
            int gn = n0 + wn * 64 + nt * 8 + l2;
            if (gn < Nact) {
                size_t o0 = (size_t)gm * Nact + gn;
                size_t o1 = (size_t)(gm + 8) * Nact + gn;
                float2 v0 = make_float2(acc[mt][nt][0], acc[mt][nt][1]);
                float2 v1 = make_float2(acc[mt][nt][2], acc[mt][nt][3]);
                if (R) {
                    const float2 r0 = *(const float2*)&R[o0];
                    const float2 r1 = *(const float2*)&R[o1];
                    v0.x += r0.x; v0.y += r0.y; v1.x += r1.x; v1.y += r1.y;
                }
                *(float2*)&C[o0] = v0;
                *(float2*)&C[o1] = v1;
            }
        }
    }
}

// ---------------------------------------------------------------------------
// fp32 -> bf16 hi/lo split
// ---------------------------------------------------------------------------
__global__ void split_f32(const float* __restrict__ src,
                          __nv_bfloat16* __restrict__ hi, __nv_bfloat16* __restrict__ lo, int n)
{
    int i = blockIdx.x * blockDim.x + threadIdx.x;
    if (i >= n) return;
    float v = src[i];
    __nv_bfloat16 h = __float2bfloat16_rn(v);
    hi[i] = h;
    lo[i] = __float2bfloat16_rn(v - __bfloat162float(h));
}

__global__ void split_pad_w(const float* __restrict__ w,
                            __nv_bfloat16* __restrict__ hi, __nv_bfloat16* __restrict__ lo,
                            int nsrc, int ntot)
{
    int i = blockIdx.x * blockDim.x + threadIdx.x;
    if (i >= ntot) return;
    float v = (i < nsrc) ? w[i] : 0.f;
    __nv_bfloat16 h = __float2bfloat16_rn(v);
    hi[i] = h;
    lo[i] = __float2bfloat16_rn(v - __bfloat162float(h));
}

// ---------------------------------------------------------------------------
// f32x2 helpers
// ---------------------------------------------------------------------------
__device__ __forceinline__ ull pk2(float x, float y) {
    ull r; asm("mov.b64 %0,{%1,%2};" : "=l"(r) : "f"(x), "f"(y)); return r;
}
__device__ __forceinline__ float2 upk2(ull v) {
    float2 r; asm("mov.b64 {%0,%1},%2;" : "=f"(r.x), "=f"(r.y) : "l"(v)); return r;
}
__device__ __forceinline__ ull f2fma(ull a, ull b, ull c) {
    ull d; asm("fma.rn.f32x2 %0,%1,%2,%3;" : "=l"(d) : "l"(a), "l"(b), "l"(c)); return d;
}
__device__ __forceinline__ ull f2mul(ull a, ull b) {
    ull d; asm("mul.rn.f32x2 %0,%1,%2;" : "=l"(d) : "l"(a), "l"(b)); return d;
}

// ---------------------------------------------------------------------------
// Causal depthwise conv1d (kernel 4) + SiLU over xBC channels of g_zx
// ---------------------------------------------------------------------------
__global__ void conv_silu(const float* __restrict__ cw, const float* __restrict__ cb)
{
    int idx = blockIdx.x * blockDim.x + threadIdx.x;
    if (idx >= M_TOK * CONVD) return;
    int c = idx % CONVD, m = idx / CONVD;
    int l = m & (LSEQ - 1);
    float acc = cb[c];
#pragma unroll
    for (int k = 0; k < 4; k++) {
        int ll = l - 3 + k;
        if (ll >= 0)
            acc = fmaf(g_zx[(size_t)(m - 3 + k) * NPROJ + DINNER + c], cw[c * 4 + k], acc);
    }
    float s = 1.f / (1.f + __expf(-acc));
    g_xc[idx] = acc * s;
}

// ---------------------------------------------------------------------------
// dt = softplus(dt_raw + dt_bias); dA = exp(dt*A); packed (dt,dA) per (b,h,l)
// ---------------------------------------------------------------------------
__global__ void dt_dA(const float* __restrict__ dtb, const float* __restrict__ alog)
{
    int idx = blockIdx.x * blockDim.x + threadIdx.x;
    if (idx >= M_TOK * NH) return;
    int h = idx % NH, m = idx / NH;
    int b = m / LSEQ, l = m % LSEQ;
    float v = g_zx[(size_t)m * NPROJ + DINNER + CONVD + h] + dtb[h];
    float sp = fmaxf(v, 0.f) + log1pf(expf(-fabsf(v)));
    float A = -expf(alog[h]);
    g_dtdA[(size_t)(b * NH + h) * LSEQ + l] = make_float2(sp, expf(sp * A));
}

// ---------------------------------------------------------------------------
// Selective SSM scan. One CTA per (b,h). 8-stage cp.async ring, 1 bar/step.
// Stage layout (floats):
//   x[0..63] | Bil[64..191] | Cil[192..319] | dt,dA[320,321]
// B/C stored INTERLEAVED at float2 granularity: global float2 index nb*8+i
// lives at smem float2 index i*8+nb  ->  for fixed i, lanes nb=0..7 read 8
// consecutive 8B words (conflict-free; same-nb lanes broadcast).
// ---------------------------------------------------------------------------
#define NSTG 8
#define STGF 336                   // floats per stage (1344 B)

__global__ __launch_bounds__(512, 1)
void scan_kernel(const float* __restrict__ Dv)
{
    __shared__ __align__(16) float sh[NSTG][STGF];
    uint32_t sb = smem_u32(sh);
    int bh = blockIdx.x;
    int b = bh / NH, h = bh % NH;
    int tid = threadIdx.x;
    int p = tid >> 3, nb = tid & 7;
    float Dh = Dv[h];

    // per-thread loader setup (145 loader threads)
    const char* src = nullptr;
    uint32_t dsto = 0;
    size_t stride = (size_t)CONVD * 4;
    const char* xcb = (const char*)(g_xc + (size_t)b * LSEQ * CONVD);
    if (tid < 16) {                       // x: 16 x cp16
        src = xcb + (size_t)h * HD * 4 + tid * 16;
        dsto = tid * 16;
    } else if (tid < 80) {                // B: 64 x cp8, interleaved store
        int t = tid - 16;
        src = xcb + (size_t)DINNER * 4 + t * 8;
        dsto = 256 + (uint32_t)(((t & 7) * 8 + (t >> 3)) * 8);
    } else if (tid < 144) {               // C: 64 x cp8, interleaved store
        int t = tid - 80;
        src = xcb + (size_t)(DINNER + DST) * 4 + t * 8;
        dsto = 768 + (uint32_t)(((t & 7) * 8 + (t >> 3)) * 8);
    } else if (tid == 144) {              // dt,dA: 1 x cp8
        src = (const char*)(g_dtdA + (size_t)bh * LSEQ);
        dsto = 1280;
        stride = 8;
    }

    auto issue = [&](int step) {
        if (step < LSEQ) {
            uint32_t d = sb + (uint32_t)((step & (NSTG - 1)) * (STGF * 4)) + dsto;
            if (tid < 16)        { cp16(d, src); src += stride; }
            else if (tid < 145)  { cp8(d, src);  src += stride; }
        }
        cp_commit();
    };

#pragma unroll
    for (int s = 0; s < NSTG - 1; s++) issue(s);   // stages 0..6

    ull st[8];
#pragma unroll
    for (int i = 0; i < 8; i++) st[i] = 0ull;

    float* ybase = g_y + (size_t)b * LSEQ * DINNER + h * HD + p;

    for (int l = 0; l < LSEQ; l++) {
        cp_wait6();            // stage l complete (7 groups outstanding -> 6)
        __syncthreads();       // data visible; prev compute finished
        issue(l + NSTG - 1);   // overwrite slot consumed at iteration l-1

        const float* bp = sh[l & (NSTG - 1)];
        float xp  = bp[p];
        float dt  = bp[320], dA = bp[321];
        float dtx = dt * xp;
        ull dA2  = pk2(dA, dA);
        ull dtx2 = pk2(dtx, dtx);
        const ull* B2 = (const ull*)(bp + 64);     // interleaved: idx i*8+nb
        const ull* C2 = (const ull*)(bp + 192);

        ull acc2 = 0ull;
#pragma unroll
        for (int i = 0; i < 8; i++) {
            st[i] = f2fma(st[i], dA2, f2mul(dtx2, B2[i * 8 + nb]));
            acc2  = f2fma(st[i], C2[i * 8 + nb], acc2);
        }
        float2 av = upk2(acc2);
        float acc = av.x + av.y;
        acc += __shfl_xor_sync(0xffffffffu, acc, 1);
        acc += __shfl_xor_sync(0xffffffffu, acc, 2);
        acc += __shfl_xor_sync(0xffffffffu, acc, 4);
        if (nb == 0)
            ybase[(size_t)l * DINNER] = acc + Dh * xp;
    }
}

// ---------------------------------------------------------------------------
// y = y * silu(z); rmsnorm; * norm_w; emit bf16 hi/lo for out_proj
// ---------------------------------------------------------------------------
__global__ __launch_bounds__(256)
void gate_norm(const float* __restrict__ nw)
{
    __shared__ float warpsum[8];
    __shared__ float stot;
    int m = blockIdx.x;
    int tid = threadIdx.x;
    float vals[6];
    float ss = 0.f;
#pragma unroll
    for (int j = 0; j < 6; j++) {
        int i = tid + j * 256;
        float yv = g_y[(size_t)m * DINNER + i];
        float zv = g_zx[(size_t)m * NPROJ + i];
        float g = zv / (1.f + __expf(-zv));
        float v = yv * g;
        vals[j] = v;
        ss = fmaf(v, v, ss);
    }
#pragma unroll
    for (int o = 16; o > 0; o >>= 1) ss += __shfl_xor_sync(0xffffffffu, ss, o);
    if ((tid & 31) == 0) warpsum[tid >> 5] = ss;
    __syncthreads();
    if (tid == 0) {
        float t = 0.f;
#pragma unroll
        for (int w = 0; w < 8; w++) t += warpsum[w];
        stot = t;
    }
    __syncthreads();
    float scale = rsqrtf(stot / (float)DINNER + 1e-5f);
#pragma unroll
    for (int j = 0; j < 6; j++) {
        int i = tid + j * 256;
        float v = vals[j] * scale * nw[i];
        __nv_bfloat16 hh = __float2bfloat16_rn(v);
        g_Yhi[(size_t)m * DINNER + i] = hh;
        g_Ylo[(size_t)m * DINNER + i] = __float2bfloat16_rn(v - __bfloat162float(hh));
    }
}

// ---------------------------------------------------------------------------
extern "C" void kernel_launch(void* const* d_in, const int* in_sizes, int n_in,
                              void* d_out, int out_size)
{
    const float* x    = (const float*)d_in[0];
    const float* wi   = (const float*)d_in[1];
    const float* cw   = (const float*)d_in[2];
    const float* cb   = (const float*)d_in[3];
    const float* dtb  = (const float*)d_in[4];
    const float* alog = (const float*)d_in[5];
    const float* Dv   = (const float*)d_in[6];
    const float* nw   = (const float*)d_in[7];
    const float* wo   = (const float*)d_in[8];
    float* out = (float*)d_out;

    float *zx;
    __nv_bfloat16 *xhi, *xlo, *wihi, *wilo, *yhi, *ylo, *wohi, *wolo;
    cudaGetSymbolAddress((void**)&zx,   g_zx);
    cudaGetSymbolAddress((void**)&xhi,  g_Xhi);
    cudaGetSymbolAddress((void**)&xlo,  g_Xlo);
    cudaGetSymbolAddress((void**)&wihi, g_Wihi);
    cudaGetSymbolAddress((void**)&wilo, g_Wilo);
    cudaGetSymbolAddress((void**)&yhi,  g_Yhi);
    cudaGetSymbolAddress((void**)&ylo,  g_Ylo);
    cudaGetSymbolAddress((void**)&wohi, g_Wohi);
    cudaGetSymbolAddress((void**)&wolo, g_Wolo);

    static const int smem_bytes = 2 * STAGE_B;  // 144 KB
    cudaFuncSetAttribute(mma_gemm, cudaFuncAttributeMaxDynamicSharedMemorySize, smem_bytes);

    dim3 blk(256);

    split_f32<<<(M_TOK * DMODEL + 255) / 256, blk>>>(x, xhi, xlo, M_TOK * DMODEL);
    split_pad_w<<<(NPAD * DMODEL + 255) / 256, blk>>>(wi, wihi, wilo,
                                                      NPROJ * DMODEL, NPAD * DMODEL);
    split_f32<<<(DMODEL * DINNER + 255) / 256, blk>>>(wo, wohi, wolo, DMODEL * DINNER);

    mma_gemm<<<dim3(NPAD / 128, M_TOK / 128), blk, smem_bytes>>>(
        xhi, xlo, wihi, wilo, nullptr, zx, NPROJ, DMODEL);

    conv_silu<<<(M_TOK * CONVD + 255) / 256, blk>>>(cw, cb);
    dt_dA<<<(M_TOK * NH + 255) / 256, blk>>>(dtb, alog);
    scan_kernel<<<96, 512>>>(Dv);
    gate_norm<<<M_TOK, blk>>>(nw);

    mma_gemm<<<dim3(DMODEL / 128, M_TOK / 128), blk, smem_bytes>>>(
        yhi, ylo, wohi, wolo, x, out, DMODEL, DINNER);
}

// round 6
// speedup vs baseline: 2.8879x; 1.0654x over previous
#include <cuda_runtime.h>
#include <cuda_bf16.h>
#include <cstdint>

#define M_TOK 8192
#define DMODEL 768
#define DINNER 1536
#define CONVD  1792
#define NH     24
#define HD     64
#define DST    128
#define NPROJ  3352
#define NPAD   3456            // 27 * 128
#define LSEQ   2048

// ---------------- device scratch (no allocation allowed) ----------------
__device__ float g_zx[M_TOK * NPROJ];    // in_proj output (z | xBC | dt)
__device__ float g_xc[M_TOK * CONVD];    // conv+silu output (xh | B | C)
__device__ float2 g_dtdA[96 * LSEQ];     // packed (dt, dA) per (b*NH+h, l)
__device__ float g_y [M_TOK * DINNER];   // scan output + D skip

__device__ __nv_bfloat16 g_Xhi[M_TOK * DMODEL];
__device__ __nv_bfloat16 g_Xlo[M_TOK * DMODEL];
__device__ __nv_bfloat16 g_Wihi[NPAD * DMODEL];
__device__ __nv_bfloat16 g_Wilo[NPAD * DMODEL];
__device__ __nv_bfloat16 g_Yhi[M_TOK * DINNER];
__device__ __nv_bfloat16 g_Ylo[M_TOK * DINNER];
__device__ __nv_bfloat16 g_Wohi[DMODEL * DINNER];
__device__ __nv_bfloat16 g_Wolo[DMODEL * DINNER];

typedef unsigned long long ull;

__device__ __forceinline__ uint32_t smem_u32(const void* p) {
    uint32_t a;
    asm("{ .reg .u64 t; cvta.to.shared.u64 t, %1; cvt.u32.u64 %0, t; }"
        : "=r"(a) : "l"(p));
    return a;
}

__device__ __forceinline__ void cp16(uint32_t dst, const void* src) {
    asm volatile("cp.async.cg.shared.global [%0], [%1], 16;"
                 :: "r"(dst), "l"(src) : "memory");
}
__device__ __forceinline__ void cp8(uint32_t dst, const void* src) {
    asm volatile("cp.async.ca.shared.global [%0], [%1], 8;"
                 :: "r"(dst), "l"(src) : "memory");
}
__device__ __forceinline__ void cp_commit() {
    asm volatile("cp.async.commit_group;" ::: "memory");
}
__device__ __forceinline__ void cp_wait0() {
    asm volatile("cp.async.wait_group 0;" ::: "memory");
}
__device__ __forceinline__ void cp_wait1() {
    asm volatile("cp.async.wait_group 1;" ::: "memory");
}
__device__ __forceinline__ void cp_wait2() {
    asm volatile("cp.async.wait_group 2;" ::: "memory");
}

__device__ __forceinline__ void ldmx4(uint32_t* r, uint32_t addr) {
    asm volatile("ldmatrix.sync.aligned.m8n8.x4.shared.b16 {%0,%1,%2,%3}, [%4];"
                 : "=r"(r[0]), "=r"(r[1]), "=r"(r[2]), "=r"(r[3]) : "r"(addr));
}

__device__ __forceinline__ void mma16816(float* c, const uint32_t* a, const uint32_t* b) {
    asm volatile(
        "mma.sync.aligned.m16n8k16.row.col.f32.bf16.bf16.f32 "
        "{%0,%1,%2,%3}, {%4,%5,%6,%7}, {%8,%9}, {%0,%1,%2,%3};"
        : "+f"(c[0]), "+f"(c[1]), "+f"(c[2]), "+f"(c[3])
        : "r"(a[0]), "r"(a[1]), "r"(a[2]), "r"(a[3]), "r"(b[0]), "r"(b[1]));
}

// ---------------------------------------------------------------------------
// Tensor-core GEMM (NT): C[m,n] = sum_k A[m,k]*B[n,k] via bf16 hi/lo 3-pass.
// 128x128 tile, 512 threads (16 warps, warp tile 32x32), K-chunk 64,
// double-buffered cp.async, mma.sync m16n8k16.
// ---------------------------------------------------------------------------
#define BK     64
#define LDT_B  144                 // smem row stride bytes (64 bf16 + 8 pad)
#define TILE_B (128 * LDT_B)       // 18432
#define STAGE_B (4 * TILE_B)       // 73728

__global__ __launch_bounds__(512, 1)
void mma_gemm(const __nv_bfloat16* __restrict__ Ahi, const __nv_bfloat16* __restrict__ Alo,
              const __nv_bfloat16* __restrict__ Bhi, const __nv_bfloat16* __restrict__ Blo,
              const float* __restrict__ R, float* __restrict__ C,
              int Nact, int K)
{
    extern __shared__ char smem[];
    uint32_t sb = smem_u32(smem);
    int tid  = threadIdx.x;
    int wid  = tid >> 5, lane = tid & 31;
    int wm   = wid & 3, wn = wid >> 2;        // 4x4 warp grid, 32x32 tiles
    int m0   = blockIdx.y * 128, n0 = blockIdx.x * 128;

    const __nv_bfloat16* srcs[4] = {Ahi, Alo, Bhi, Blo};
    const size_t rowK = (size_t)K * 2;

    auto load_stage = [&](int s, int k0) {
        uint32_t d0 = sb + s * STAGE_B;
#pragma unroll
        for (int t = 0; t < 4; t++) {
            const char* gb = (const char*)srcs[t] + (size_t)(t < 2 ? m0 : n0) * rowK + k0 * 2;
#pragma unroll
            for (int i = 0; i < 2; i++) {
                int idx = tid + i * 512;
                int row = idx >> 3, ch = idx & 7;
                cp16(d0 + t * TILE_B + row * LDT_B + ch * 16, gb + (size_t)row * rowK + ch * 16);
            }
        }
        cp_commit();
    };

    float acc[2][4][4];
#pragma unroll
    for (int mt = 0; mt < 2; mt++)
#pragma unroll
        for (int nt = 0; nt < 4; nt++)
#pragma unroll
            for (int j = 0; j < 4; j++) acc[mt][nt][j] = 0.f;

    int nch = K / BK;
    load_stage(0, 0);

    int a_row = wm * 32 + (lane & 7) + ((lane >> 3) & 1) * 8;
    int a_cb  = ((lane >> 4) & 1) * 16;
    int b_row = wn * 32 + ((lane >> 4) & 1) * 8 + (lane & 7);
    int b_cb  = ((lane >> 3) & 1) * 16;

    for (int c = 0; c < nch; c++) {
        if (c + 1 < nch) { load_stage((c + 1) & 1, (c + 1) * BK); cp_wait1(); }
        else             { cp_wait0(); }
        __syncthreads();

        uint32_t st = sb + (c & 1) * STAGE_B;
        uint32_t Ah = st, Al = st + TILE_B, Bh = st + 2 * TILE_B, Bl = st + 3 * TILE_B;

#pragma unroll
        for (int kk = 0; kk < 4; kk++) {
            int kb = kk * 32;
            uint32_t ah[2][4], al[2][4];
#pragma unroll
            for (int mt = 0; mt < 2; mt++) {
                uint32_t off = (uint32_t)((a_row + mt * 16) * LDT_B + kb + a_cb);
                ldmx4(ah[mt], Ah + off);
                ldmx4(al[mt], Al + off);
            }
            uint32_t bh[4][2], bl[4][2];
#pragma unroll
            for (int q = 0; q < 2; q++) {
                uint32_t off = (uint32_t)((b_row + q * 16) * LDT_B + kb + b_cb);
                uint32_t r[4];
                ldmx4(r, Bh + off);
                bh[2*q][0] = r[0]; bh[2*q][1] = r[1]; bh[2*q+1][0] = r[2]; bh[2*q+1][1] = r[3];
                ldmx4(r, Bl + off);
                bl[2*q][0] = r[0]; bl[2*q][1] = r[1]; bl[2*q+1][0] = r[2]; bl[2*q+1][1] = r[3];
            }
#pragma unroll
            for (int mt = 0; mt < 2; mt++)
#pragma unroll
                for (int nt = 0; nt < 4; nt++) {
                    mma16816(acc[mt][nt], ah[mt], bh[nt]);
                    mma16816(acc[mt][nt], ah[mt], bl[nt]);
                    mma16816(acc[mt][nt], al[mt], bh[nt]);
                }
        }
        __syncthreads();
    }

    int l4 = lane >> 2, l2 = (lane & 3) * 2;
#pragma unroll
    for (int mt = 0; mt < 2; mt++) {
        int gm = m0 + wm * 32 + mt * 16 + l4;
#pragma unroll
        for (int nt = 0; nt < 4; nt++) {
            int gn = n0 + wn * 32 + nt * 8 + l2;
            if (gn < Nact) {
                size_t o0 = (size_t)gm * Nact + gn;
                size_t o1 = (size_t)(gm + 8) * Nact + gn;
                float2 v0 = make_float2(acc[mt][nt][0], acc[mt][nt][1]);
                float2 v1 = make_float2(acc[mt][nt][2], acc[mt][nt][3]);
                if (R) {
                    const float2 r0 = *(const float2*)&R[o0];
                    const float2 r1 = *(const float2*)&R[o1];
                    v0.x += r0.x; v0.y += r0.y; v1.x += r1.x; v1.y += r1.y;
                }
                *(float2*)&C[o0] = v0;
                *(float2*)&C[o1] = v1;
            }
        }
    }
}

// ---------------------------------------------------------------------------
// fp32 -> bf16 hi/lo split
// ---------------------------------------------------------------------------
__global__ void split_f32(const float* __restrict__ src,
                          __nv_bfloat16* __restrict__ hi, __nv_bfloat16* __restrict__ lo, int n)
{
    int i = blockIdx.x * blockDim.x + threadIdx.x;
    if (i >= n) return;
    float v = src[i];
    __nv_bfloat16 h = __float2bfloat16_rn(v);
    hi[i] = h;
    lo[i] = __float2bfloat16_rn(v - __bfloat162float(h));
}

__global__ void split_pad_w(const float* __restrict__ w,
                            __nv_bfloat16* __restrict__ hi, __nv_bfloat16* __restrict__ lo,
                            int nsrc, int ntot)
{
    int i = blockIdx.x * blockDim.x + threadIdx.x;
    if (i >= ntot) return;
    float v = (i < nsrc) ? w[i] : 0.f;
    __nv_bfloat16 h = __float2bfloat16_rn(v);
    hi[i] = h;
    lo[i] = __float2bfloat16_rn(v - __bfloat162float(h));
}

// ---------------------------------------------------------------------------
// f32x2 helpers
// ---------------------------------------------------------------------------
__device__ __forceinline__ ull pk2(float x, float y) {
    ull r; asm("mov.b64 %0,{%1,%2};" : "=l"(r) : "f"(x), "f"(y)); return r;
}
__device__ __forceinline__ float2 upk2(ull v) {
    float2 r; asm("mov.b64 {%0,%1},%2;" : "=f"(r.x), "=f"(r.y) : "l"(v)); return r;
}
__device__ __forceinline__ ull f2fma(ull a, ull b, ull c) {
    ull d; asm("fma.rn.f32x2 %0,%1,%2,%3;" : "=l"(d) : "l"(a), "l"(b), "l"(c)); return d;
}
__device__ __forceinline__ ull f2mul(ull a, ull b) {
    ull d; asm("mul.rn.f32x2 %0,%1,%2;" : "=l"(d) : "l"(a), "l"(b)); return d;
}

// ---------------------------------------------------------------------------
// Causal depthwise conv1d (kernel 4) + SiLU over xBC channels of g_zx
// ---------------------------------------------------------------------------
__global__ void conv_silu(const float* __restrict__ cw, const float* __restrict__ cb)
{
    int idx = blockIdx.x * blockDim.x + threadIdx.x;
    if (idx >= M_TOK * CONVD) return;
    int c = idx % CONVD, m = idx / CONVD;
    int l = m & (LSEQ - 1);
    float acc = cb[c];
#pragma unroll
    for (int k = 0; k < 4; k++) {
        int ll = l - 3 + k;
        if (ll >= 0)
            acc = fmaf(g_zx[(size_t)(m - 3 + k) * NPROJ + DINNER + c], cw[c * 4 + k], acc);
    }
    float s = 1.f / (1.f + __expf(-acc));
    g_xc[idx] = acc * s;
}

// ---------------------------------------------------------------------------
// dt = softplus(dt_raw + dt_bias); dA = exp(dt*A); packed (dt,dA) per (b,h,l)
// ---------------------------------------------------------------------------
__global__ void dt_dA(const float* __restrict__ dtb, const float* __restrict__ alog)
{
    int idx = blockIdx.x * blockDim.x + threadIdx.x;
    if (idx >= M_TOK * NH) return;
    int h = idx % NH, m = idx / NH;
    int b = m / LSEQ, l = m % LSEQ;
    float v = g_zx[(size_t)m * NPROJ + DINNER + CONVD + h] + dtb[h];
    float sp = fmaxf(v, 0.f) + log1pf(expf(-fabsf(v)));
    float A = -expf(alog[h]);
    g_dtdA[(size_t)(b * NH + h) * LSEQ + l] = make_float2(sp, expf(sp * A));
}

// ---------------------------------------------------------------------------
// Selective SSM scan. One CTA per (b,h). 8-stage cp.async ring, 2 steps per
// barrier. Stage layout (floats):
//   x[0..63] | Bil[64..191] | Cil[192..319] | dt,dA[320,321]
// B/C stored INTERLEAVED at float4 granularity: global float4 chunk nb*4+j
// lives at smem float4 index j*8+nb -> lanes nb=0..7 read 8 consecutive 16B
// chunks per LDS.128 (conflict-free; p-duplicate lanes broadcast).
// ---------------------------------------------------------------------------
#define NSTG 8
#define STGF 336                   // floats per stage (1344 B)

__global__ __launch_bounds__(512, 1)
void scan_kernel(const float* __restrict__ Dv)
{
    __shared__ __align__(16) float sh[NSTG][STGF];
    uint32_t sb = smem_u32(sh);
    int bh = blockIdx.x;
    int b = bh / NH, h = bh % NH;
    int tid = threadIdx.x;
    int p = tid >> 3, nb = tid & 7;
    float Dh = Dv[h];

    // loader setup (81 loader threads, one cp op per step each)
    const char* src = nullptr;
    uint32_t dsto = 0;
    size_t stride = (size_t)CONVD * 4;
    const char* xcb = (const char*)(g_xc + (size_t)b * LSEQ * CONVD);
    if (tid < 16) {                       // x: 16 x cp16
        src = xcb + (size_t)h * HD * 4 + tid * 16;
        dsto = tid * 16;
    } else if (tid < 48) {                // B: 32 x cp16, f4-interleaved store
        int t = tid - 16;                 // global chunk g = nb*4+j
        src = xcb + (size_t)DINNER * 4 + t * 16;
        dsto = 256 + (uint32_t)(((t & 3) * 8 + (t >> 2)) * 16);
    } else if (tid < 80) {                // C: 32 x cp16, f4-interleaved store
        int t = tid - 48;
        src = xcb + (size_t)(DINNER + DST) * 4 + t * 16;
        dsto = 768 + (uint32_t)(((t & 3) * 8 + (t >> 2)) * 16);
    } else if (tid == 80) {               // dt,dA: 1 x cp8
        src = (const char*)(g_dtdA + (size_t)bh * LSEQ);
        dsto = 1280;
        stride = 8;
    }

    // one commit group covers TWO steps
    auto issue_pair = [&](int jp) {
#pragma unroll
        for (int q = 0; q < 2; q++) {
            int step = 2 * jp + q;
            if (step < LSEQ && tid <= 80) {
                uint32_t d = sb + (uint32_t)((step & (NSTG - 1)) * (STGF * 4)) + dsto;
                if (tid < 80) cp16(d, src); else cp8(d, src);
                src += stride;
            }
        }
        cp_commit();
    };

    issue_pair(0); issue_pair(1); issue_pair(2);   // stages 0..5

    ull st[8];
#pragma unroll
    for (int i = 0; i < 8; i++) st[i] = 0ull;

    float* ybase = g_y + (size_t)b * LSEQ * DINNER + h * HD + p;

    auto compute = [&](int l) {
        const float* bp = sh[l & (NSTG - 1)];
        float xp  = bp[p];
        float dt  = bp[320], dA = bp[321];
        float dtx = dt * xp;
        ull dA2  = pk2(dA, dA);
        ull dtx2 = pk2(dtx, dtx);
        const ulonglong2* B4 = (const ulonglong2*)(bp + 64);
        const ulonglong2* C4 = (const ulonglong2*)(bp + 192);

        ull bb[8], cc[8];
#pragma unroll
        for (int j = 0; j < 4; j++) {
            ulonglong2 bv = B4[j * 8 + nb];
            ulonglong2 cv = C4[j * 8 + nb];
            bb[2*j] = bv.x; bb[2*j+1] = bv.y;
            cc[2*j] = cv.x; cc[2*j+1] = cv.y;
        }
        ull acc2 = 0ull;
#pragma unroll
        for (int i = 0; i < 8; i++) {
            st[i] = f2fma(st[i], dA2, f2mul(dtx2, bb[i]));
            acc2  = f2fma(st[i], cc[i], acc2);
        }
        float2 av = upk2(acc2);
        float acc = av.x + av.y;
        acc += __shfl_xor_sync(0xffffffffu, acc, 1);
        acc += __shfl_xor_sync(0xffffffffu, acc, 2);
        acc += __shfl_xor_sync(0xffffffffu, acc, 4);
        if (nb == 0)
            ybase[(size_t)l * DINNER] = acc + Dh * xp;
    };

    for (int j = 0; j < LSEQ / 2; j++) {
        cp_wait2();            // pair j complete (3 groups in flight -> 2)
        __syncthreads();       // data visible; prev pair's compute finished
        issue_pair(j + 3);     // overwrites stages consumed at pair j-1
        compute(2 * j);
        compute(2 * j + 1);
    }
}

// ---------------------------------------------------------------------------
// y = y * silu(z); rmsnorm; * norm_w; emit bf16 hi/lo for out_proj
// ---------------------------------------------------------------------------
__global__ __launch_bounds__(256)
void gate_norm(const float* __restrict__ nw)
{
    __shared__ float warpsum[8];
    __shared__ float stot;
    int m = blockIdx.x;
    int tid = threadIdx.x;
    float vals[6];
    float ss = 0.f;
#pragma unroll
    for (int j = 0; j < 6; j++) {
        int i = tid + j * 256;
        float yv = g_y[(size_t)m * DINNER + i];
        float zv = g_zx[(size_t)m * NPROJ + i];
        float g = zv / (1.f + __expf(-zv));
        float v = yv * g;
        vals[j] = v;
        ss = fmaf(v, v, ss);
    }
#pragma unroll
    for (int o = 16; o > 0; o >>= 1) ss += __shfl_xor_sync(0xffffffffu, ss, o);
    if ((tid & 31) == 0) warpsum[tid >> 5] = ss;
    __syncthreads();
    if (tid == 0) {
        float t = 0.f;
#pragma unroll
        for (int w = 0; w < 8; w++) t += warpsum[w];
        stot = t;
    }
    __syncthreads();
    float scale = rsqrtf(stot / (float)DINNER + 1e-5f);
#pragma unroll
    for (int j = 0; j < 6; j++) {
        int i = tid + j * 256;
        float v = vals[j] * scale * nw[i];
        __nv_bfloat16 hh = __float2bfloat16_rn(v);
        g_Yhi[(size_t)m * DINNER + i] = hh;
        g_Ylo[(size_t)m * DINNER + i] = __float2bfloat16_rn(v - __bfloat162float(hh));
    }
}

// ---------------------------------------------------------------------------
extern "C" void kernel_launch(void* const* d_in, const int* in_sizes, int n_in,
                              void* d_out, int out_size)
{
    const float* x    = (const float*)d_in[0];
    const float* wi   = (const float*)d_in[1];
    const float* cw   = (const float*)d_in[2];
    const float* cb   = (const float*)d_in[3];
    const float* dtb  = (const float*)d_in[4];
    const float* alog = (const float*)d_in[5];
    const float* Dv   = (const float*)d_in[6];
    const float* nw   = (const float*)d_in[7];
    const float* wo   = (const float*)d_in[8];
    float* out = (float*)d_out;

    float *zx;
    __nv_bfloat16 *xhi, *xlo, *wihi, *wilo, *yhi, *ylo, *wohi, *wolo;
    cudaGetSymbolAddress((void**)&zx,   g_zx);
    cudaGetSymbolAddress((void**)&xhi,  g_Xhi);
    cudaGetSymbolAddress((void**)&xlo,  g_Xlo);
    cudaGetSymbolAddress((void**)&wihi, g_Wihi);
    cudaGetSymbolAddress((void**)&wilo, g_Wilo);
    cudaGetSymbolAddress((void**)&yhi,  g_Yhi);
    cudaGetSymbolAddress((void**)&ylo,  g_Ylo);
    cudaGetSymbolAddress((void**)&wohi, g_Wohi);
    cudaGetSymbolAddress((void**)&wolo, g_Wolo);

    static const int smem_bytes = 2 * STAGE_B;  // 144 KB
    cudaFuncSetAttribute(mma_gemm, cudaFuncAttributeMaxDynamicSharedMemorySize, smem_bytes);

    dim3 blk(256);

    split_f32<<<(M_TOK * DMODEL + 255) / 256, blk>>>(x, xhi, xlo, M_TOK * DMODEL);
    split_pad_w<<<(NPAD * DMODEL + 255) / 256, blk>>>(wi, wihi, wilo,
                                                      NPROJ * DMODEL, NPAD * DMODEL);
    split_f32<<<(DMODEL * DINNER + 255) / 256, blk>>>(wo, wohi, wolo, DMODEL * DINNER);

    mma_gemm<<<dim3(NPAD / 128, M_TOK / 128), 512, smem_bytes>>>(
        xhi, xlo, wihi, wilo, nullptr, zx, NPROJ, DMODEL);

    conv_silu<<<(M_TOK * CONVD + 255) / 256, blk>>>(cw, cb);
    dt_dA<<<(M_TOK * NH + 255) / 256, blk>>>(dtb, alog);
    scan_kernel<<<96, 512>>>(Dv);
    gate_norm<<<M_TOK, blk>>>(nw);

    mma_gemm<<<dim3(DMODEL / 128, M_TOK / 128), 512, smem_bytes>>>(
        yhi, ylo, wohi, wolo, x, out, DMODEL, DINNER);
}

// round 7
// speedup vs baseline: 3.1273x; 1.0829x over previous
#include <cuda_runtime.h>
#include <cuda_bf16.h>
#include <cstdint>

#define M_TOK 8192
#define DMODEL 768
#define DINNER 1536
#define CONVD  1792
#define NH     24
#define HD     64
#define DST    128
#define NPROJ  3352
#define NPAD   3456            // 27 * 128
#define LSEQ   2048

// ---------------- device scratch (no allocation allowed) ----------------
__device__ float g_zx[M_TOK * NPROJ];    // in_proj output (z | xBC | dt)
__device__ float g_xc[M_TOK * CONVD];    // conv+silu output (xh | B | C)
__device__ float2 g_dtdA[96 * LSEQ];     // packed (dt, dA) per (b*NH+h, l)
__device__ float g_y [M_TOK * DINNER];   // scan output + D skip

__device__ __nv_bfloat16 g_Xhi[M_TOK * DMODEL];
__device__ __nv_bfloat16 g_Xlo[M_TOK * DMODEL];
__device__ __nv_bfloat16 g_Wihi[NPAD * DMODEL];
__device__ __nv_bfloat16 g_Wilo[NPAD * DMODEL];
__device__ __nv_bfloat16 g_Yhi[M_TOK * DINNER];
__device__ __nv_bfloat16 g_Ylo[M_TOK * DINNER];
__device__ __nv_bfloat16 g_Wohi[DMODEL * DINNER];
__device__ __nv_bfloat16 g_Wolo[DMODEL * DINNER];

typedef unsigned long long ull;

__device__ __forceinline__ uint32_t smem_u32(const void* p) {
    uint32_t a;
    asm("{ .reg .u64 t; cvta.to.shared.u64 t, %1; cvt.u32.u64 %0, t; }"
        : "=r"(a) : "l"(p));
    return a;
}

__device__ __forceinline__ void cp16(uint32_t dst, const void* src) {
    asm volatile("cp.async.cg.shared.global [%0], [%1], 16;"
                 :: "r"(dst), "l"(src) : "memory");
}
__device__ __forceinline__ void cp8(uint32_t dst, const void* src) {
    asm volatile("cp.async.ca.shared.global [%0], [%1], 8;"
                 :: "r"(dst), "l"(src) : "memory");
}
__device__ __forceinline__ void cp_commit() {
    asm volatile("cp.async.commit_group;" ::: "memory");
}
__device__ __forceinline__ void cp_wait0() {
    asm volatile("cp.async.wait_group 0;" ::: "memory");
}
__device__ __forceinline__ void cp_wait1() {
    asm volatile("cp.async.wait_group 1;" ::: "memory");
}
__device__ __forceinline__ void cp_wait2() {
    asm volatile("cp.async.wait_group 2;" ::: "memory");
}

__device__ __forceinline__ void ldmx4(uint32_t* r, uint32_t addr) {
    asm volatile("ldmatrix.sync.aligned.m8n8.x4.shared.b16 {%0,%1,%2,%3}, [%4];"
                 : "=r"(r[0]), "=r"(r[1]), "=r"(r[2]), "=r"(r[3]) : "r"(addr));
}

__device__ __forceinline__ void mma16816(float* c, const uint32_t* a, const uint32_t* b) {
    asm volatile(
        "mma.sync.aligned.m16n8k16.row.col.f32.bf16.bf16.f32 "
        "{%0,%1,%2,%3}, {%4,%5,%6,%7}, {%8,%9}, {%0,%1,%2,%3};"
        : "+f"(c[0]), "+f"(c[1]), "+f"(c[2]), "+f"(c[3])
        : "r"(a[0]), "r"(a[1]), "r"(a[2]), "r"(a[3]), "r"(b[0]), "r"(b[1]));
}

// ---------------------------------------------------------------------------
// Tensor-core GEMM (NT): C[m,n] = sum_k A[m,k]*B[n,k] via bf16 hi/lo 3-pass.
// 128x128 tile, 256 threads (8 warps, warp tile 32x64), K-chunk 64,
// double-buffered cp.async, mma.sync m16n8k16.   (Round-5 geometry)
// ---------------------------------------------------------------------------
#define BK     64
#define LDT_B  144                 // smem row stride bytes (64 bf16 + 8 pad)
#define TILE_B (128 * LDT_B)       // 18432
#define STAGE_B (4 * TILE_B)       // 73728

__global__ __launch_bounds__(256, 1)
void mma_gemm(const __nv_bfloat16* __restrict__ Ahi, const __nv_bfloat16* __restrict__ Alo,
              const __nv_bfloat16* __restrict__ Bhi, const __nv_bfloat16* __restrict__ Blo,
              const float* __restrict__ R, float* __restrict__ C,
              int Nact, int K)
{
    extern __shared__ char smem[];
    uint32_t sb = smem_u32(smem);
    int tid  = threadIdx.x;
    int wid  = tid >> 5, lane = tid & 31;
    int wm   = wid & 3, wn = wid >> 2;
    int m0   = blockIdx.y * 128, n0 = blockIdx.x * 128;

    const __nv_bfloat16* srcs[4] = {Ahi, Alo, Bhi, Blo};
    const size_t rowK = (size_t)K * 2;

    auto load_stage = [&](int s, int k0) {
        uint32_t d0 = sb + s * STAGE_B;
#pragma unroll
        for (int t = 0; t < 4; t++) {
            const char* gb = (const char*)srcs[t] + (size_t)(t < 2 ? m0 : n0) * rowK + k0 * 2;
#pragma unroll
            for (int i = 0; i < 4; i++) {
                int idx = tid + i * 256;
                int row = idx >> 3, ch = idx & 7;
                cp16(d0 + t * TILE_B + row * LDT_B + ch * 16, gb + (size_t)row * rowK + ch * 16);
            }
        }
        cp_commit();
    };

    float acc[2][8][4];
#pragma unroll
    for (int mt = 0; mt < 2; mt++)
#pragma unroll
        for (int nt = 0; nt < 8; nt++)
#pragma unroll
            for (int j = 0; j < 4; j++) acc[mt][nt][j] = 0.f;

    int nch = K / BK;
    load_stage(0, 0);

    int a_row = wm * 32 + (lane & 7) + ((lane >> 3) & 1) * 8;
    int a_cb  = ((lane >> 4) & 1) * 16;
    int b_row = wn * 64 + ((lane >> 4) & 1) * 8 + (lane & 7);
    int b_cb  = ((lane >> 3) & 1) * 16;

    for (int c = 0; c < nch; c++) {
        if (c + 1 < nch) { load_stage((c + 1) & 1, (c + 1) * BK); cp_wait1(); }
        else             { cp_wait0(); }
        __syncthreads();

        uint32_t st = sb + (c & 1) * STAGE_B;
        uint32_t Ah = st, Al = st + TILE_B, Bh = st + 2 * TILE_B, Bl = st + 3 * TILE_B;

#pragma unroll
        for (int kk = 0; kk < 4; kk++) {
            int kb = kk * 32;
            uint32_t ah[2][4], al[2][4];
#pragma unroll
            for (int mt = 0; mt < 2; mt++) {
                uint32_t off = (uint32_t)((a_row + mt * 16) * LDT_B + kb + a_cb);
                ldmx4(ah[mt], Ah + off);
                ldmx4(al[mt], Al + off);
            }
            uint32_t bh[8][2], bl[8][2];
#pragma unroll
            for (int q = 0; q < 4; q++) {
                uint32_t off = (uint32_t)((b_row + q * 16) * LDT_B + kb + b_cb);
                uint32_t r[4];
                ldmx4(r, Bh + off);
                bh[2*q][0] = r[0]; bh[2*q][1] = r[1]; bh[2*q+1][0] = r[2]; bh[2*q+1][1] = r[3];
                ldmx4(r, Bl + off);
                bl[2*q][0] = r[0]; bl[2*q][1] = r[1]; bl[2*q+1][0] = r[2]; bl[2*q+1][1] = r[3];
            }
#pragma unroll
            for (int mt = 0; mt < 2; mt++)
#pragma unroll
                for (int nt = 0; nt < 8; nt++) {
                    mma16816(acc[mt][nt], ah[mt], bh[nt]);
                    mma16816(acc[mt][nt], ah[mt], bl[nt]);
                    mma16816(acc[mt][nt], al[mt], bh[nt]);
                }
        }
        __syncthreads();
    }

    int l4 = lane >> 2, l2 = (lane & 3) * 2;
#pragma unroll
    for (int mt = 0; mt < 2; mt++) {
        int gm = m0 + wm * 32 + mt * 16 + l4;
#pragma unroll
        for (int nt = 0; nt < 8; nt++) {
            int gn = n0 + wn * 64 + nt * 8 + l2;
            if (gn < Nact) {
                size_t o0 = (size_t)gm * Nact + gn;
                size_t o1 = (size_t)(gm + 8) * Nact + gn;
                float2 v0 = make_float2(acc[mt][nt][0], acc[mt][nt][1]);
                float2 v1 = make_float2(acc[mt][nt][2], acc[mt][nt][3]);
                if (R) {
                    const float2 r0 = *(const float2*)&R[o0];
                    const float2 r1 = *(const float2*)&R[o1];
                    v0.x += r0.x; v0.y += r0.y; v1.x += r1.x; v1.y += r1.y;
                }
                *(float2*)&C[o0] = v0;
                *(float2*)&C[o1] = v1;
            }
        }
    }
}

// ---------------------------------------------------------------------------
// fp32 -> bf16 hi/lo split
// ---------------------------------------------------------------------------
__global__ void split_f32(const float* __restrict__ src,
                          __nv_bfloat16* __restrict__ hi, __nv_bfloat16* __restrict__ lo, int n)
{
    int i = blockIdx.x * blockDim.x + threadIdx.x;
    if (i >= n) return;
    float v = src[i];
    __nv_bfloat16 h = __float2bfloat16_rn(v);
    hi[i] = h;
    lo[i] = __float2bfloat16_rn(v - __bfloat162float(h));
}

__global__ void split_pad_w(const float* __restrict__ w,
                            __nv_bfloat16* __restrict__ hi, __nv_bfloat16* __restrict__ lo,
                            int nsrc, int ntot)
{
    int i = blockIdx.x * blockDim.x + threadIdx.x;
    if (i >= ntot) return;
    float v = (i < nsrc) ? w[i] : 0.f;
    __nv_bfloat16 h = __float2bfloat16_rn(v);
    hi[i] = h;
    lo[i] = __float2bfloat16_rn(v - __bfloat162float(h));
}

// ---------------------------------------------------------------------------
// f32x2 helpers
// ---------------------------------------------------------------------------
__device__ __forceinline__ ull pk2(float x, float y) {
    ull r; asm("mov.b64 %0,{%1,%2};" : "=l"(r) : "f"(x), "f"(y)); return r;
}
__device__ __forceinline__ float2 upk2(ull v) {
    float2 r; asm("mov.b64 {%0,%1},%2;" : "=f"(r.x), "=f"(r.y) : "l"(v)); return r;
}
__device__ __forceinline__ ull f2fma(ull a, ull b, ull c) {
    ull d; asm("fma.rn.f32x2 %0,%1,%2,%3;" : "=l"(d) : "l"(a), "l"(b), "l"(c)); return d;
}
__device__ __forceinline__ ull f2mul(ull a, ull b) {
    ull d; asm("mul.rn.f32x2 %0,%1,%2;" : "=l"(d) : "l"(a), "l"(b)); return d;
}

// ---------------------------------------------------------------------------
// Causal depthwise conv1d (kernel 4) + SiLU over xBC channels of g_zx
// ---------------------------------------------------------------------------
__global__ void conv_silu(const float* __restrict__ cw, const float* __restrict__ cb)
{
    int idx = blockIdx.x * blockDim.x + threadIdx.x;
    if (idx >= M_TOK * CONVD) return;
    int c = idx % CONVD, m = idx / CONVD;
    int l = m & (LSEQ - 1);
    float acc = cb[c];
#pragma unroll
    for (int k = 0; k < 4; k++) {
        int ll = l - 3 + k;
        if (ll >= 0)
            acc = fmaf(g_zx[(size_t)(m - 3 + k) * NPROJ + DINNER + c], cw[c * 4 + k], acc);
    }
    float s = 1.f / (1.f + __expf(-acc));
    g_xc[idx] = acc * s;
}

// ---------------------------------------------------------------------------
// dt = softplus(dt_raw + dt_bias); dA = exp(dt*A); packed (dt,dA) per (b,h,l)
// ---------------------------------------------------------------------------
__global__ void dt_dA(const float* __restrict__ dtb, const float* __restrict__ alog)
{
    int idx = blockIdx.x * blockDim.x + threadIdx.x;
    if (idx >= M_TOK * NH) return;
    int h = idx % NH, m = idx / NH;
    int b = m / LSEQ, l = m % LSEQ;
    float v = g_zx[(size_t)m * NPROJ + DINNER + CONVD + h] + dtb[h];
    float sp = fmaxf(v, 0.f) + log1pf(expf(-fabsf(v)));
    float A = -expf(alog[h]);
    g_dtdA[(size_t)(b * NH + h) * LSEQ + l] = make_float2(sp, expf(sp * A));
}

// ---------------------------------------------------------------------------
// Selective SSM scan. One CTA per (b,h). 16-stage cp.async ring, 4 steps per
// barrier, shuffle-free output: per-step partials go to a smem staging buffer,
// a bulk reduce every 8 steps writes y (coalesced STG).
// Stage layout (floats): x[0..63] | Bil[64..191] | Cil[192..319] | dt,dA[320,321]
// B/C interleaved at float4 granularity (conflict-free LDS.128 + broadcast).
// ---------------------------------------------------------------------------
#define NSTG 16
#define STGF 336                   // floats per stage (1344 B)

__global__ __launch_bounds__(512, 1)
void scan_kernel(const float* __restrict__ Dv)
{
    __shared__ __align__(16) float sh[NSTG][STGF];   // 21504 B
    __shared__ __align__(16) float yb[8][512];       // 16384 B partial staging
    uint32_t sb = smem_u32(sh);
    int bh = blockIdx.x;
    int b = bh / NH, h = bh % NH;
    int tid = threadIdx.x;
    int p = tid >> 3, nb = tid & 7;
    float dh0 = (nb == 0) ? Dv[h] : 0.f;

    // loader setup (81 loader threads)
    const char* src = nullptr;
    uint32_t dsto = 0;
    size_t stride = (size_t)CONVD * 4;
    const char* xcb = (const char*)(g_xc + (size_t)b * LSEQ * CONVD);
    if (tid < 16) {                       // x: 16 x cp16
        src = xcb + (size_t)h * HD * 4 + tid * 16;
        dsto = tid * 16;
    } else if (tid < 48) {                // B: 32 x cp16, f4-interleaved
        int t = tid - 16;
        src = xcb + (size_t)DINNER * 4 + t * 16;
        dsto = 256 + (uint32_t)(((t & 3) * 8 + (t >> 2)) * 16);
    } else if (tid < 80) {                // C: 32 x cp16, f4-interleaved
        int t = tid - 48;
        src = xcb + (size_t)(DINNER + DST) * 4 + t * 16;
        dsto = 768 + (uint32_t)(((t & 3) * 8 + (t >> 2)) * 16);
    } else if (tid == 80) {               // dt,dA: 1 x cp8
        src = (const char*)(g_dtdA + (size_t)bh * LSEQ);
        dsto = 1280;
        stride = 8;
    }

    // one commit group covers FOUR steps
    auto issue_group = [&](int gq) {
#pragma unroll
        for (int q = 0; q < 4; q++) {
            int step = 4 * gq + q;
            if (step < LSEQ && tid <= 80) {
                uint32_t d = sb + (uint32_t)((step & (NSTG - 1)) * (STGF * 4)) + dsto;
                if (tid < 80) cp16(d, src); else cp8(d, src);
                src += stride;
            }
        }
        cp_commit();
    };

    issue_group(0); issue_group(1); issue_group(2);   // stages 0..11

    ull st[8];
#pragma unroll
    for (int i = 0; i < 8; i++) st[i] = 0ull;

    float* ybase = g_y + (size_t)b * LSEQ * DINNER + h * HD;

    // reducer mapping: thread handles (s = tid>>6, p = tid&63)
    int rs = tid >> 6, rp = tid & 63;

    for (int g = 0; g < LSEQ / 4; g++) {
        cp_wait2();            // group g data ready (3 in flight -> 2)
        __syncthreads();       // visible to all; prev compute/reduce finished
        issue_group(g + 3);    // overwrites stages of group g-1 (done)

#pragma unroll
        for (int q = 0; q < 4; q++) {
            int l = 4 * g + q;
            const float* bp = sh[l & (NSTG - 1)];
            float xp  = bp[p];
            float2 da = *(const float2*)(bp + 320);
            float dtx = da.x * xp;
            ull dA2  = pk2(da.y, da.y);
            ull dtx2 = pk2(dtx, dtx);
            const ulonglong2* B4 = (const ulonglong2*)(bp + 64);
            const ulonglong2* C4 = (const ulonglong2*)(bp + 192);

            ull bb[8], cc[8];
#pragma unroll
            for (int j = 0; j < 4; j++) {
                ulonglong2 bv = B4[j * 8 + nb];
                ulonglong2 cv = C4[j * 8 + nb];
                bb[2*j] = bv.x; bb[2*j+1] = bv.y;
                cc[2*j] = cv.x; cc[2*j+1] = cv.y;
            }
            ull acc2 = 0ull;
#pragma unroll
            for (int i = 0; i < 8; i++) {
                st[i] = f2fma(st[i], dA2, f2mul(dtx2, bb[i]));
                acc2  = f2fma(st[i], cc[i], acc2);
            }
            float2 av = upk2(acc2);
            yb[l & 7][tid] = fmaf(dh0, xp, av.x + av.y);   // partial (sum over nb pending)
        }

        if (g & 1) {
            __syncthreads();   // all partials of this 8-step window written
            const float4* r4 = (const float4*)(yb[rs] + rp * 8);
            float4 v0 = r4[0], v1 = r4[1];
            float acc = ((v0.x + v0.y) + (v0.z + v0.w))
                      + ((v1.x + v1.y) + (v1.z + v1.w));
            int l0 = 4 * (g - 1);
            ybase[(size_t)(l0 + rs) * DINNER + rp] = acc;
        }
    }
}

// ---------------------------------------------------------------------------
// y = y * silu(z); rmsnorm; * norm_w; emit bf16 hi/lo for out_proj
// ---------------------------------------------------------------------------
__global__ __launch_bounds__(256)
void gate_norm(const float* __restrict__ nw)
{
    __shared__ float warpsum[8];
    __shared__ float stot;
    int m = blockIdx.x;
    int tid = threadIdx.x;
    float vals[6];
    float ss = 0.f;
#pragma unroll
    for (int j = 0; j < 6; j++) {
        int i = tid + j * 256;
        float yv = g_y[(size_t)m * DINNER + i];
        float zv = g_zx[(size_t)m * NPROJ + i];
        float g = zv / (1.f + __expf(-zv));
        float v = yv * g;
        vals[j] = v;
        ss = fmaf(v, v, ss);
    }
#pragma unroll
    for (int o = 16; o > 0; o >>= 1) ss += __shfl_xor_sync(0xffffffffu, ss, o);
    if ((tid & 31) == 0) warpsum[tid >> 5] = ss;
    __syncthreads();
    if (tid == 0) {
        float t = 0.f;
#pragma unroll
        for (int w = 0; w < 8; w++) t += warpsum[w];
        stot = t;
    }
    __syncthreads();
    float scale = rsqrtf(stot / (float)DINNER + 1e-5f);
#pragma unroll
    for (int j = 0; j < 6; j++) {
        int i = tid + j * 256;
        float v = vals[j] * scale * nw[i];
        __nv_bfloat16 hh = __float2bfloat16_rn(v);
        g_Yhi[(size_t)m * DINNER + i] = hh;
        g_Ylo[(size_t)m * DINNER + i] = __float2bfloat16_rn(v - __bfloat162float(hh));
    }
}

// ---------------------------------------------------------------------------
extern "C" void kernel_launch(void* const* d_in, const int* in_sizes, int n_in,
                              void* d_out, int out_size)
{
    const float* x    = (const float*)d_in[0];
    const float* wi   = (const float*)d_in[1];
    const float* cw   = (const float*)d_in[2];
    const float* cb   = (const float*)d_in[3];
    const float* dtb  = (const float*)d_in[4];
    const float* alog = (const float*)d_in[5];
    const float* Dv   = (const float*)d_in[6];
    const float* nw   = (const float*)d_in[7];
    const float* wo   = (const float*)d_in[8];
    float* out = (float*)d_out;

    float *zx;
    __nv_bfloat16 *xhi, *xlo, *wihi, *wilo, *yhi, *ylo, *wohi, *wolo;
    cudaGetSymbolAddress((void**)&zx,   g_zx);
    cudaGetSymbolAddress((void**)&xhi,  g_Xhi);
    cudaGetSymbolAddress((void**)&xlo,  g_Xlo);
    cudaGetSymbolAddress((void**)&wihi, g_Wihi);
    cudaGetSymbolAddress((void**)&wilo, g_Wilo);
    cudaGetSymbolAddress((void**)&yhi,  g_Yhi);
    cudaGetSymbolAddress((void**)&ylo,  g_Ylo);
    cudaGetSymbolAddress((void**)&wohi, g_Wohi);
    cudaGetSymbolAddress((void**)&wolo, g_Wolo);

    static const int smem_bytes = 2 * STAGE_B;  // 144 KB
    cudaFuncSetAttribute(mma_gemm, cudaFuncAttributeMaxDynamicSharedMemorySize, smem_bytes);

    dim3 blk(256);

    split_f32<<<(M_TOK * DMODEL + 255) / 256, blk>>>(x, xhi, xlo, M_TOK * DMODEL);
    split_pad_w<<<(NPAD * DMODEL + 255) / 256, blk>>>(wi, wihi, wilo,
                                                      NPROJ * DMODEL, NPAD * DMODEL);
    split_f32<<<(DMODEL * DINNER + 255) / 256, blk>>>(wo, wohi, wolo, DMODEL * DINNER);

    mma_gemm<<<dim3(NPAD / 128, M_TOK / 128), blk, smem_bytes>>>(
        xhi, xlo, wihi, wilo, nullptr, zx, NPROJ, DMODEL);

    conv_silu<<<(M_TOK * CONVD + 255) / 256, blk>>>(cw, cb);
    dt_dA<<<(M_TOK * NH + 255) / 256, blk>>>(dtb, alog);
    scan_kernel<<<96, 512>>>(Dv);
    gate_norm<<<M_TOK, blk>>>(nw);

    mma_gemm<<<dim3(DMODEL / 128, M_TOK / 128), blk, smem_bytes>>>(
        yhi, ylo, wohi, wolo, x, out, DMODEL, DINNER);
}

// round 8
// speedup vs baseline: 3.2034x; 1.0243x over previous
#include <cuda_runtime.h>
#include <cuda_bf16.h>
#include <cstdint>

#define M_TOK 8192
#define DMODEL 768
#define DINNER 1536
#define CONVD  1792
#define NH     24
#define HD     64
#define DST    128
#define NPROJ  3352
#define NPAD   3456            // 27 * 128
#define LSEQ   2048

// ---------------- device scratch (no allocation allowed) ----------------
__device__ float g_zx[M_TOK * NPROJ];    // in_proj output (z | xBC | dt)
__device__ float g_xc[M_TOK * CONVD];    // conv+silu output (xh | B | C)
__device__ float2 g_dtdA[96 * LSEQ];     // packed (dt, dA) per (b*NH+h, l)
__device__ float g_y [M_TOK * DINNER];   // scan output + D skip
__device__ float g_cstate[96 * 2 * 64 * 128];  // per-chunk final local state
__device__ float g_pref[96 * LSEQ];            // per-chunk dA prefix products

__device__ __nv_bfloat16 g_Xhi[M_TOK * DMODEL];
__device__ __nv_bfloat16 g_Xlo[M_TOK * DMODEL];
__device__ __nv_bfloat16 g_Wihi[NPAD * DMODEL];
__device__ __nv_bfloat16 g_Wilo[NPAD * DMODEL];
__device__ __nv_bfloat16 g_Yhi[M_TOK * DINNER];
__device__ __nv_bfloat16 g_Ylo[M_TOK * DINNER];
__device__ __nv_bfloat16 g_Wohi[DMODEL * DINNER];
__device__ __nv_bfloat16 g_Wolo[DMODEL * DINNER];

typedef unsigned long long ull;

__device__ __forceinline__ uint32_t smem_u32(const void* p) {
    uint32_t a;
    asm("{ .reg .u64 t; cvta.to.shared.u64 t, %1; cvt.u32.u64 %0, t; }"
        : "=r"(a) : "l"(p));
    return a;
}

__device__ __forceinline__ void cp16(uint32_t dst, const void* src) {
    asm volatile("cp.async.cg.shared.global [%0], [%1], 16;"
                 :: "r"(dst), "l"(src) : "memory");
}
__device__ __forceinline__ void cp8(uint32_t dst, const void* src) {
    asm volatile("cp.async.ca.shared.global [%0], [%1], 8;"
                 :: "r"(dst), "l"(src) : "memory");
}
__device__ __forceinline__ void cp4(uint32_t dst, const void* src) {
    asm volatile("cp.async.ca.shared.global [%0], [%1], 4;"
                 :: "r"(dst), "l"(src) : "memory");
}
__device__ __forceinline__ void cp_commit() {
    asm volatile("cp.async.commit_group;" ::: "memory");
}
__device__ __forceinline__ void cp_wait0() {
    asm volatile("cp.async.wait_group 0;" ::: "memory");
}
__device__ __forceinline__ void cp_wait1() {
    asm volatile("cp.async.wait_group 1;" ::: "memory");
}
__device__ __forceinline__ void cp_wait2() {
    asm volatile("cp.async.wait_group 2;" ::: "memory");
}

__device__ __forceinline__ void ldmx4(uint32_t* r, uint32_t addr) {
    asm volatile("ldmatrix.sync.aligned.m8n8.x4.shared.b16 {%0,%1,%2,%3}, [%4];"
                 : "=r"(r[0]), "=r"(r[1]), "=r"(r[2]), "=r"(r[3]) : "r"(addr));
}

__device__ __forceinline__ void mma16816(float* c, const uint32_t* a, const uint32_t* b) {
    asm volatile(
        "mma.sync.aligned.m16n8k16.row.col.f32.bf16.bf16.f32 "
        "{%0,%1,%2,%3}, {%4,%5,%6,%7}, {%8,%9}, {%0,%1,%2,%3};"
        : "+f"(c[0]), "+f"(c[1]), "+f"(c[2]), "+f"(c[3])
        : "r"(a[0]), "r"(a[1]), "r"(a[2]), "r"(a[3]), "r"(b[0]), "r"(b[1]));
}

// ---------------------------------------------------------------------------
// Tensor-core GEMM (NT): unchanged Round-5 geometry.
// ---------------------------------------------------------------------------
#define BK     64
#define LDT_B  144
#define TILE_B (128 * LDT_B)
#define STAGE_B (4 * TILE_B)

__global__ __launch_bounds__(256, 1)
void mma_gemm(const __nv_bfloat16* __restrict__ Ahi, const __nv_bfloat16* __restrict__ Alo,
              const __nv_bfloat16* __restrict__ Bhi, const __nv_bfloat16* __restrict__ Blo,
              const float* __restrict__ R, float* __restrict__ C,
              int Nact, int K)
{
    extern __shared__ char smem[];
    uint32_t sb = smem_u32(smem);
    int tid  = threadIdx.x;
    int wid  = tid >> 5, lane = tid & 31;
    int wm   = wid & 3, wn = wid >> 2;
    int m0   = blockIdx.y * 128, n0 = blockIdx.x * 128;

    const __nv_bfloat16* srcs[4] = {Ahi, Alo, Bhi, Blo};
    const size_t rowK = (size_t)K * 2;

    auto load_stage = [&](int s, int k0) {
        uint32_t d0 = sb + s * STAGE_B;
#pragma unroll
        for (int t = 0; t < 4; t++) {
            const char* gb = (const char*)srcs[t] + (size_t)(t < 2 ? m0 : n0) * rowK + k0 * 2;
#pragma unroll
            for (int i = 0; i < 4; i++) {
                int idx = tid + i * 256;
                int row = idx >> 3, ch = idx & 7;
                cp16(d0 + t * TILE_B + row * LDT_B + ch * 16, gb + (size_t)row * rowK + ch * 16);
            }
        }
        cp_commit();
    };

    float acc[2][8][4];
#pragma unroll
    for (int mt = 0; mt < 2; mt++)
#pragma unroll
        for (int nt = 0; nt < 8; nt++)
#pragma unroll
            for (int j = 0; j < 4; j++) acc[mt][nt][j] = 0.f;

    int nch = K / BK;
    load_stage(0, 0);

    int a_row = wm * 32 + (lane & 7) + ((lane >> 3) & 1) * 8;
    int a_cb  = ((lane >> 4) & 1) * 16;
    int b_row = wn * 64 + ((lane >> 4) & 1) * 8 + (lane & 7);
    int b_cb  = ((lane >> 3) & 1) * 16;

    for (int c = 0; c < nch; c++) {
        if (c + 1 < nch) { load_stage((c + 1) & 1, (c + 1) * BK); cp_wait1(); }
        else             { cp_wait0(); }
        __syncthreads();

        uint32_t st = sb + (c & 1) * STAGE_B;
        uint32_t Ah = st, Al = st + TILE_B, Bh = st + 2 * TILE_B, Bl = st + 3 * TILE_B;

#pragma unroll
        for (int kk = 0; kk < 4; kk++) {
            int kb = kk * 32;
            uint32_t ah[2][4], al[2][4];
#pragma unroll
            for (int mt = 0; mt < 2; mt++) {
                uint32_t off = (uint32_t)((a_row + mt * 16) * LDT_B + kb + a_cb);
                ldmx4(ah[mt], Ah + off);
                ldmx4(al[mt], Al + off);
            }
            uint32_t bh[8][2], bl[8][2];
#pragma unroll
            for (int q = 0; q < 4; q++) {
                uint32_t off = (uint32_t)((b_row + q * 16) * LDT_B + kb + b_cb);
                uint32_t r[4];
                ldmx4(r, Bh + off);
                bh[2*q][0] = r[0]; bh[2*q][1] = r[1]; bh[2*q+1][0] = r[2]; bh[2*q+1][1] = r[3];
                ldmx4(r, Bl + off);
                bl[2*q][0] = r[0]; bl[2*q][1] = r[1]; bl[2*q+1][0] = r[2]; bl[2*q+1][1] = r[3];
            }
#pragma unroll
            for (int mt = 0; mt < 2; mt++)
#pragma unroll
                for (int nt = 0; nt < 8; nt++) {
                    mma16816(acc[mt][nt], ah[mt], bh[nt]);
                    mma16816(acc[mt][nt], ah[mt], bl[nt]);
                    mma16816(acc[mt][nt], al[mt], bh[nt]);
                }
        }
        __syncthreads();
    }

    int l4 = lane >> 2, l2 = (lane & 3) * 2;
#pragma unroll
    for (int mt = 0; mt < 2; mt++) {
        int gm = m0 + wm * 32 + mt * 16 + l4;
#pragma unroll
        for (int nt = 0; nt < 8; nt++) {
            int gn = n0 + wn * 64 + nt * 8 + l2;
            if (gn < Nact) {
                size_t o0 = (size_t)gm * Nact + gn;
                size_t o1 = (size_t)(gm + 8) * Nact + gn;
                float2 v0 = make_float2(acc[mt][nt][0], acc[mt][nt][1]);
                float2 v1 = make_float2(acc[mt][nt][2], acc[mt][nt][3]);
                if (R) {
                    const float2 r0 = *(const float2*)&R[o0];
                    const float2 r1 = *(const float2*)&R[o1];
                    v0.x += r0.x; v0.y += r0.y; v1.x += r1.x; v1.y += r1.y;
                }
                *(float2*)&C[o0] = v0;
                *(float2*)&C[o1] = v1;
            }
        }
    }
}

// ---------------------------------------------------------------------------
__global__ void split_f32(const float* __restrict__ src,
                          __nv_bfloat16* __restrict__ hi, __nv_bfloat16* __restrict__ lo, int n)
{
    int i = blockIdx.x * blockDim.x + threadIdx.x;
    if (i >= n) return;
    float v = src[i];
    __nv_bfloat16 h = __float2bfloat16_rn(v);
    hi[i] = h;
    lo[i] = __float2bfloat16_rn(v - __bfloat162float(h));
}

__global__ void split_pad_w(const float* __restrict__ w,
                            __nv_bfloat16* __restrict__ hi, __nv_bfloat16* __restrict__ lo,
                            int nsrc, int ntot)
{
    int i = blockIdx.x * blockDim.x + threadIdx.x;
    if (i >= ntot) return;
    float v = (i < nsrc) ? w[i] : 0.f;
    __nv_bfloat16 h = __float2bfloat16_rn(v);
    hi[i] = h;
    lo[i] = __float2bfloat16_rn(v - __bfloat162float(h));
}

// ---------------------------------------------------------------------------
__device__ __forceinline__ ull pk2(float x, float y) {
    ull r; asm("mov.b64 %0,{%1,%2};" : "=l"(r) : "f"(x), "f"(y)); return r;
}
__device__ __forceinline__ float2 upk2(ull v) {
    float2 r; asm("mov.b64 {%0,%1},%2;" : "=f"(r.x), "=f"(r.y) : "l"(v)); return r;
}
__device__ __forceinline__ ull f2fma(ull a, ull b, ull c) {
    ull d; asm("fma.rn.f32x2 %0,%1,%2,%3;" : "=l"(d) : "l"(a), "l"(b), "l"(c)); return d;
}
__device__ __forceinline__ ull f2mul(ull a, ull b) {
    ull d; asm("mul.rn.f32x2 %0,%1,%2;" : "=l"(d) : "l"(a), "l"(b)); return d;
}

// ---------------------------------------------------------------------------
__global__ void conv_silu(const float* __restrict__ cw, const float* __restrict__ cb)
{
    int idx = blockIdx.x * blockDim.x + threadIdx.x;
    if (idx >= M_TOK * CONVD) return;
    int c = idx % CONVD, m = idx / CONVD;
    int l = m & (LSEQ - 1);
    float acc = cb[c];
#pragma unroll
    for (int k = 0; k < 4; k++) {
        int ll = l - 3 + k;
        if (ll >= 0)
            acc = fmaf(g_zx[(size_t)(m - 3 + k) * NPROJ + DINNER + c], cw[c * 4 + k], acc);
    }
    float s = 1.f / (1.f + __expf(-acc));
    g_xc[idx] = acc * s;
}

// ---------------------------------------------------------------------------
__global__ void dt_dA(const float* __restrict__ dtb, const float* __restrict__ alog)
{
    int idx = blockIdx.x * blockDim.x + threadIdx.x;
    if (idx >= M_TOK * NH) return;
    int h = idx % NH, m = idx / NH;
    int b = m / LSEQ, l = m % LSEQ;
    float v = g_zx[(size_t)m * NPROJ + DINNER + CONVD + h] + dtb[h];
    float sp = fmaxf(v, 0.f) + log1pf(expf(-fabsf(v)));
    float A = -expf(alog[h]);
    g_dtdA[(size_t)(b * NH + h) * LSEQ + l] = make_float2(sp, expf(sp * A));
}

// ---------------------------------------------------------------------------
// Chunked selective SSM scan. 3 time-chunks per (b,h): grid 288, 2 CTAs/SM.
// Each chunk runs the LOCAL scan (zero init state), stores:
//   - local y contribution (+ D skip) to g_y
//   - prefix products pref_t = prod(dA) over the chunk  (chunks >= 1)
//   - final local state Sl_c                           (chunks 0,1)
// fixup_kernel later adds pref_t * (C_t . S_init_c) for chunks 1,2.
// ---------------------------------------------------------------------------
#define NSTG 16
#define STGF 336
#define LCH  688                  // chunk lengths: 688, 688, 672

__global__ __launch_bounds__(512, 2)
void scan_kernel(const float* __restrict__ Dv)
{
    __shared__ __align__(16) float sh[NSTG][STGF];
    __shared__ __align__(16) float yb[8][512];
    uint32_t sb = smem_u32(sh);
    int bc = blockIdx.x;
    int bh = bc % 96;
    int c  = bc / 96;                  // 0..2
    int t0 = c * LCH;
    int T  = (c < 2) ? LCH : (LSEQ - 2 * LCH);
    int b = bh / NH, h = bh % NH;
    int tid = threadIdx.x;
    int p = tid >> 3, nb = tid & 7;
    float dh0 = (nb == 0) ? Dv[h] : 0.f;

    // loader setup (81 loader threads), offset by chunk start t0
    const char* src = nullptr;
    uint32_t dsto = 0;
    size_t stride = (size_t)CONVD * 4;
    const char* xcb = (const char*)(g_xc + ((size_t)b * LSEQ + t0) * CONVD);
    if (tid < 16) {                       // x: 16 x cp16
        src = xcb + (size_t)h * HD * 4 + tid * 16;
        dsto = tid * 16;
    } else if (tid < 48) {                // B: 32 x cp16, f4-interleaved
        int t = tid - 16;
        src = xcb + (size_t)DINNER * 4 + t * 16;
        dsto = 256 + (uint32_t)(((t & 3) * 8 + (t >> 2)) * 16);
    } else if (tid < 80) {                // C: 32 x cp16, f4-interleaved
        int t = tid - 48;
        src = xcb + (size_t)(DINNER + DST) * 4 + t * 16;
        dsto = 768 + (uint32_t)(((t & 3) * 8 + (t >> 2)) * 16);
    } else if (tid == 80) {               // dt,dA: 1 x cp8
        src = (const char*)(g_dtdA + (size_t)bh * LSEQ + t0);
        dsto = 1280;
        stride = 8;
    }

    auto issue_group = [&](int gq) {
#pragma unroll
        for (int q = 0; q < 4; q++) {
            int step = 4 * gq + q;
            if (step < T && tid <= 80) {
                uint32_t d = sb + (uint32_t)((step & (NSTG - 1)) * (STGF * 4)) + dsto;
                if (tid < 80) cp16(d, src); else cp8(d, src);
                src += stride;
            }
        }
        cp_commit();
    };

    issue_group(0); issue_group(1); issue_group(2);

    ull st[8];
#pragma unroll
    for (int i = 0; i < 8; i++) st[i] = 0ull;

    float* ybase = g_y + ((size_t)b * LSEQ + t0) * DINNER + h * HD;
    int rs = tid >> 6, rp = tid & 63;
    float run = 1.f;
    float* prefp = g_pref + (size_t)bh * LSEQ + t0;

    for (int g = 0; g < T / 4; g++) {
        cp_wait2();
        __syncthreads();
        issue_group(g + 3);

#pragma unroll
        for (int q = 0; q < 4; q++) {
            int l = 4 * g + q;
            const float* bp = sh[l & (NSTG - 1)];
            float xp  = bp[p];
            float2 da = *(const float2*)(bp + 320);
            float dtx = da.x * xp;
            ull dA2  = pk2(da.y, da.y);
            ull dtx2 = pk2(dtx, dtx);
            const ulonglong2* B4 = (const ulonglong2*)(bp + 64);
            const ulonglong2* C4 = (const ulonglong2*)(bp + 192);

            ull bb[8], cc[8];
#pragma unroll
            for (int j = 0; j < 4; j++) {
                ulonglong2 bv = B4[j * 8 + nb];
                ulonglong2 cv = C4[j * 8 + nb];
                bb[2*j] = bv.x; bb[2*j+1] = bv.y;
                cc[2*j] = cv.x; cc[2*j+1] = cv.y;
            }
            ull acc2 = 0ull;
#pragma unroll
            for (int i = 0; i < 8; i++) {
                st[i] = f2fma(st[i], dA2, f2mul(dtx2, bb[i]));
                acc2  = f2fma(st[i], cc[i], acc2);
            }
            float2 av = upk2(acc2);
            yb[l & 7][tid] = fmaf(dh0, xp, av.x + av.y);

            if (tid == 96 && c > 0) {      // serial dA prefix product
                run *= da.y;
                prefp[l] = run;
            }
        }

        if (g & 1) {
            __syncthreads();
            const float4* r4 = (const float4*)(yb[rs] + rp * 8);
            float4 v0 = r4[0], v1 = r4[1];
            float acc = ((v0.x + v0.y) + (v0.z + v0.w))
                      + ((v1.x + v1.y) + (v1.z + v1.w));
            int l0 = 4 * (g - 1);
            ybase[(size_t)(l0 + rs) * DINNER + rp] = acc;
        }
    }

    // store final local state for chunks 0,1 (consumed by fixup)
    if (c < 2) {
        ulonglong2* dst = (ulonglong2*)(g_cstate + ((size_t)bh * 2 + c) * 8192
                                        + p * 128 + nb * 16);
#pragma unroll
        for (int j = 0; j < 4; j++) {
            ulonglong2 v; v.x = st[2*j]; v.y = st[2*j+1];
            dst[j] = v;
        }
    }
}

// ---------------------------------------------------------------------------
// Fix-up: y[t] += pref_t * (C_t . S_init_c) for chunks 1,2 (each split in 2).
// S_init slice lives in registers; C streamed via cp.async ring.
// ---------------------------------------------------------------------------
#define FSTG 16
#define FSTGF 132

__global__ __launch_bounds__(512, 2)
void fixup_kernel()
{
    __shared__ __align__(16) float sh[FSTG][FSTGF];
    __shared__ __align__(16) float yb[8][512];
    uint32_t sb = smem_u32(sh);
    int bx = blockIdx.x;
    int bh = bx % 96;
    int r  = bx / 96;                 // 0..3
    int c  = 1 + (r >> 1);            // chunk 1 or 2
    int half = r & 1;
    int Tc = (c == 1) ? LCH : (LSEQ - 2 * LCH);
    int Th = Tc / 2;
    int t0 = c * LCH + half * Th;
    int b = bh / NH, h = bh % NH;
    int tid = threadIdx.x;
    int p = tid >> 3, nb = tid & 7;

    // S_init slice -> registers. S_init_1 = Sl_0 ; S_init_2 = Sl_1 + Q1*Sl_0
    float q1 = (c == 2) ? g_pref[(size_t)bh * LSEQ + 2 * LCH - 1] : 0.f;
    ull sini[8];
    {
        const float4* s1 = (const float4*)(g_cstate + ((size_t)bh * 2 + (c - 1)) * 8192
                                           + p * 128 + nb * 16);
        const float4* s0 = (const float4*)(g_cstate + ((size_t)bh * 2) * 8192
                                           + p * 128 + nb * 16);
#pragma unroll
        for (int i = 0; i < 4; i++) {
            float4 v = s1[i];
            if (c == 2) {
                float4 w = s0[i];
                v.x = fmaf(q1, w.x, v.x); v.y = fmaf(q1, w.y, v.y);
                v.z = fmaf(q1, w.z, v.z); v.w = fmaf(q1, w.w, v.w);
            }
            sini[2*i]   = pk2(v.x, v.y);
            sini[2*i+1] = pk2(v.z, v.w);
        }
    }

    // loaders: C (32 x cp16, f4-interleaved) + pref (1 x cp4)
    const char* src = nullptr;
    uint32_t dsto = 0;
    size_t stride = (size_t)CONVD * 4;
    if (tid < 32) {
        src = (const char*)(g_xc + ((size_t)b * LSEQ + t0) * CONVD + DINNER + DST) + tid * 16;
        dsto = (uint32_t)((((tid & 3) * 8) + (tid >> 2)) * 16);
    } else if (tid == 32) {
        src = (const char*)(g_pref + (size_t)bh * LSEQ + t0);
        dsto = 512;
        stride = 4;
    }

    auto issue_group = [&](int gq) {
#pragma unroll
        for (int q = 0; q < 4; q++) {
            int step = 4 * gq + q;
            if (step < Th && tid <= 32) {
                uint32_t d = sb + (uint32_t)((step & (FSTG - 1)) * (FSTGF * 4)) + dsto;
                if (tid < 32) cp16(d, src); else cp4(d, src);
                src += stride;
            }
        }
        cp_commit();
    };
    issue_group(0); issue_group(1); issue_group(2);

    float* ybase = g_y + ((size_t)b * LSEQ + t0) * DINNER + h * HD;
    int rs = tid >> 6, rp = tid & 63;

    for (int g = 0; g < Th / 4; g++) {
        cp_wait2();
        __syncthreads();
        issue_group(g + 3);

#pragma unroll
        for (int q = 0; q < 4; q++) {
            int l = 4 * g + q;
            const float* bp = sh[l & (FSTG - 1)];
            const ulonglong2* C4 = (const ulonglong2*)bp;
            ull cc[8];
#pragma unroll
            for (int j = 0; j < 4; j++) {
                ulonglong2 cv = C4[j * 8 + nb];
                cc[2*j] = cv.x; cc[2*j+1] = cv.y;
            }
            ull acc2 = 0ull;
#pragma unroll
            for (int i = 0; i < 8; i++) acc2 = f2fma(sini[i], cc[i], acc2);
            float2 av = upk2(acc2);
            yb[l & 7][tid] = (av.x + av.y) * bp[128];
        }

        if (g & 1) {
            __syncthreads();
            const float4* r4 = (const float4*)(yb[rs] + rp * 8);
            float4 v0 = r4[0], v1 = r4[1];
            float acc = ((v0.x + v0.y) + (v0.z + v0.w))
                      + ((v1.x + v1.y) + (v1.z + v1.w));
            int l0 = 4 * (g - 1);
            float* yp = ybase + (size_t)(l0 + rs) * DINNER + rp;
            *yp += acc;
        }
    }
}

// ---------------------------------------------------------------------------
__global__ __launch_bounds__(256)
void gate_norm(const float* __restrict__ nw)
{
    __shared__ float warpsum[8];
    __shared__ float stot;
    int m = blockIdx.x;
    int tid = threadIdx.x;
    float vals[6];
    float ss = 0.f;
#pragma unroll
    for (int j = 0; j < 6; j++) {
        int i = tid + j * 256;
        float yv = g_y[(size_t)m * DINNER + i];
        float zv = g_zx[(size_t)m * NPROJ + i];
        float g = zv / (1.f + __expf(-zv));
        float v = yv * g;
        vals[j] = v;
        ss = fmaf(v, v, ss);
    }
#pragma unroll
    for (int o = 16; o > 0; o >>= 1) ss += __shfl_xor_sync(0xffffffffu, ss, o);
    if ((tid & 31) == 0) warpsum[tid >> 5] = ss;
    __syncthreads();
    if (tid == 0) {
        float t = 0.f;
#pragma unroll
        for (int w = 0; w < 8; w++) t += warpsum[w];
        stot = t;
    }
    __syncthreads();
    float scale = rsqrtf(stot / (float)DINNER + 1e-5f);
#pragma unroll
    for (int j = 0; j < 6; j++) {
        int i = tid + j * 256;
        float v = vals[j] * scale * nw[i];
        __nv_bfloat16 hh = __float2bfloat16_rn(v);
        g_Yhi[(size_t)m * DINNER + i] = hh;
        g_Ylo[(size_t)m * DINNER + i] = __float2bfloat16_rn(v - __bfloat162float(hh));
    }
}

// ---------------------------------------------------------------------------
extern "C" void kernel_launch(void* const* d_in, const int* in_sizes, int n_in,
                              void* d_out, int out_size)
{
    const float* x    = (const float*)d_in[0];
    const float* wi   = (const float*)d_in[1];
    const float* cw   = (const float*)d_in[2];
    const float* cb   = (const float*)d_in[3];
    const float* dtb  = (const float*)d_in[4];
    const float* alog = (const float*)d_in[5];
    const float* Dv   = (const float*)d_in[6];
    const float* nw   = (const float*)d_in[7];
    const float* wo   = (const float*)d_in[8];
    float* out = (float*)d_out;

    float *zx;
    __nv_bfloat16 *xhi, *xlo, *wihi, *wilo, *yhi, *ylo, *wohi, *wolo;
    cudaGetSymbolAddress((void**)&zx,   g_zx);
    cudaGetSymbolAddress((void**)&xhi,  g_Xhi);
    cudaGetSymbolAddress((void**)&xlo,  g_Xlo);
    cudaGetSymbolAddress((void**)&wihi, g_Wihi);
    cudaGetSymbolAddress((void**)&wilo, g_Wilo);
    cudaGetSymbolAddress((void**)&yhi,  g_Yhi);
    cudaGetSymbolAddress((void**)&ylo,  g_Ylo);
    cudaGetSymbolAddress((void**)&wohi, g_Wohi);
    cudaGetSymbolAddress((void**)&wolo, g_Wolo);

    static const int smem_bytes = 2 * STAGE_B;  // 144 KB
    cudaFuncSetAttribute(mma_gemm, cudaFuncAttributeMaxDynamicSharedMemorySize, smem_bytes);

    dim3 blk(256);

    split_f32<<<(M_TOK * DMODEL + 255) / 256, blk>>>(x, xhi, xlo, M_TOK * DMODEL);
    split_pad_w<<<(NPAD * DMODEL + 255) / 256, blk>>>(wi, wihi, wilo,
                                                      NPROJ * DMODEL, NPAD * DMODEL);
    split_f32<<<(DMODEL * DINNER + 255) / 256, blk>>>(wo, wohi, wolo, DMODEL * DINNER);

    mma_gemm<<<dim3(NPAD / 128, M_TOK / 128), blk, smem_bytes>>>(
        xhi, xlo, wihi, wilo, nullptr, zx, NPROJ, DMODEL);

    conv_silu<<<(M_TOK * CONVD + 255) / 256, blk>>>(cw, cb);
    dt_dA<<<(M_TOK * NH + 255) / 256, blk>>>(dtb, alog);
    scan_kernel<<<288, 512>>>(Dv);
    fixup_kernel<<<384, 512>>>();
    gate_norm<<<M_TOK, blk>>>(nw);

    mma_gemm<<<dim3(DMODEL / 128, M_TOK / 128), blk, smem_bytes>>>(
        yhi, ylo, wohi, wolo, x, out, DMODEL, DINNER);
}

// round 9
// speedup vs baseline: 3.5675x; 1.1137x over previous
#include <cuda_runtime.h>
#include <cuda_bf16.h>
#include <cstdint>

#define M_TOK 8192
#define DMODEL 768
#define DINNER 1536
#define CONVD  1792
#define NH     24
#define HD     64
#define DST    128
#define NPROJ  3352
#define NPAD   3456            // 27 * 128
#define LSEQ   2048

// ---------------- device scratch (no allocation allowed) ----------------
__device__ float g_zx[M_TOK * NPROJ];    // in_proj output (z | xBC | dt)
__device__ float g_xc[M_TOK * CONVD];    // conv+silu output (xh | B | C)
__device__ float2 g_dtdA[96 * LSEQ];     // packed (dt, dA) per (b*NH+h, l)
__device__ float g_y [M_TOK * DINNER];   // scan output + D skip
__device__ float g_cstate[96 * 2 * 64 * 128];  // per-chunk final local state
__device__ float g_pref[96 * LSEQ];            // per-chunk dA prefix products

__device__ __nv_bfloat16 g_Xhi[M_TOK * DMODEL];
__device__ __nv_bfloat16 g_Xlo[M_TOK * DMODEL];
__device__ __nv_bfloat16 g_Wihi[NPAD * DMODEL];
__device__ __nv_bfloat16 g_Wilo[NPAD * DMODEL];
__device__ __nv_bfloat16 g_Yhi[M_TOK * DINNER];
__device__ __nv_bfloat16 g_Ylo[M_TOK * DINNER];
__device__ __nv_bfloat16 g_Wohi[DMODEL * DINNER];
__device__ __nv_bfloat16 g_Wolo[DMODEL * DINNER];

typedef unsigned long long ull;

__device__ __forceinline__ uint32_t smem_u32(const void* p) {
    uint32_t a;
    asm("{ .reg .u64 t; cvta.to.shared.u64 t, %1; cvt.u32.u64 %0, t; }"
        : "=r"(a) : "l"(p));
    return a;
}

__device__ __forceinline__ void cp16(uint32_t dst, const void* src) {
    asm volatile("cp.async.cg.shared.global [%0], [%1], 16;"
                 :: "r"(dst), "l"(src) : "memory");
}
__device__ __forceinline__ void cp8(uint32_t dst, const void* src) {
    asm volatile("cp.async.ca.shared.global [%0], [%1], 8;"
                 :: "r"(dst), "l"(src) : "memory");
}
__device__ __forceinline__ void cp4(uint32_t dst, const void* src) {
    asm volatile("cp.async.ca.shared.global [%0], [%1], 4;"
                 :: "r"(dst), "l"(src) : "memory");
}
__device__ __forceinline__ void cp_commit() {
    asm volatile("cp.async.commit_group;" ::: "memory");
}
__device__ __forceinline__ void cp_wait0() {
    asm volatile("cp.async.wait_group 0;" ::: "memory");
}
__device__ __forceinline__ void cp_wait1() {
    asm volatile("cp.async.wait_group 1;" ::: "memory");
}
__device__ __forceinline__ void cp_wait2() {
    asm volatile("cp.async.wait_group 2;" ::: "memory");
}

__device__ __forceinline__ void ldmx4(uint32_t* r, uint32_t addr) {
    asm volatile("ldmatrix.sync.aligned.m8n8.x4.shared.b16 {%0,%1,%2,%3}, [%4];"
                 : "=r"(r[0]), "=r"(r[1]), "=r"(r[2]), "=r"(r[3]) : "r"(addr));
}

__device__ __forceinline__ void mma16816(float* c, const uint32_t* a, const uint32_t* b) {
    asm volatile(
        "mma.sync.aligned.m16n8k16.row.col.f32.bf16.bf16.f32 "
        "{%0,%1,%2,%3}, {%4,%5,%6,%7}, {%8,%9}, {%0,%1,%2,%3};"
        : "+f"(c[0]), "+f"(c[1]), "+f"(c[2]), "+f"(c[3])
        : "r"(a[0]), "r"(a[1]), "r"(a[2]), "r"(a[3]), "r"(b[0]), "r"(b[1]));
}

// ---------------------------------------------------------------------------
// Tensor-core GEMM (NT): bf16 hi/lo 3-pass, 128x128 tile, 256 threads,
// K-chunk 64. NOW: 3-stage cp.async ring, ONE barrier per chunk.
// ---------------------------------------------------------------------------
#define BK     64
#define LDT_B  144
#define TILE_B (128 * LDT_B)       // 18432
#define STAGE_B (4 * TILE_B)       // 73728

__global__ __launch_bounds__(256, 1)
void mma_gemm(const __nv_bfloat16* __restrict__ Ahi, const __nv_bfloat16* __restrict__ Alo,
              const __nv_bfloat16* __restrict__ Bhi, const __nv_bfloat16* __restrict__ Blo,
              const float* __restrict__ R, float* __restrict__ C,
              int Nact, int K)
{
    extern __shared__ char smem[];
    uint32_t sb = smem_u32(smem);
    int tid  = threadIdx.x;
    int wid  = tid >> 5, lane = tid & 31;
    int wm   = wid & 3, wn = wid >> 2;
    int m0   = blockIdx.y * 128, n0 = blockIdx.x * 128;

    const __nv_bfloat16* srcs[4] = {Ahi, Alo, Bhi, Blo};
    const size_t rowK = (size_t)K * 2;

    auto load_stage = [&](int s, int k0) {
        uint32_t d0 = sb + s * STAGE_B;
#pragma unroll
        for (int t = 0; t < 4; t++) {
            const char* gb = (const char*)srcs[t] + (size_t)(t < 2 ? m0 : n0) * rowK + k0 * 2;
#pragma unroll
            for (int i = 0; i < 4; i++) {
                int idx = tid + i * 256;
                int row = idx >> 3, ch = idx & 7;
                cp16(d0 + t * TILE_B + row * LDT_B + ch * 16, gb + (size_t)row * rowK + ch * 16);
            }
        }
        cp_commit();
    };

    float acc[2][8][4];
#pragma unroll
    for (int mt = 0; mt < 2; mt++)
#pragma unroll
        for (int nt = 0; nt < 8; nt++)
#pragma unroll
            for (int j = 0; j < 4; j++) acc[mt][nt][j] = 0.f;

    int nch = K / BK;
    load_stage(0, 0);
    load_stage(1, BK);

    int a_row = wm * 32 + (lane & 7) + ((lane >> 3) & 1) * 8;
    int a_cb  = ((lane >> 4) & 1) * 16;
    int b_row = wn * 64 + ((lane >> 4) & 1) * 8 + (lane & 7);
    int b_cb  = ((lane >> 3) & 1) * 16;

    int sidx = 0;
    for (int c = 0; c < nch; c++) {
        if (c + 1 < nch) cp_wait1(); else cp_wait0();
        __syncthreads();                 // stage c visible; prev compute done
        if (c + 2 < nch) {
            int ns = sidx + 2; if (ns >= 3) ns -= 3;
            load_stage(ns, (c + 2) * BK);
        }

        uint32_t st = sb + sidx * STAGE_B;
        if (++sidx == 3) sidx = 0;
        uint32_t Ah = st, Al = st + TILE_B, Bh = st + 2 * TILE_B, Bl = st + 3 * TILE_B;

#pragma unroll
        for (int kk = 0; kk < 4; kk++) {
            int kb = kk * 32;
            uint32_t ah[2][4], al[2][4];
#pragma unroll
            for (int mt = 0; mt < 2; mt++) {
                uint32_t off = (uint32_t)((a_row + mt * 16) * LDT_B + kb + a_cb);
                ldmx4(ah[mt], Ah + off);
                ldmx4(al[mt], Al + off);
            }
            uint32_t bh[8][2], bl[8][2];
#pragma unroll
            for (int q = 0; q < 4; q++) {
                uint32_t off = (uint32_t)((b_row + q * 16) * LDT_B + kb + b_cb);
                uint32_t r[4];
                ldmx4(r, Bh + off);
                bh[2*q][0] = r[0]; bh[2*q][1] = r[1]; bh[2*q+1][0] = r[2]; bh[2*q+1][1] = r[3];
                ldmx4(r, Bl + off);
                bl[2*q][0] = r[0]; bl[2*q][1] = r[1]; bl[2*q+1][0] = r[2]; bl[2*q+1][1] = r[3];
            }
#pragma unroll
            for (int mt = 0; mt < 2; mt++)
#pragma unroll
                for (int nt = 0; nt < 8; nt++) {
                    mma16816(acc[mt][nt], ah[mt], bh[nt]);
                    mma16816(acc[mt][nt], ah[mt], bl[nt]);
                    mma16816(acc[mt][nt], al[mt], bh[nt]);
                }
        }
    }

    int l4 = lane >> 2, l2 = (lane & 3) * 2;
#pragma unroll
    for (int mt = 0; mt < 2; mt++) {
        int gm = m0 + wm * 32 + mt * 16 + l4;
#pragma unroll
        for (int nt = 0; nt < 8; nt++) {
            int gn = n0 + wn * 64 + nt * 8 + l2;
            if (gn < Nact) {
                size_t o0 = (size_t)gm * Nact + gn;
                size_t o1 = (size_t)(gm + 8) * Nact + gn;
                float2 v0 = make_float2(acc[mt][nt][0], acc[mt][nt][1]);
                float2 v1 = make_float2(acc[mt][nt][2], acc[mt][nt][3]);
                if (R) {
                    const float2 r0 = *(const float2*)&R[o0];
                    const float2 r1 = *(const float2*)&R[o1];
                    v0.x += r0.x; v0.y += r0.y; v1.x += r1.x; v1.y += r1.y;
                }
                *(float2*)&C[o0] = v0;
                *(float2*)&C[o1] = v1;
            }
        }
    }
}

// ---------------------------------------------------------------------------
__global__ void split_f32(const float* __restrict__ src,
                          __nv_bfloat16* __restrict__ hi, __nv_bfloat16* __restrict__ lo, int n)
{
    int i = blockIdx.x * blockDim.x + threadIdx.x;
    if (i >= n) return;
    float v = src[i];
    __nv_bfloat16 h = __float2bfloat16_rn(v);
    hi[i] = h;
    lo[i] = __float2bfloat16_rn(v - __bfloat162float(h));
}

__global__ void split_pad_w(const float* __restrict__ w,
                            __nv_bfloat16* __restrict__ hi, __nv_bfloat16* __restrict__ lo,
                            int nsrc, int ntot)
{
    int i = blockIdx.x * blockDim.x + threadIdx.x;
    if (i >= ntot) return;
    float v = (i < nsrc) ? w[i] : 0.f;
    __nv_bfloat16 h = __float2bfloat16_rn(v);
    hi[i] = h;
    lo[i] = __float2bfloat16_rn(v - __bfloat162float(h));
}

// ---------------------------------------------------------------------------
__device__ __forceinline__ ull pk2(float x, float y) {
    ull r; asm("mov.b64 %0,{%1,%2};" : "=l"(r) : "f"(x), "f"(y)); return r;
}
__device__ __forceinline__ float2 upk2(ull v) {
    float2 r; asm("mov.b64 {%0,%1},%2;" : "=f"(r.x), "=f"(r.y) : "l"(v)); return r;
}
__device__ __forceinline__ ull f2fma(ull a, ull b, ull c) {
    ull d; asm("fma.rn.f32x2 %0,%1,%2,%3;" : "=l"(d) : "l"(a), "l"(b), "l"(c)); return d;
}
__device__ __forceinline__ ull f2mul(ull a, ull b) {
    ull d; asm("mul.rn.f32x2 %0,%1,%2;" : "=l"(d) : "l"(a), "l"(b)); return d;
}

// ---------------------------------------------------------------------------
__global__ void conv_silu(const float* __restrict__ cw, const float* __restrict__ cb)
{
    int idx = blockIdx.x * blockDim.x + threadIdx.x;
    if (idx >= M_TOK * CONVD) return;
    int c = idx % CONVD, m = idx / CONVD;
    int l = m & (LSEQ - 1);
    float acc = cb[c];
#pragma unroll
    for (int k = 0; k < 4; k++) {
        int ll = l - 3 + k;
        if (ll >= 0)
            acc = fmaf(g_zx[(size_t)(m - 3 + k) * NPROJ + DINNER + c], cw[c * 4 + k], acc);
    }
    float s = 1.f / (1.f + __expf(-acc));
    g_xc[idx] = acc * s;
}

// ---------------------------------------------------------------------------
__global__ void dt_dA(const float* __restrict__ dtb, const float* __restrict__ alog)
{
    int idx = blockIdx.x * blockDim.x + threadIdx.x;
    if (idx >= M_TOK * NH) return;
    int h = idx % NH, m = idx / NH;
    int b = m / LSEQ, l = m % LSEQ;
    float v = g_zx[(size_t)m * NPROJ + DINNER + CONVD + h] + dtb[h];
    float sp = fmaxf(v, 0.f) + log1pf(expf(-fabsf(v)));
    float A = -expf(alog[h]);
    g_dtdA[(size_t)(b * NH + h) * LSEQ + l] = make_float2(sp, expf(sp * A));
}

// ---------------------------------------------------------------------------
// Chunked selective SSM scan, crossbar-optimized decomposition.
// 256 threads; thread (pg = tid>>4, nq = tid&15) owns p in [4pg,4pg+4),
// n in [8nq, 8nq+8): state = 16 ull.  Per-step smem reads: 1 x-LDS.128 +
// 2 B-LDS.128 + 2 C-LDS.128  (was 8 wide reads/thread at 512 thr).
// B/C stored interleaved at f4 granularity: global chunk t -> idx (t&1)*16+(t>>1).
// Partials staged in XOR-swizzled yb[8][1024]; bulk reduce every 8 steps.
// ---------------------------------------------------------------------------
#define NSTG 16
#define STGF 336
#define LCH  688                  // chunk lengths: 688, 688, 672

__global__ __launch_bounds__(256, 2)
void scan_kernel(const float* __restrict__ Dv)
{
    __shared__ __align__(16) float sh[NSTG][STGF];    // 21504 B
    __shared__ __align__(16) float yb[8][1024];       // 32768 B
    uint32_t sb = smem_u32(sh);
    int bc = blockIdx.x;
    int bh = bc % 96;
    int c  = bc / 96;                  // 0..2
    int t0 = c * LCH;
    int T  = (c < 2) ? LCH : (LSEQ - 2 * LCH);
    int b = bh / NH, h = bh % NH;
    int tid = threadIdx.x;
    int pg = tid >> 4, nq = tid & 15;
    int xorm = (pg & 1) * 16;
    float dh0 = (nq == 0) ? Dv[h] : 0.f;

    // loader setup (81 loader threads)
    const char* src = nullptr;
    uint32_t dsto = 0;
    size_t stride = (size_t)CONVD * 4;
    const char* xcb = (const char*)(g_xc + ((size_t)b * LSEQ + t0) * CONVD);
    if (tid < 16) {                       // x: 16 x cp16
        src = xcb + (size_t)h * HD * 4 + tid * 16;
        dsto = tid * 16;
    } else if (tid < 48) {                // B: 32 x cp16, chunk t -> (t&1)*16+(t>>1)
        int t = tid - 16;
        src = xcb + (size_t)DINNER * 4 + t * 16;
        dsto = 256 + (uint32_t)((((t & 1) * 16) + (t >> 1)) * 16);
    } else if (tid < 80) {                // C
        int t = tid - 48;
        src = xcb + (size_t)(DINNER + DST) * 4 + t * 16;
        dsto = 768 + (uint32_t)((((t & 1) * 16) + (t >> 1)) * 16);
    } else if (tid == 80) {               // dt,dA: 1 x cp8
        src = (const char*)(g_dtdA + (size_t)bh * LSEQ + t0);
        dsto = 1280;
        stride = 8;
    }

    auto issue_group = [&](int gq) {
#pragma unroll
        for (int q = 0; q < 4; q++) {
            int step = 4 * gq + q;
            if (step < T && tid <= 80) {
                uint32_t d = sb + (uint32_t)((step & (NSTG - 1)) * (STGF * 4)) + dsto;
                if (tid < 80) cp16(d, src); else cp8(d, src);
                src += stride;
            }
        }
        cp_commit();
    };

    issue_group(0); issue_group(1); issue_group(2);

    ull st[4][4];
#pragma unroll
    for (int pi = 0; pi < 4; pi++)
#pragma unroll
        for (int k = 0; k < 4; k++) st[pi][k] = 0ull;

    float* ybase = g_y + ((size_t)b * LSEQ + t0) * DINNER + h * HD;
    float run = 1.f;
    float* prefp = g_pref + (size_t)bh * LSEQ + t0;

    for (int g = 0; g < T / 4; g++) {
        cp_wait2();
        __syncthreads();
        issue_group(g + 3);

#pragma unroll
        for (int q = 0; q < 4; q++) {
            int l = 4 * g + q;
            const float* bp = sh[l & (NSTG - 1)];
            float4 xv = *(const float4*)(bp + 4 * pg);
            float2 da = *(const float2*)(bp + 320);
            ull dA2 = pk2(da.y, da.y);
            float xs[4] = {xv.x, xv.y, xv.z, xv.w};
            ull dtx2[4];
#pragma unroll
            for (int pi = 0; pi < 4; pi++) {
                float d = da.x * xs[pi];
                dtx2[pi] = pk2(d, d);
            }
            const ulonglong2* B4 = (const ulonglong2*)(bp + 64);
            const ulonglong2* C4 = (const ulonglong2*)(bp + 192);
            ull bb[4], cc[4];
#pragma unroll
            for (int j = 0; j < 2; j++) {
                ulonglong2 bv = B4[j * 16 + nq];
                ulonglong2 cv = C4[j * 16 + nq];
                bb[2*j] = bv.x; bb[2*j+1] = bv.y;
                cc[2*j] = cv.x; cc[2*j+1] = cv.y;
            }
            float* yrow = yb[l & 7] + 64 * pg;
#pragma unroll
            for (int pi = 0; pi < 4; pi++) {
                ull acc2 = 0ull;
#pragma unroll
                for (int k = 0; k < 4; k++) {
                    st[pi][k] = f2fma(st[pi][k], dA2, f2mul(dtx2[pi], bb[k]));
                    acc2 = f2fma(st[pi][k], cc[k], acc2);
                }
                float2 av = upk2(acc2);
                yrow[(16 * pi + nq) ^ xorm] = fmaf(dh0, xs[pi], av.x + av.y);
            }
            if (tid == 255 && c > 0) {      // serial dA prefix product
                run *= da.y;
                prefp[l] = run;
            }
        }

        if (g & 1) {
            __syncthreads();   // all partials of this 8-step window written
#pragma unroll
            for (int k = 0; k < 2; k++) {
                int o = tid + 256 * k;
                int s_ = o >> 6, p = o & 63;
                int rpg = p >> 2, rpi = p & 3;
                const float4* r4 = (const float4*)(yb[s_] + 64 * rpg
                                                   + (16 * (rpi ^ (rpg & 1))));
                float4 v0 = r4[0], v1 = r4[1], v2 = r4[2], v3 = r4[3];
                float acc = (((v0.x + v0.y) + (v0.z + v0.w))
                           + ((v1.x + v1.y) + (v1.z + v1.w)))
                          + (((v2.x + v2.y) + (v2.z + v2.w))
                           + ((v3.x + v3.y) + (v3.z + v3.w)));
                int l0 = 4 * (g - 1);
                ybase[(size_t)(l0 + s_) * DINNER + p] = acc;
            }
        }
    }

    // store final local state for chunks 0,1 (fixup input; layout [p][n])
    if (c < 2) {
        float* cs = g_cstate + ((size_t)bh * 2 + c) * 8192;
#pragma unroll
        for (int pi = 0; pi < 4; pi++) {
            int p = 4 * pg + pi;
#pragma unroll
            for (int j = 0; j < 2; j++) {
                float2 a = upk2(st[pi][2*j]);
                float2 d = upk2(st[pi][2*j+1]);
                float4 v = make_float4(a.x, a.y, d.x, d.y);
                *(float4*)(cs + p * 128 + 8 * nq + 4 * j) = v;
            }
        }
    }
}

// ---------------------------------------------------------------------------
// Fix-up: y[t] += pref_t * (C_t . S_init_c) for chunks 1,2 (each split in 2).
// ---------------------------------------------------------------------------
#define FSTG 16
#define FSTGF 132

__global__ __launch_bounds__(512, 2)
void fixup_kernel()
{
    __shared__ __align__(16) float sh[FSTG][FSTGF];
    __shared__ __align__(16) float yb[8][512];
    uint32_t sb = smem_u32(sh);
    int bx = blockIdx.x;
    int bh = bx % 96;
    int r  = bx / 96;                 // 0..3
    int c  = 1 + (r >> 1);            // chunk 1 or 2
    int half = r & 1;
    int Tc = (c == 1) ? LCH : (LSEQ - 2 * LCH);
    int Th = Tc / 2;
    int t0 = c * LCH + half * Th;
    int b = bh / NH, h = bh % NH;
    int tid = threadIdx.x;
    int p = tid >> 3, nb = tid & 7;

    float q1 = (c == 2) ? g_pref[(size_t)bh * LSEQ + 2 * LCH - 1] : 0.f;
    ull sini[8];
    {
        const float4* s1 = (const float4*)(g_cstate + ((size_t)bh * 2 + (c - 1)) * 8192
                                           + p * 128 + nb * 16);
        const float4* s0 = (const float4*)(g_cstate + ((size_t)bh * 2) * 8192
                                           + p * 128 + nb * 16);
#pragma unroll
        for (int i = 0; i < 4; i++) {
            float4 v = s1[i];
            if (c == 2) {
                float4 w = s0[i];
                v.x = fmaf(q1, w.x, v.x); v.y = fmaf(q1, w.y, v.y);
                v.z = fmaf(q1, w.z, v.z); v.w = fmaf(q1, w.w, v.w);
            }
            sini[2*i]   = pk2(v.x, v.y);
            sini[2*i+1] = pk2(v.z, v.w);
        }
    }

    const char* src = nullptr;
    uint32_t dsto = 0;
    size_t stride = (size_t)CONVD * 4;
    if (tid < 32) {
        src = (const char*)(g_xc + ((size_t)b * LSEQ + t0) * CONVD + DINNER + DST) + tid * 16;
        dsto = (uint32_t)((((tid & 3) * 8) + (tid >> 2)) * 16);
    } else if (tid == 32) {
        src = (const char*)(g_pref + (size_t)bh * LSEQ + t0);
        dsto = 512;
        stride = 4;
    }

    auto issue_group = [&](int gq) {
#pragma unroll
        for (int q = 0; q < 4; q++) {
            int step = 4 * gq + q;
            if (step < Th && tid <= 32) {
                uint32_t d = sb + (uint32_t)((step & (FSTG - 1)) * (FSTGF * 4)) + dsto;
                if (tid < 32) cp16(d, src); else cp4(d, src);
                src += stride;
            }
        }
        cp_commit();
    };
    issue_group(0); issue_group(1); issue_group(2);

    float* ybase = g_y + ((size_t)b * LSEQ + t0) * DINNER + h * HD;
    int rs = tid >> 6, rp = tid & 63;

    for (int g = 0; g < Th / 4; g++) {
        cp_wait2();
        __syncthreads();
        issue_group(g + 3);

#pragma unroll
        for (int q = 0; q < 4; q++) {
            int l = 4 * g + q;
            const float* bp = sh[l & (FSTG - 1)];
            const ulonglong2* C4 = (const ulonglong2*)bp;
            ull cc[8];
#pragma unroll
            for (int j = 0; j < 4; j++) {
                ulonglong2 cv = C4[j * 8 + nb];
                cc[2*j] = cv.x; cc[2*j+1] = cv.y;
            }
            ull acc2 = 0ull;
#pragma unroll
            for (int i = 0; i < 8; i++) acc2 = f2fma(sini[i], cc[i], acc2);
            float2 av = upk2(acc2);
            yb[l & 7][tid] = (av.x + av.y) * bp[128];
        }

        if (g & 1) {
            __syncthreads();
            const float4* r4 = (const float4*)(yb[rs] + rp * 8);
            float4 v0 = r4[0], v1 = r4[1];
            float acc = ((v0.x + v0.y) + (v0.z + v0.w))
                      + ((v1.x + v1.y) + (v1.z + v1.w));
            int l0 = 4 * (g - 1);
            float* yp = ybase + (size_t)(l0 + rs) * DINNER + rp;
            *yp += acc;
        }
    }
}

// ---------------------------------------------------------------------------
__global__ __launch_bounds__(256)
void gate_norm(const float* __restrict__ nw)
{
    __shared__ float warpsum[8];
    __shared__ float stot;
    int m = blockIdx.x;
    int tid = threadIdx.x;
    float vals[6];
    float ss = 0.f;
#pragma unroll
    for (int j = 0; j < 6; j++) {
        int i = tid + j * 256;
        float yv = g_y[(size_t)m * DINNER + i];
        float zv = g_zx[(size_t)m * NPROJ + i];
        float g = zv / (1.f + __expf(-zv));
        float v = yv * g;
        vals[j] = v;
        ss = fmaf(v, v, ss);
    }
#pragma unroll
    for (int o = 16; o > 0; o >>= 1) ss += __shfl_xor_sync(0xffffffffu, ss, o);
    if ((tid & 31) == 0) warpsum[tid >> 5] = ss;
    __syncthreads();
    if (tid == 0) {
        float t = 0.f;
#pragma unroll
        for (int w = 0; w < 8; w++) t += warpsum[w];
        stot = t;
    }
    __syncthreads();
    float scale = rsqrtf(stot / (float)DINNER + 1e-5f);
#pragma unroll
    for (int j = 0; j < 6; j++) {
        int i = tid + j * 256;
        float v = vals[j] * scale * nw[i];
        __nv_bfloat16 hh = __float2bfloat16_rn(v);
        g_Yhi[(size_t)m * DINNER + i] = hh;
        g_Ylo[(size_t)m * DINNER + i] = __float2bfloat16_rn(v - __bfloat162float(hh));
    }
}

// ---------------------------------------------------------------------------
extern "C" void kernel_launch(void* const* d_in, const int* in_sizes, int n_in,
                              void* d_out, int out_size)
{
    const float* x    = (const float*)d_in[0];
    const float* wi   = (const float*)d_in[1];
    const float* cw   = (const float*)d_in[2];
    const float* cb   = (const float*)d_in[3];
    const float* dtb  = (const float*)d_in[4];
    const float* alog = (const float*)d_in[5];
    const float* Dv   = (const float*)d_in[6];
    const float* nw   = (const float*)d_in[7];
    const float* wo   = (const float*)d_in[8];
    float* out = (float*)d_out;

    float *zx;
    __nv_bfloat16 *xhi, *xlo, *wihi, *wilo, *yhi, *ylo, *wohi, *wolo;
    cudaGetSymbolAddress((void**)&zx,   g_zx);
    cudaGetSymbolAddress((void**)&xhi,  g_Xhi);
    cudaGetSymbolAddress((void**)&xlo,  g_Xlo);
    cudaGetSymbolAddress((void**)&wihi, g_Wihi);
    cudaGetSymbolAddress((void**)&wilo, g_Wilo);
    cudaGetSymbolAddress((void**)&yhi,  g_Yhi);
    cudaGetSymbolAddress((void**)&ylo,  g_Ylo);
    cudaGetSymbolAddress((void**)&wohi, g_Wohi);
    cudaGetSymbolAddress((void**)&wolo, g_Wolo);

    static const int smem_bytes = 3 * STAGE_B;  // 221184 B (3-stage ring)
    cudaFuncSetAttribute(mma_gemm, cudaFuncAttributeMaxDynamicSharedMemorySize, smem_bytes);

    dim3 blk(256);

    split_f32<<<(M_TOK * DMODEL + 255) / 256, blk>>>(x, xhi, xlo, M_TOK * DMODEL);
    split_pad_w<<<(NPAD * DMODEL + 255) / 256, blk>>>(wi, wihi, wilo,
                                                      NPROJ * DMODEL, NPAD * DMODEL);
    split_f32<<<(DMODEL * DINNER + 255) / 256, blk>>>(wo, wohi, wolo, DMODEL * DINNER);

    mma_gemm<<<dim3(NPAD / 128, M_TOK / 128), blk, smem_bytes>>>(
        xhi, xlo, wihi, wilo, nullptr, zx, NPROJ, DMODEL);

    conv_silu<<<(M_TOK * CONVD + 255) / 256, blk>>>(cw, cb);
    dt_dA<<<(M_TOK * NH + 255) / 256, blk>>>(dtb, alog);
    scan_kernel<<<288, 256>>>(Dv);
    fixup_kernel<<<384, 512>>>();
    gate_norm<<<M_TOK, blk>>>(nw);

    mma_gemm<<<dim3(DMODEL / 128, M_TOK / 128), blk, smem_bytes>>>(
        yhi, ylo, wohi, wolo, x, out, DMODEL, DINNER);
}

// round 10
// speedup vs baseline: 3.5939x; 1.0074x over previous
#include <cuda_runtime.h>
#include <cuda_bf16.h>
#include <cstdint>

#define M_TOK 8192
#define DMODEL 768
#define DINNER 1536
#define CONVD  1792
#define NH     24
#define HD     64
#define DST    128
#define NPROJ  3352
#define NPAD   3456            // 54 * 64
#define LSEQ   2048

// ---------------- device scratch (no allocation allowed) ----------------
__device__ float g_zx[M_TOK * NPROJ];    // in_proj output (z | xBC | dt)
__device__ float g_xc[M_TOK * CONVD];    // conv+silu output (xh | B | C)
__device__ float2 g_dtdA[96 * LSEQ];     // packed (dt, dA) per (b*NH+h, l)
__device__ float g_y [M_TOK * DINNER];   // scan output + D skip
__device__ float g_cstate[96 * 2 * 64 * 128];  // per-chunk final local state
__device__ float g_pref[96 * LSEQ];            // per-chunk dA prefix products

__device__ __nv_bfloat16 g_Xhi[M_TOK * DMODEL];
__device__ __nv_bfloat16 g_Xlo[M_TOK * DMODEL];
__device__ __nv_bfloat16 g_Wihi[NPAD * DMODEL];
__device__ __nv_bfloat16 g_Wilo[NPAD * DMODEL];
__device__ __nv_bfloat16 g_Yhi[M_TOK * DINNER];
__device__ __nv_bfloat16 g_Ylo[M_TOK * DINNER];
__device__ __nv_bfloat16 g_Wohi[DMODEL * DINNER];
__device__ __nv_bfloat16 g_Wolo[DMODEL * DINNER];

typedef unsigned long long ull;

__device__ __forceinline__ uint32_t smem_u32(const void* p) {
    uint32_t a;
    asm("{ .reg .u64 t; cvta.to.shared.u64 t, %1; cvt.u32.u64 %0, t; }"
        : "=r"(a) : "l"(p));
    return a;
}

__device__ __forceinline__ void cp16(uint32_t dst, const void* src) {
    asm volatile("cp.async.cg.shared.global [%0], [%1], 16;"
                 :: "r"(dst), "l"(src) : "memory");
}
__device__ __forceinline__ void cp8(uint32_t dst, const void* src) {
    asm volatile("cp.async.ca.shared.global [%0], [%1], 8;"
                 :: "r"(dst), "l"(src) : "memory");
}
__device__ __forceinline__ void cp4(uint32_t dst, const void* src) {
    asm volatile("cp.async.ca.shared.global [%0], [%1], 4;"
                 :: "r"(dst), "l"(src) : "memory");
}
__device__ __forceinline__ void cp_commit() {
    asm volatile("cp.async.commit_group;" ::: "memory");
}
__device__ __forceinline__ void cp_wait0() {
    asm volatile("cp.async.wait_group 0;" ::: "memory");
}
__device__ __forceinline__ void cp_wait1() {
    asm volatile("cp.async.wait_group 1;" ::: "memory");
}
__device__ __forceinline__ void cp_wait2() {
    asm volatile("cp.async.wait_group 2;" ::: "memory");
}

__device__ __forceinline__ void ldmx4(uint32_t* r, uint32_t addr) {
    asm volatile("ldmatrix.sync.aligned.m8n8.x4.shared.b16 {%0,%1,%2,%3}, [%4];"
                 : "=r"(r[0]), "=r"(r[1]), "=r"(r[2]), "=r"(r[3]) : "r"(addr));
}

__device__ __forceinline__ void mma16816(float* c, const uint32_t* a, const uint32_t* b) {
    asm volatile(
        "mma.sync.aligned.m16n8k16.row.col.f32.bf16.bf16.f32 "
        "{%0,%1,%2,%3}, {%4,%5,%6,%7}, {%8,%9}, {%0,%1,%2,%3};"
        : "+f"(c[0]), "+f"(c[1]), "+f"(c[2]), "+f"(c[3])
        : "r"(a[0]), "r"(a[1]), "r"(a[2]), "r"(a[3]), "r"(b[0]), "r"(b[1]));
}

// ---------------------------------------------------------------------------
// Tensor-core GEMM (NT): bf16 hi/lo 3-pass.  NEW geometry: CTA tile 128x64,
// 8 warps (4m x 2n, warp tile 32x32), K-chunk 64, 2-stage ring,
// 110.6 KB smem -> 2 CTAs/SM for latency hiding.
// ---------------------------------------------------------------------------
#define BK      64
#define LDT_B   144
#define TILE_A  (128 * LDT_B)          // 18432
#define TILE_BB (64 * LDT_B)           // 9216
#define STAGE_B (2 * TILE_A + 2 * TILE_BB)  // 55296

__global__ __launch_bounds__(256, 2)
void mma_gemm(const __nv_bfloat16* __restrict__ Ahi, const __nv_bfloat16* __restrict__ Alo,
              const __nv_bfloat16* __restrict__ Bhi, const __nv_bfloat16* __restrict__ Blo,
              const float* __restrict__ R, float* __restrict__ C,
              int Nact, int K)
{
    extern __shared__ char smem[];
    uint32_t sb = smem_u32(smem);
    int tid  = threadIdx.x;
    int wid  = tid >> 5, lane = tid & 31;
    int wm   = wid & 3, wn = wid >> 2;        // warp tile 32x32
    int m0   = blockIdx.y * 128, n0 = blockIdx.x * 64;

    const __nv_bfloat16* srcs[4] = {Ahi, Alo, Bhi, Blo};
    const size_t rowK = (size_t)K * 2;

    auto load_stage = [&](int s, int k0) {
        uint32_t d0 = sb + s * STAGE_B;
#pragma unroll
        for (int t = 0; t < 2; t++) {          // A hi/lo: 128 rows
            const char* gb = (const char*)srcs[t] + (size_t)m0 * rowK + k0 * 2;
#pragma unroll
            for (int i = 0; i < 4; i++) {
                int idx = tid + i * 256;
                int row = idx >> 3, ch = idx & 7;
                cp16(d0 + t * TILE_A + row * LDT_B + ch * 16, gb + (size_t)row * rowK + ch * 16);
            }
        }
#pragma unroll
        for (int t = 0; t < 2; t++) {          // B hi/lo: 64 rows
            const char* gb = (const char*)srcs[2 + t] + (size_t)n0 * rowK + k0 * 2;
#pragma unroll
            for (int i = 0; i < 2; i++) {
                int idx = tid + i * 256;
                int row = idx >> 3, ch = idx & 7;
                cp16(d0 + 2 * TILE_A + t * TILE_BB + row * LDT_B + ch * 16,
                     gb + (size_t)row * rowK + ch * 16);
            }
        }
        cp_commit();
    };

    float acc[2][4][4];
#pragma unroll
    for (int mt = 0; mt < 2; mt++)
#pragma unroll
        for (int nt = 0; nt < 4; nt++)
#pragma unroll
            for (int j = 0; j < 4; j++) acc[mt][nt][j] = 0.f;

    int nch = K / BK;
    load_stage(0, 0);

    int a_row = wm * 32 + (lane & 7) + ((lane >> 3) & 1) * 8;
    int a_cb  = ((lane >> 4) & 1) * 16;
    int b_row = wn * 32 + ((lane >> 4) & 1) * 8 + (lane & 7);
    int b_cb  = ((lane >> 3) & 1) * 16;

    for (int c = 0; c < nch; c++) {
        if (c + 1 < nch) { load_stage((c + 1) & 1, (c + 1) * BK); cp_wait1(); }
        else             { cp_wait0(); }
        __syncthreads();

        uint32_t st = sb + (c & 1) * STAGE_B;
        uint32_t Ah = st, Al = st + TILE_A;
        uint32_t Bh = st + 2 * TILE_A, Bl = st + 2 * TILE_A + TILE_BB;

#pragma unroll
        for (int kk = 0; kk < 4; kk++) {
            int kb = kk * 32;
            uint32_t ah[2][4], al[2][4];
#pragma unroll
            for (int mt = 0; mt < 2; mt++) {
                uint32_t off = (uint32_t)((a_row + mt * 16) * LDT_B + kb + a_cb);
                ldmx4(ah[mt], Ah + off);
                ldmx4(al[mt], Al + off);
            }
            uint32_t bh[4][2], bl[4][2];
#pragma unroll
            for (int q = 0; q < 2; q++) {
                uint32_t off = (uint32_t)((b_row + q * 16) * LDT_B + kb + b_cb);
                uint32_t r[4];
                ldmx4(r, Bh + off);
                bh[2*q][0] = r[0]; bh[2*q][1] = r[1]; bh[2*q+1][0] = r[2]; bh[2*q+1][1] = r[3];
                ldmx4(r, Bl + off);
                bl[2*q][0] = r[0]; bl[2*q][1] = r[1]; bl[2*q+1][0] = r[2]; bl[2*q+1][1] = r[3];
            }
#pragma unroll
            for (int mt = 0; mt < 2; mt++)
#pragma unroll
                for (int nt = 0; nt < 4; nt++) {
                    mma16816(acc[mt][nt], ah[mt], bh[nt]);
                    mma16816(acc[mt][nt], ah[mt], bl[nt]);
                    mma16816(acc[mt][nt], al[mt], bh[nt]);
                }
        }
        __syncthreads();
    }

    int l4 = lane >> 2, l2 = (lane & 3) * 2;
#pragma unroll
    for (int mt = 0; mt < 2; mt++) {
        int gm = m0 + wm * 32 + mt * 16 + l4;
#pragma unroll
        for (int nt = 0; nt < 4; nt++) {
            int gn = n0 + wn * 32 + nt * 8 + l2;
            if (gn < Nact) {
                size_t o0 = (size_t)gm * Nact + gn;
                size_t o1 = (size_t)(gm + 8) * Nact + gn;
                float2 v0 = make_float2(acc[mt][nt][0], acc[mt][nt][1]);
                float2 v1 = make_float2(acc[mt][nt][2], acc[mt][nt][3]);
                if (R) {
                    const float2 r0 = *(const float2*)&R[o0];
                    const float2 r1 = *(const float2*)&R[o1];
                    v0.x += r0.x; v0.y += r0.y; v1.x += r1.x; v1.y += r1.y;
                }
                *(float2*)&C[o0] = v0;
                *(float2*)&C[o1] = v1;
            }
        }
    }
}

// ---------------------------------------------------------------------------
// fp32 -> bf16 hi/lo split, float4-vectorized
// ---------------------------------------------------------------------------
__device__ __forceinline__ void split4_store(__nv_bfloat16* hi, __nv_bfloat16* lo,
                                             int i4, float4 v)
{
    __nv_bfloat162 h0 = __floats2bfloat162_rn(v.x, v.y);
    __nv_bfloat162 h1 = __floats2bfloat162_rn(v.z, v.w);
    float2 f0 = __bfloat1622float2(h0);
    float2 f1 = __bfloat1622float2(h1);
    __nv_bfloat162 l0 = __floats2bfloat162_rn(v.x - f0.x, v.y - f0.y);
    __nv_bfloat162 l1 = __floats2bfloat162_rn(v.z - f1.x, v.w - f1.y);
    ((uint2*)hi)[i4] = make_uint2(*(uint32_t*)&h0, *(uint32_t*)&h1);
    ((uint2*)lo)[i4] = make_uint2(*(uint32_t*)&l0, *(uint32_t*)&l1);
}

__global__ void split_f32(const float* __restrict__ src,
                          __nv_bfloat16* __restrict__ hi, __nv_bfloat16* __restrict__ lo, int n4)
{
    int i = blockIdx.x * blockDim.x + threadIdx.x;
    if (i >= n4) return;
    split4_store(hi, lo, i, ((const float4*)src)[i]);
}

__global__ void split_pad_w(const float* __restrict__ w,
                            __nv_bfloat16* __restrict__ hi, __nv_bfloat16* __restrict__ lo,
                            int nsrc4, int ntot4)
{
    int i = blockIdx.x * blockDim.x + threadIdx.x;
    if (i >= ntot4) return;
    float4 v = make_float4(0.f, 0.f, 0.f, 0.f);
    if (i < nsrc4) v = ((const float4*)w)[i];
    split4_store(hi, lo, i, v);
}

// ---------------------------------------------------------------------------
__device__ __forceinline__ ull pk2(float x, float y) {
    ull r; asm("mov.b64 %0,{%1,%2};" : "=l"(r) : "f"(x), "f"(y)); return r;
}
__device__ __forceinline__ float2 upk2(ull v) {
    float2 r; asm("mov.b64 {%0,%1},%2;" : "=f"(r.x), "=f"(r.y) : "l"(v)); return r;
}
__device__ __forceinline__ ull f2fma(ull a, ull b, ull c) {
    ull d; asm("fma.rn.f32x2 %0,%1,%2,%3;" : "=l"(d) : "l"(a), "l"(b), "l"(c)); return d;
}
__device__ __forceinline__ ull f2mul(ull a, ull b) {
    ull d; asm("mul.rn.f32x2 %0,%1,%2;" : "=l"(d) : "l"(a), "l"(b)); return d;
}

// ---------------------------------------------------------------------------
// Causal depthwise conv1d + SiLU, float4 over 4 channels
// ---------------------------------------------------------------------------
__global__ void conv_silu(const float* __restrict__ cw, const float* __restrict__ cb)
{
    int idx = blockIdx.x * blockDim.x + threadIdx.x;
    if (idx >= M_TOK * (CONVD / 4)) return;
    int c4 = idx % (CONVD / 4), m = idx / (CONVD / 4);
    int c = c4 * 4;
    int l = m & (LSEQ - 1);
    float4 acc = *(const float4*)&cb[c];
    float4 w0 = ((const float4*)cw)[c];
    float4 w1 = ((const float4*)cw)[c + 1];
    float4 w2 = ((const float4*)cw)[c + 2];
    float4 w3 = ((const float4*)cw)[c + 3];
    const float* wk0 = (const float*)&w0;
    const float* wk1 = (const float*)&w1;
    const float* wk2 = (const float*)&w2;
    const float* wk3 = (const float*)&w3;
#pragma unroll
    for (int k = 0; k < 4; k++) {
        int ll = l - 3 + k;
        if (ll >= 0) {
            float4 xv = *(const float4*)&g_zx[(size_t)(m - 3 + k) * NPROJ + DINNER + c];
            acc.x = fmaf(xv.x, wk0[k], acc.x);
            acc.y = fmaf(xv.y, wk1[k], acc.y);
            acc.z = fmaf(xv.z, wk2[k], acc.z);
            acc.w = fmaf(xv.w, wk3[k], acc.w);
        }
    }
    acc.x *= 1.f / (1.f + __expf(-acc.x));
    acc.y *= 1.f / (1.f + __expf(-acc.y));
    acc.z *= 1.f / (1.f + __expf(-acc.z));
    acc.w *= 1.f / (1.f + __expf(-acc.w));
    *(float4*)&g_xc[(size_t)m * CONVD + c] = acc;
}

// ---------------------------------------------------------------------------
__global__ void dt_dA(const float* __restrict__ dtb, const float* __restrict__ alog)
{
    int idx = blockIdx.x * blockDim.x + threadIdx.x;
    if (idx >= M_TOK * NH) return;
    int h = idx % NH, m = idx / NH;
    int b = m / LSEQ, l = m % LSEQ;
    float v = g_zx[(size_t)m * NPROJ + DINNER + CONVD + h] + dtb[h];
    float sp = fmaxf(v, 0.f) + log1pf(expf(-fabsf(v)));
    float A = -expf(alog[h]);
    g_dtdA[(size_t)(b * NH + h) * LSEQ + l] = make_float2(sp, expf(sp * A));
}

// ---------------------------------------------------------------------------
// Chunked selective SSM scan (unchanged from Round 9).
// ---------------------------------------------------------------------------
#define NSTG 16
#define STGF 336
#define LCH  688

__global__ __launch_bounds__(256, 2)
void scan_kernel(const float* __restrict__ Dv)
{
    __shared__ __align__(16) float sh[NSTG][STGF];
    __shared__ __align__(16) float yb[8][1024];
    uint32_t sb = smem_u32(sh);
    int bc = blockIdx.x;
    int bh = bc % 96;
    int c  = bc / 96;
    int t0 = c * LCH;
    int T  = (c < 2) ? LCH : (LSEQ - 2 * LCH);
    int b = bh / NH, h = bh % NH;
    int tid = threadIdx.x;
    int pg = tid >> 4, nq = tid & 15;
    int xorm = (pg & 1) * 16;
    float dh0 = (nq == 0) ? Dv[h] : 0.f;

    const char* src = nullptr;
    uint32_t dsto = 0;
    size_t stride = (size_t)CONVD * 4;
    const char* xcb = (const char*)(g_xc + ((size_t)b * LSEQ + t0) * CONVD);
    if (tid < 16) {
        src = xcb + (size_t)h * HD * 4 + tid * 16;
        dsto = tid * 16;
    } else if (tid < 48) {
        int t = tid - 16;
        src = xcb + (size_t)DINNER * 4 + t * 16;
        dsto = 256 + (uint32_t)((((t & 1) * 16) + (t >> 1)) * 16);
    } else if (tid < 80) {
        int t = tid - 48;
        src = xcb + (size_t)(DINNER + DST) * 4 + t * 16;
        dsto = 768 + (uint32_t)((((t & 1) * 16) + (t >> 1)) * 16);
    } else if (tid == 80) {
        src = (const char*)(g_dtdA + (size_t)bh * LSEQ + t0);
        dsto = 1280;
        stride = 8;
    }

    auto issue_group = [&](int gq) {
#pragma unroll
        for (int q = 0; q < 4; q++) {
            int step = 4 * gq + q;
            if (step < T && tid <= 80) {
                uint32_t d = sb + (uint32_t)((step & (NSTG - 1)) * (STGF * 4)) + dsto;
                if (tid < 80) cp16(d, src); else cp8(d, src);
                src += stride;
            }
        }
        cp_commit();
    };

    issue_group(0); issue_group(1); issue_group(2);

    ull st[4][4];
#pragma unroll
    for (int pi = 0; pi < 4; pi++)
#pragma unroll
        for (int k = 0; k < 4; k++) st[pi][k] = 0ull;

    float* ybase = g_y + ((size_t)b * LSEQ + t0) * DINNER + h * HD;
    float run = 1.f;
    float* prefp = g_pref + (size_t)bh * LSEQ + t0;

    for (int g = 0; g < T / 4; g++) {
        cp_wait2();
        __syncthreads();
        issue_group(g + 3);

#pragma unroll
        for (int q = 0; q < 4; q++) {
            int l = 4 * g + q;
            const float* bp = sh[l & (NSTG - 1)];
            float4 xv = *(const float4*)(bp + 4 * pg);
            float2 da = *(const float2*)(bp + 320);
            ull dA2 = pk2(da.y, da.y);
            float xs[4] = {xv.x, xv.y, xv.z, xv.w};
            ull dtx2[4];
#pragma unroll
            for (int pi = 0; pi < 4; pi++) {
                float d = da.x * xs[pi];
                dtx2[pi] = pk2(d, d);
            }
            const ulonglong2* B4 = (const ulonglong2*)(bp + 64);
            const ulonglong2* C4 = (const ulonglong2*)(bp + 192);
            ull bb[4], cc[4];
#pragma unroll
            for (int j = 0; j < 2; j++) {
                ulonglong2 bv = B4[j * 16 + nq];
                ulonglong2 cv = C4[j * 16 + nq];
                bb[2*j] = bv.x; bb[2*j+1] = bv.y;
                cc[2*j] = cv.x; cc[2*j+1] = cv.y;
            }
            float* yrow = yb[l & 7] + 64 * pg;
#pragma unroll
            for (int pi = 0; pi < 4; pi++) {
                ull acc2 = 0ull;
#pragma unroll
                for (int k = 0; k < 4; k++) {
                    st[pi][k] = f2fma(st[pi][k], dA2, f2mul(dtx2[pi], bb[k]));
                    acc2 = f2fma(st[pi][k], cc[k], acc2);
                }
                float2 av = upk2(acc2);
                yrow[(16 * pi + nq) ^ xorm] = fmaf(dh0, xs[pi], av.x + av.y);
            }
            if (tid == 255 && c > 0) {
                run *= da.y;
                prefp[l] = run;
            }
        }

        if (g & 1) {
            __syncthreads();
#pragma unroll
            for (int k = 0; k < 2; k++) {
                int o = tid + 256 * k;
                int s_ = o >> 6, p = o & 63;
                int rpg = p >> 2, rpi = p & 3;
                const float4* r4 = (const float4*)(yb[s_] + 64 * rpg
                                                   + (16 * (rpi ^ (rpg & 1))));
                float4 v0 = r4[0], v1 = r4[1], v2 = r4[2], v3 = r4[3];
                float acc = (((v0.x + v0.y) + (v0.z + v0.w))
                           + ((v1.x + v1.y) + (v1.z + v1.w)))
                          + (((v2.x + v2.y) + (v2.z + v2.w))
                           + ((v3.x + v3.y) + (v3.z + v3.w)));
                int l0 = 4 * (g - 1);
                ybase[(size_t)(l0 + s_) * DINNER + p] = acc;
            }
        }
    }

    if (c < 2) {
        float* cs = g_cstate + ((size_t)bh * 2 + c) * 8192;
#pragma unroll
        for (int pi = 0; pi < 4; pi++) {
            int p = 4 * pg + pi;
#pragma unroll
            for (int j = 0; j < 2; j++) {
                float2 a = upk2(st[pi][2*j]);
                float2 d = upk2(st[pi][2*j+1]);
                float4 v = make_float4(a.x, a.y, d.x, d.y);
                *(float4*)(cs + p * 128 + 8 * nq + 4 * j) = v;
            }
        }
    }
}

// ---------------------------------------------------------------------------
// Fix-up (unchanged from Round 9).
// ---------------------------------------------------------------------------
#define FSTG 16
#define FSTGF 132

__global__ __launch_bounds__(512, 2)
void fixup_kernel()
{
    __shared__ __align__(16) float sh[FSTG][FSTGF];
    __shared__ __align__(16) float yb[8][512];
    uint32_t sb = smem_u32(sh);
    int bx = blockIdx.x;
    int bh = bx % 96;
    int r  = bx / 96;
    int c  = 1 + (r >> 1);
    int half = r & 1;
    int Tc = (c == 1) ? LCH : (LSEQ - 2 * LCH);
    int Th = Tc / 2;
    int t0 = c * LCH + half * Th;
    int b = bh / NH, h = bh % NH;
    int tid = threadIdx.x;
    int p = tid >> 3, nb = tid & 7;

    float q1 = (c == 2) ? g_pref[(size_t)bh * LSEQ + 2 * LCH - 1] : 0.f;
    ull sini[8];
    {
        const float4* s1 = (const float4*)(g_cstate + ((size_t)bh * 2 + (c - 1)) * 8192
                                           + p * 128 + nb * 16);
        const float4* s0 = (const float4*)(g_cstate + ((size_t)bh * 2) * 8192
                                           + p * 128 + nb * 16);
#pragma unroll
        for (int i = 0; i < 4; i++) {
            float4 v = s1[i];
            if (c == 2) {
                float4 w = s0[i];
                v.x = fmaf(q1, w.x, v.x); v.y = fmaf(q1, w.y, v.y);
                v.z = fmaf(q1, w.z, v.z); v.w = fmaf(q1, w.w, v.w);
            }
            sini[2*i]   = pk2(v.x, v.y);
            sini[2*i+1] = pk2(v.z, v.w);
        }
    }

    const char* src = nullptr;
    uint32_t dsto = 0;
    size_t stride = (size_t)CONVD * 4;
    if (tid < 32) {
        src = (const char*)(g_xc + ((size_t)b * LSEQ + t0) * CONVD + DINNER + DST) + tid * 16;
        dsto = (uint32_t)((((tid & 3) * 8) + (tid >> 2)) * 16);
    } else if (tid == 32) {
        src = (const char*)(g_pref + (size_t)bh * LSEQ + t0);
        dsto = 512;
        stride = 4;
    }

    auto issue_group = [&](int gq) {
#pragma unroll
        for (int q = 0; q < 4; q++) {
            int step = 4 * gq + q;
            if (step < Th && tid <= 32) {
                uint32_t d = sb + (uint32_t)((step & (FSTG - 1)) * (FSTGF * 4)) + dsto;
                if (tid < 32) cp16(d, src); else cp4(d, src);
                src += stride;
            }
        }
        cp_commit();
    };
    issue_group(0); issue_group(1); issue_group(2);

    float* ybase = g_y + ((size_t)b * LSEQ + t0) * DINNER + h * HD;
    int rs = tid >> 6, rp = tid & 63;

    for (int g = 0; g < Th / 4; g++) {
        cp_wait2();
        __syncthreads();
        issue_group(g + 3);

#pragma unroll
        for (int q = 0; q < 4; q++) {
            int l = 4 * g + q;
            const float* bp = sh[l & (FSTG - 1)];
            const ulonglong2* C4 = (const ulonglong2*)bp;
            ull cc[8];
#pragma unroll
            for (int j = 0; j < 4; j++) {
                ulonglong2 cv = C4[j * 8 + nb];
                cc[2*j] = cv.x; cc[2*j+1] = cv.y;
            }
            ull acc2 = 0ull;
#pragma unroll
            for (int i = 0; i < 8; i++) acc2 = f2fma(sini[i], cc[i], acc2);
            float2 av = upk2(acc2);
            yb[l & 7][tid] = (av.x + av.y) * bp[128];
        }

        if (g & 1) {
            __syncthreads();
            const float4* r4 = (const float4*)(yb[rs] + rp * 8);
            float4 v0 = r4[0], v1 = r4[1];
            float acc = ((v0.x + v0.y) + (v0.z + v0.w))
                      + ((v1.x + v1.y) + (v1.z + v1.w));
            int l0 = 4 * (g - 1);
            float* yp = ybase + (size_t)(l0 + rs) * DINNER + rp;
            *yp += acc;
        }
    }
}

// ---------------------------------------------------------------------------
// gate + rmsnorm, float4-vectorized (384 threads x 1 float4 = 1536)
// ---------------------------------------------------------------------------
__global__ __launch_bounds__(384)
void gate_norm(const float* __restrict__ nw)
{
    __shared__ float warpsum[12];
    __shared__ float stot;
    int m = blockIdx.x;
    int tid = threadIdx.x;
    float4 yv = ((const float4*)(g_y + (size_t)m * DINNER))[tid];
    float4 zv = ((const float4*)(g_zx + (size_t)m * NPROJ))[tid];
    float4 v;
    v.x = yv.x * (zv.x / (1.f + __expf(-zv.x)));
    v.y = yv.y * (zv.y / (1.f + __expf(-zv.y)));
    v.z = yv.z * (zv.z / (1.f + __expf(-zv.z)));
    v.w = yv.w * (zv.w / (1.f + __expf(-zv.w)));
    float ss = fmaf(v.x, v.x, fmaf(v.y, v.y, fmaf(v.z, v.z, v.w * v.w)));
#pragma unroll
    for (int o = 16; o > 0; o >>= 1) ss += __shfl_xor_sync(0xffffffffu, ss, o);
    if ((tid & 31) == 0) warpsum[tid >> 5] = ss;
    __syncthreads();
    if (tid == 0) {
        float t = 0.f;
#pragma unroll
        for (int w = 0; w < 12; w++) t += warpsum[w];
        stot = t;
    }
    __syncthreads();
    float scale = rsqrtf(stot / (float)DINNER + 1e-5f);
    float4 nv = ((const float4*)nw)[tid];
    v.x *= scale * nv.x; v.y *= scale * nv.y;
    v.z *= scale * nv.z; v.w *= scale * nv.w;
    split4_store(g_Yhi + (size_t)m * DINNER, g_Ylo + (size_t)m * DINNER, tid, v);
}

// ---------------------------------------------------------------------------
extern "C" void kernel_launch(void* const* d_in, const int* in_sizes, int n_in,
                              void* d_out, int out_size)
{
    const float* x    = (const float*)d_in[0];
    const float* wi   = (const float*)d_in[1];
    const float* cw   = (const float*)d_in[2];
    const float* cb   = (const float*)d_in[3];
    const float* dtb  = (const float*)d_in[4];
    const float* alog = (const float*)d_in[5];
    const float* Dv   = (const float*)d_in[6];
    const float* nw   = (const float*)d_in[7];
    const float* wo   = (const float*)d_in[8];
    float* out = (float*)d_out;

    float *zx;
    __nv_bfloat16 *xhi, *xlo, *wihi, *wilo, *yhi, *ylo, *wohi, *wolo;
    cudaGetSymbolAddress((void**)&zx,   g_zx);
    cudaGetSymbolAddress((void**)&xhi,  g_Xhi);
    cudaGetSymbolAddress((void**)&xlo,  g_Xlo);
    cudaGetSymbolAddress((void**)&wihi, g_Wihi);
    cudaGetSymbolAddress((void**)&wilo, g_Wilo);
    cudaGetSymbolAddress((void**)&yhi,  g_Yhi);
    cudaGetSymbolAddress((void**)&ylo,  g_Ylo);
    cudaGetSymbolAddress((void**)&wohi, g_Wohi);
    cudaGetSymbolAddress((void**)&wolo, g_Wolo);

    static const int smem_bytes = 2 * STAGE_B;  // 110592 B -> 2 CTAs/SM
    cudaFuncSetAttribute(mma_gemm, cudaFuncAttributeMaxDynamicSharedMemorySize, smem_bytes);

    dim3 blk(256);

    split_f32<<<(M_TOK * DMODEL / 4 + 255) / 256, blk>>>(x, xhi, xlo, M_TOK * DMODEL / 4);
    split_pad_w<<<(NPAD * DMODEL / 4 + 255) / 256, blk>>>(wi, wihi, wilo,
                                                          NPROJ * DMODEL / 4, NPAD * DMODEL / 4);
    split_f32<<<(DMODEL * DINNER / 4 + 255) / 256, blk>>>(wo, wohi, wolo, DMODEL * DINNER / 4);

    mma_gemm<<<dim3(NPAD / 64, M_TOK / 128), blk, smem_bytes>>>(
        xhi, xlo, wihi, wilo, nullptr, zx, NPROJ, DMODEL);

    conv_silu<<<(M_TOK * (CONVD / 4) + 255) / 256, blk>>>(cw, cb);
    dt_dA<<<(M_TOK * NH + 255) / 256, blk>>>(dtb, alog);
    scan_kernel<<<288, 256>>>(Dv);
    fixup_kernel<<<384, 512>>>();
    gate_norm<<<M_TOK, 384>>>(nw);

    mma_gemm<<<dim3(DMODEL / 64, M_TOK / 128), blk, smem_bytes>>>(
        yhi, ylo, wohi, wolo, x, out, DMODEL, DINNER);
}

// round 11
// speedup vs baseline: 3.9934x; 1.1112x over previous
#include <cuda_runtime.h>
#include <cuda_fp16.h>
#include <cuda_bf16.h>
#include <cstdint>

#define M_TOK 8192
#define DMODEL 768
#define DINNER 1536
#define CONVD  1792
#define NH     24
#define HD     64
#define DST    128
#define NPROJ  3352
#define NPAD   3456
#define LSEQ   2048

// ---------------- device scratch (no allocation allowed) ----------------
__device__ float g_zx[M_TOK * NPROJ];    // in_proj output (z | xBC | dt-unused)
__device__ float g_xc[M_TOK * CONVD];    // conv+silu output (xh | B | C)
__device__ float2 g_dtdA[96 * LSEQ];     // packed (dt, dA) per (b*NH+h, l)
__device__ float g_y [M_TOK * DINNER];   // scan output + D skip
__device__ float g_cstate[96 * 2 * 64 * 128];
__device__ float g_pref[96 * LSEQ];

__device__ __half g_Xhi[M_TOK * DMODEL];
__device__ __half g_Xlo[M_TOK * DMODEL];
__device__ __half g_Wih[NPAD * DMODEL];
__device__ __half g_Yhi[M_TOK * DINNER];
__device__ __half g_Ylo[M_TOK * DINNER];
__device__ __half g_Woh[DMODEL * DINNER];

typedef unsigned long long ull;

__device__ __forceinline__ uint32_t smem_u32(const void* p) {
    uint32_t a;
    asm("{ .reg .u64 t; cvta.to.shared.u64 t, %1; cvt.u32.u64 %0, t; }"
        : "=r"(a) : "l"(p));
    return a;
}

__device__ __forceinline__ void cp16(uint32_t dst, const void* src) {
    asm volatile("cp.async.cg.shared.global [%0], [%1], 16;"
                 :: "r"(dst), "l"(src) : "memory");
}
__device__ __forceinline__ void cp8(uint32_t dst, const void* src) {
    asm volatile("cp.async.ca.shared.global [%0], [%1], 8;"
                 :: "r"(dst), "l"(src) : "memory");
}
__device__ __forceinline__ void cp4(uint32_t dst, const void* src) {
    asm volatile("cp.async.ca.shared.global [%0], [%1], 4;"
                 :: "r"(dst), "l"(src) : "memory");
}
__device__ __forceinline__ void cp_commit() {
    asm volatile("cp.async.commit_group;" ::: "memory");
}
__device__ __forceinline__ void cp_wait0() {
    asm volatile("cp.async.wait_group 0;" ::: "memory");
}
__device__ __forceinline__ void cp_wait1() {
    asm volatile("cp.async.wait_group 1;" ::: "memory");
}
__device__ __forceinline__ void cp_wait2() {
    asm volatile("cp.async.wait_group 2;" ::: "memory");
}

__device__ __forceinline__ void ldmx4(uint32_t* r, uint32_t addr) {
    asm volatile("ldmatrix.sync.aligned.m8n8.x4.shared.b16 {%0,%1,%2,%3}, [%4];"
                 : "=r"(r[0]), "=r"(r[1]), "=r"(r[2]), "=r"(r[3]) : "r"(addr));
}

__device__ __forceinline__ void mma16816h(float* c, const uint32_t* a, const uint32_t* b) {
    asm volatile(
        "mma.sync.aligned.m16n8k16.row.col.f32.f16.f16.f32 "
        "{%0,%1,%2,%3}, {%4,%5,%6,%7}, {%8,%9}, {%0,%1,%2,%3};"
        : "+f"(c[0]), "+f"(c[1]), "+f"(c[2]), "+f"(c[3])
        : "r"(a[0]), "r"(a[1]), "r"(a[2]), "r"(a[3]), "r"(b[0]), "r"(b[1]));
}

// ---------------------------------------------------------------------------
// fp16 2-pass GEMM (NT): C = A*B^T with A = Ah+Al (fp16 split), B = Bh (fp16).
// CTA tile 256x128, 8 warps (4m x 2n, warp tile 64x64), K-chunk 64,
// 2-stage cp.async ring (184 KB smem).
// ---------------------------------------------------------------------------
#define BK      64
#define LDT_B   144
#define ROW_A   256
#define ROW_BT  128
#define STAGE_B ((2 * ROW_A + ROW_BT) * LDT_B)   // 92160

__global__ __launch_bounds__(256, 1)
void mma_gemm(const __half* __restrict__ Ahi, const __half* __restrict__ Alo,
              const __half* __restrict__ Bh_,
              const float* __restrict__ R, float* __restrict__ C,
              int Nact, int K)
{
    extern __shared__ char smem[];
    uint32_t sb = smem_u32(smem);
    int tid  = threadIdx.x;
    int wid  = tid >> 5, lane = tid & 31;
    int wm   = wid & 3, wn = wid >> 2;        // warp tile 64x64
    int m0   = blockIdx.y * 256, n0 = blockIdx.x * 128;

    const size_t rowK = (size_t)K * 2;

    auto load_stage = [&](int s, int k0) {
        uint32_t d0 = sb + s * STAGE_B;
#pragma unroll
        for (int i = 0; i < 20; i++) {
            int idx = tid + i * 256;
            int row = idx >> 3, ch = idx & 7;
            const char* src;
            if (row < ROW_A)
                src = (const char*)Ahi + (size_t)(m0 + row) * rowK + k0 * 2;
            else if (row < 2 * ROW_A)
                src = (const char*)Alo + (size_t)(m0 + row - ROW_A) * rowK + k0 * 2;
            else
                src = (const char*)Bh_ + (size_t)(n0 + row - 2 * ROW_A) * rowK + k0 * 2;
            cp16(d0 + row * LDT_B + ch * 16, src + ch * 16);
        }
        cp_commit();
    };

    float acc[4][8][4];
#pragma unroll
    for (int mt = 0; mt < 4; mt++)
#pragma unroll
        for (int nt = 0; nt < 8; nt++)
#pragma unroll
            for (int j = 0; j < 4; j++) acc[mt][nt][j] = 0.f;

    int nch = K / BK;
    load_stage(0, 0);

    int a_row = wm * 64 + (lane & 7) + ((lane >> 3) & 1) * 8;
    int a_cb  = ((lane >> 4) & 1) * 16;
    int b_row = wn * 64 + ((lane >> 4) & 1) * 8 + (lane & 7);
    int b_cb  = ((lane >> 3) & 1) * 16;

    for (int c = 0; c < nch; c++) {
        if (c + 1 < nch) { load_stage((c + 1) & 1, (c + 1) * BK); cp_wait1(); }
        else             { cp_wait0(); }
        __syncthreads();

        uint32_t st = sb + (c & 1) * STAGE_B;
        uint32_t Ah = st;
        uint32_t Al = st + ROW_A * LDT_B;
        uint32_t Bh = st + 2 * ROW_A * LDT_B;

#pragma unroll
        for (int kk = 0; kk < 4; kk++) {
            int kb = kk * 32;
            uint32_t ah[4][4], al[4][4];
#pragma unroll
            for (int mt = 0; mt < 4; mt++) {
                uint32_t off = (uint32_t)((a_row + mt * 16) * LDT_B + kb + a_cb);
                ldmx4(ah[mt], Ah + off);
                ldmx4(al[mt], Al + off);
            }
            uint32_t bh[8][2];
#pragma unroll
            for (int q = 0; q < 4; q++) {
                uint32_t off = (uint32_t)((b_row + q * 16) * LDT_B + kb + b_cb);
                uint32_t r[4];
                ldmx4(r, Bh + off);
                bh[2*q][0] = r[0]; bh[2*q][1] = r[1];
                bh[2*q+1][0] = r[2]; bh[2*q+1][1] = r[3];
            }
#pragma unroll
            for (int mt = 0; mt < 4; mt++)
#pragma unroll
                for (int nt = 0; nt < 8; nt++) {
                    mma16816h(acc[mt][nt], ah[mt], bh[nt]);
                    mma16816h(acc[mt][nt], al[mt], bh[nt]);
                }
        }
        __syncthreads();
    }

    int l4 = lane >> 2, l2 = (lane & 3) * 2;
#pragma unroll
    for (int mt = 0; mt < 4; mt++) {
        int gm = m0 + wm * 64 + mt * 16 + l4;
#pragma unroll
        for (int nt = 0; nt < 8; nt++) {
            int gn = n0 + wn * 64 + nt * 8 + l2;
            if (gn < Nact) {
                size_t o0 = (size_t)gm * Nact + gn;
                size_t o1 = (size_t)(gm + 8) * Nact + gn;
                float2 v0 = make_float2(acc[mt][nt][0], acc[mt][nt][1]);
                float2 v1 = make_float2(acc[mt][nt][2], acc[mt][nt][3]);
                if (R) {
                    const float2 r0 = *(const float2*)&R[o0];
                    const float2 r1 = *(const float2*)&R[o1];
                    v0.x += r0.x; v0.y += r0.y; v1.x += r1.x; v1.y += r1.y;
                }
                *(float2*)&C[o0] = v0;
                *(float2*)&C[o1] = v1;
            }
        }
    }
}

// ---------------------------------------------------------------------------
// fp32 -> fp16 hi/lo split (float4-vectorized) and hi-only convert
// ---------------------------------------------------------------------------
__device__ __forceinline__ void split4h_store(__half* hi, __half* lo, int i4, float4 v)
{
    __half2 h0 = __floats2half2_rn(v.x, v.y);
    __half2 h1 = __floats2half2_rn(v.z, v.w);
    float2 f0 = __half22float2(h0);
    float2 f1 = __half22float2(h1);
    __half2 l0 = __floats2half2_rn(v.x - f0.x, v.y - f0.y);
    __half2 l1 = __floats2half2_rn(v.z - f1.x, v.w - f1.y);
    ((uint2*)hi)[i4] = make_uint2(*(uint32_t*)&h0, *(uint32_t*)&h1);
    ((uint2*)lo)[i4] = make_uint2(*(uint32_t*)&l0, *(uint32_t*)&l1);
}

__global__ void split_f16(const float* __restrict__ src,
                          __half* __restrict__ hi, __half* __restrict__ lo, int n4)
{
    int i = blockIdx.x * blockDim.x + threadIdx.x;
    if (i >= n4) return;
    split4h_store(hi, lo, i, ((const float4*)src)[i]);
}

__global__ void conv_hi16(const float* __restrict__ w, __half* __restrict__ hi,
                          int nsrc4, int ntot4)
{
    int i = blockIdx.x * blockDim.x + threadIdx.x;
    if (i >= ntot4) return;
    float4 v = make_float4(0.f, 0.f, 0.f, 0.f);
    if (i < nsrc4) v = ((const float4*)w)[i];
    __half2 h0 = __floats2half2_rn(v.x, v.y);
    __half2 h1 = __floats2half2_rn(v.z, v.w);
    ((uint2*)hi)[i] = make_uint2(*(uint32_t*)&h0, *(uint32_t*)&h1);
}

// ---------------------------------------------------------------------------
__device__ __forceinline__ ull pk2(float x, float y) {
    ull r; asm("mov.b64 %0,{%1,%2};" : "=l"(r) : "f"(x), "f"(y)); return r;
}
__device__ __forceinline__ float2 upk2(ull v) {
    float2 r; asm("mov.b64 {%0,%1},%2;" : "=f"(r.x), "=f"(r.y) : "l"(v)); return r;
}
__device__ __forceinline__ ull f2fma(ull a, ull b, ull c) {
    ull d; asm("fma.rn.f32x2 %0,%1,%2,%3;" : "=l"(d) : "l"(a), "l"(b), "l"(c)); return d;
}
__device__ __forceinline__ ull f2mul(ull a, ull b) {
    ull d; asm("mul.rn.f32x2 %0,%1,%2;" : "=l"(d) : "l"(a), "l"(b)); return d;
}

// ---------------------------------------------------------------------------
// Causal depthwise conv1d + SiLU, float4 over 4 channels
// ---------------------------------------------------------------------------
__global__ void conv_silu(const float* __restrict__ cw, const float* __restrict__ cb)
{
    int idx = blockIdx.x * blockDim.x + threadIdx.x;
    if (idx >= M_TOK * (CONVD / 4)) return;
    int c4 = idx % (CONVD / 4), m = idx / (CONVD / 4);
    int c = c4 * 4;
    int l = m & (LSEQ - 1);
    float4 acc = *(const float4*)&cb[c];
    float4 w0 = ((const float4*)cw)[c];
    float4 w1 = ((const float4*)cw)[c + 1];
    float4 w2 = ((const float4*)cw)[c + 2];
    float4 w3 = ((const float4*)cw)[c + 3];
    const float* wk0 = (const float*)&w0;
    const float* wk1 = (const float*)&w1;
    const float* wk2 = (const float*)&w2;
    const float* wk3 = (const float*)&w3;
#pragma unroll
    for (int k = 0; k < 4; k++) {
        int ll = l - 3 + k;
        if (ll >= 0) {
            float4 xv = *(const float4*)&g_zx[(size_t)(m - 3 + k) * NPROJ + DINNER + c];
            acc.x = fmaf(xv.x, wk0[k], acc.x);
            acc.y = fmaf(xv.y, wk1[k], acc.y);
            acc.z = fmaf(xv.z, wk2[k], acc.z);
            acc.w = fmaf(xv.w, wk3[k], acc.w);
        }
    }
    acc.x *= 1.f / (1.f + __expf(-acc.x));
    acc.y *= 1.f / (1.f + __expf(-acc.y));
    acc.z *= 1.f / (1.f + __expf(-acc.z));
    acc.w *= 1.f / (1.f + __expf(-acc.w));
    *(float4*)&g_xc[(size_t)m * CONVD + c] = acc;
}

// ---------------------------------------------------------------------------
// EXACT fp32 dt path: dt_raw = x_row . Wi[3328+h], then softplus/exp.
// (dt errors are exponentially amplified across the scan; keep fp32-exact.)
// One block per token row; smem-staged x row; warp w handles heads w, w+8, w+16.
// ---------------------------------------------------------------------------
__global__ __launch_bounds__(256)
void dt_exact(const float* __restrict__ x, const float* __restrict__ wi,
              const float* __restrict__ dtb, const float* __restrict__ alog)
{
    __shared__ __align__(16) float xrow[DMODEL];
    int m = blockIdx.x;
    int tid = threadIdx.x;
    if (tid < 192)
        ((float4*)xrow)[tid] = ((const float4*)(x + (size_t)m * DMODEL))[tid];
    __syncthreads();
    int w = tid >> 5, lane = tid & 31;
#pragma unroll
    for (int hh = 0; hh < 3; hh++) {
        int h = w + hh * 8;
        const float4* wr4 = (const float4*)(wi + (size_t)(DINNER + CONVD + h) * DMODEL);
        const float4* xr4 = (const float4*)xrow;
        float dot = 0.f;
#pragma unroll
        for (int j = 0; j < 6; j++) {
            int k = lane + j * 32;
            float4 a = xr4[k], b = wr4[k];
            dot = fmaf(a.x, b.x, fmaf(a.y, b.y, fmaf(a.z, b.z, fmaf(a.w, b.w, dot))));
        }
#pragma unroll
        for (int o = 16; o > 0; o >>= 1) dot += __shfl_xor_sync(0xffffffffu, dot, o);
        if (lane == 0) {
            float v = dot + dtb[h];
            float sp = fmaxf(v, 0.f) + log1pf(expf(-fabsf(v)));
            float A = -expf(alog[h]);
            int b = m / LSEQ, l = m % LSEQ;
            g_dtdA[(size_t)(b * NH + h) * LSEQ + l] = make_float2(sp, expf(sp * A));
        }
    }
}

// ---------------------------------------------------------------------------
// Chunked selective SSM scan (unchanged from Round 9/10).
// ---------------------------------------------------------------------------
#define NSTG 16
#define STGF 336
#define LCH  688

__global__ __launch_bounds__(256, 2)
void scan_kernel(const float* __restrict__ Dv)
{
    __shared__ __align__(16) float sh[NSTG][STGF];
    __shared__ __align__(16) float yb[8][1024];
    uint32_t sb = smem_u32(sh);
    int bc = blockIdx.x;
    int bh = bc % 96;
    int c  = bc / 96;
    int t0 = c * LCH;
    int T  = (c < 2) ? LCH : (LSEQ - 2 * LCH);
    int b = bh / NH, h = bh % NH;
    int tid = threadIdx.x;
    int pg = tid >> 4, nq = tid & 15;
    int xorm = (pg & 1) * 16;
    float dh0 = (nq == 0) ? Dv[h] : 0.f;

    const char* src = nullptr;
    uint32_t dsto = 0;
    size_t stride = (size_t)CONVD * 4;
    const char* xcb = (const char*)(g_xc + ((size_t)b * LSEQ + t0) * CONVD);
    if (tid < 16) {
        src = xcb + (size_t)h * HD * 4 + tid * 16;
        dsto = tid * 16;
    } else if (tid < 48) {
        int t = tid - 16;
        src = xcb + (size_t)DINNER * 4 + t * 16;
        dsto = 256 + (uint32_t)((((t & 1) * 16) + (t >> 1)) * 16);
    } else if (tid < 80) {
        int t = tid - 48;
        src = xcb + (size_t)(DINNER + DST) * 4 + t * 16;
        dsto = 768 + (uint32_t)((((t & 1) * 16) + (t >> 1)) * 16);
    } else if (tid == 80) {
        src = (const char*)(g_dtdA + (size_t)bh * LSEQ + t0);
        dsto = 1280;
        stride = 8;
    }

    auto issue_group = [&](int gq) {
#pragma unroll
        for (int q = 0; q < 4; q++) {
            int step = 4 * gq + q;
            if (step < T && tid <= 80) {
                uint32_t d = sb + (uint32_t)((step & (NSTG - 1)) * (STGF * 4)) + dsto;
                if (tid < 80) cp16(d, src); else cp8(d, src);
                src += stride;
            }
        }
        cp_commit();
    };

    issue_group(0); issue_group(1); issue_group(2);

    ull st[4][4];
#pragma unroll
    for (int pi = 0; pi < 4; pi++)
#pragma unroll
        for (int k = 0; k < 4; k++) st[pi][k] = 0ull;

    float* ybase = g_y + ((size_t)b * LSEQ + t0) * DINNER + h * HD;
    float run = 1.f;
    float* prefp = g_pref + (size_t)bh * LSEQ + t0;

    for (int g = 0; g < T / 4; g++) {
        cp_wait2();
        __syncthreads();
        issue_group(g + 3);

#pragma unroll
        for (int q = 0; q < 4; q++) {
            int l = 4 * g + q;
            const float* bp = sh[l & (NSTG - 1)];
            float4 xv = *(const float4*)(bp + 4 * pg);
            float2 da = *(const float2*)(bp + 320);
            ull dA2 = pk2(da.y, da.y);
            float xs[4] = {xv.x, xv.y, xv.z, xv.w};
            ull dtx2[4];
#pragma unroll
            for (int pi = 0; pi < 4; pi++) {
                float d = da.x * xs[pi];
                dtx2[pi] = pk2(d, d);
            }
            const ulonglong2* B4 = (const ulonglong2*)(bp + 64);
            const ulonglong2* C4 = (const ulonglong2*)(bp + 192);
            ull bb[4], cc[4];
#pragma unroll
            for (int j = 0; j < 2; j++) {
                ulonglong2 bv = B4[j * 16 + nq];
                ulonglong2 cv = C4[j * 16 + nq];
                bb[2*j] = bv.x; bb[2*j+1] = bv.y;
                cc[2*j] = cv.x; cc[2*j+1] = cv.y;
            }
            float* yrow = yb[l & 7] + 64 * pg;
#pragma unroll
            for (int pi = 0; pi < 4; pi++) {
                ull acc2 = 0ull;
#pragma unroll
                for (int k = 0; k < 4; k++) {
                    st[pi][k] = f2fma(st[pi][k], dA2, f2mul(dtx2[pi], bb[k]));
                    acc2 = f2fma(st[pi][k], cc[k], acc2);
                }
                float2 av = upk2(acc2);
                yrow[(16 * pi + nq) ^ xorm] = fmaf(dh0, xs[pi], av.x + av.y);
            }
            if (tid == 255 && c > 0) {
                run *= da.y;
                prefp[l] = run;
            }
        }

        if (g & 1) {
            __syncthreads();
#pragma unroll
            for (int k = 0; k < 2; k++) {
                int o = tid + 256 * k;
                int s_ = o >> 6, p = o & 63;
                int rpg = p >> 2, rpi = p & 3;
                const float4* r4 = (const float4*)(yb[s_] + 64 * rpg
                                                   + (16 * (rpi ^ (rpg & 1))));
                float4 v0 = r4[0], v1 = r4[1], v2 = r4[2], v3 = r4[3];
                float acc = (((v0.x + v0.y) + (v0.z + v0.w))
                           + ((v1.x + v1.y) + (v1.z + v1.w)))
                          + (((v2.x + v2.y) + (v2.z + v2.w))
                           + ((v3.x + v3.y) + (v3.z + v3.w)));
                int l0 = 4 * (g - 1);
                ybase[(size_t)(l0 + s_) * DINNER + p] = acc;
            }
        }
    }

    if (c < 2) {
        float* cs = g_cstate + ((size_t)bh * 2 + c) * 8192;
#pragma unroll
        for (int pi = 0; pi < 4; pi++) {
            int p = 4 * pg + pi;
#pragma unroll
            for (int j = 0; j < 2; j++) {
                float2 a = upk2(st[pi][2*j]);
                float2 d = upk2(st[pi][2*j+1]);
                float4 v = make_float4(a.x, a.y, d.x, d.y);
                *(float4*)(cs + p * 128 + 8 * nq + 4 * j) = v;
            }
        }
    }
}

// ---------------------------------------------------------------------------
// Fix-up (unchanged).
// ---------------------------------------------------------------------------
#define FSTG 16
#define FSTGF 132

__global__ __launch_bounds__(512, 2)
void fixup_kernel()
{
    __shared__ __align__(16) float sh[FSTG][FSTGF];
    __shared__ __align__(16) float yb[8][512];
    uint32_t sb = smem_u32(sh);
    int bx = blockIdx.x;
    int bh = bx % 96;
    int r  = bx / 96;
    int c  = 1 + (r >> 1);
    int half = r & 1;
    int Tc = (c == 1) ? LCH : (LSEQ - 2 * LCH);
    int Th = Tc / 2;
    int t0 = c * LCH + half * Th;
    int b = bh / NH, h = bh % NH;
    int tid = threadIdx.x;
    int p = tid >> 3, nb = tid & 7;

    float q1 = (c == 2) ? g_pref[(size_t)bh * LSEQ + 2 * LCH - 1] : 0.f;
    ull sini[8];
    {
        const float4* s1 = (const float4*)(g_cstate + ((size_t)bh * 2 + (c - 1)) * 8192
                                           + p * 128 + nb * 16);
        const float4* s0 = (const float4*)(g_cstate + ((size_t)bh * 2) * 8192
                                           + p * 128 + nb * 16);
#pragma unroll
        for (int i = 0; i < 4; i++) {
            float4 v = s1[i];
            if (c == 2) {
                float4 w = s0[i];
                v.x = fmaf(q1, w.x, v.x); v.y = fmaf(q1, w.y, v.y);
                v.z = fmaf(q1, w.z, v.z); v.w = fmaf(q1, w.w, v.w);
            }
            sini[2*i]   = pk2(v.x, v.y);
            sini[2*i+1] = pk2(v.z, v.w);
        }
    }

    const char* src = nullptr;
    uint32_t dsto = 0;
    size_t stride = (size_t)CONVD * 4;
    if (tid < 32) {
        src = (const char*)(g_xc + ((size_t)b * LSEQ + t0) * CONVD + DINNER + DST) + tid * 16;
        dsto = (uint32_t)((((tid & 3) * 8) + (tid >> 2)) * 16);
    } else if (tid == 32) {
        src = (const char*)(g_pref + (size_t)bh * LSEQ + t0);
        dsto = 512;
        stride = 4;
    }

    auto issue_group = [&](int gq) {
#pragma unroll
        for (int q = 0; q < 4; q++) {
            int step = 4 * gq + q;
            if (step < Th && tid <= 32) {
                uint32_t d = sb + (uint32_t)((step & (FSTG - 1)) * (FSTGF * 4)) + dsto;
                if (tid < 32) cp16(d, src); else cp4(d, src);
                src += stride;
            }
        }
        cp_commit();
    };
    issue_group(0); issue_group(1); issue_group(2);

    float* ybase = g_y + ((size_t)b * LSEQ + t0) * DINNER + h * HD;
    int rs = tid >> 6, rp = tid & 63;

    for (int g = 0; g < Th / 4; g++) {
        cp_wait2();
        __syncthreads();
        issue_group(g + 3);

#pragma unroll
        for (int q = 0; q < 4; q++) {
            int l = 4 * g + q;
            const float* bp = sh[l & (FSTG - 1)];
            const ulonglong2* C4 = (const ulonglong2*)bp;
            ull cc[8];
#pragma unroll
            for (int j = 0; j < 4; j++) {
                ulonglong2 cv = C4[j * 8 + nb];
                cc[2*j] = cv.x; cc[2*j+1] = cv.y;
            }
            ull acc2 = 0ull;
#pragma unroll
            for (int i = 0; i < 8; i++) acc2 = f2fma(sini[i], cc[i], acc2);
            float2 av = upk2(acc2);
            yb[l & 7][tid] = (av.x + av.y) * bp[128];
        }

        if (g & 1) {
            __syncthreads();
            const float4* r4 = (const float4*)(yb[rs] + rp * 8);
            float4 v0 = r4[0], v1 = r4[1];
            float acc = ((v0.x + v0.y) + (v0.z + v0.w))
                      + ((v1.x + v1.y) + (v1.z + v1.w));
            int l0 = 4 * (g - 1);
            float* yp = ybase + (size_t)(l0 + rs) * DINNER + rp;
            *yp += acc;
        }
    }
}

// ---------------------------------------------------------------------------
// gate + rmsnorm, emits fp16 hi/lo
// ---------------------------------------------------------------------------
__global__ __launch_bounds__(384)
void gate_norm(const float* __restrict__ nw)
{
    __shared__ float warpsum[12];
    __shared__ float stot;
    int m = blockIdx.x;
    int tid = threadIdx.x;
    float4 yv = ((const float4*)(g_y + (size_t)m * DINNER))[tid];
    float4 zv = ((const float4*)(g_zx + (size_t)m * NPROJ))[tid];
    float4 v;
    v.x = yv.x * (zv.x / (1.f + __expf(-zv.x)));
    v.y = yv.y * (zv.y / (1.f + __expf(-zv.y)));
    v.z = yv.z * (zv.z / (1.f + __expf(-zv.z)));
    v.w = yv.w * (zv.w / (1.f + __expf(-zv.w)));
    float ss = fmaf(v.x, v.x, fmaf(v.y, v.y, fmaf(v.z, v.z, v.w * v.w)));
#pragma unroll
    for (int o = 16; o > 0; o >>= 1) ss += __shfl_xor_sync(0xffffffffu, ss, o);
    if ((tid & 31) == 0) warpsum[tid >> 5] = ss;
    __syncthreads();
    if (tid == 0) {
        float t = 0.f;
#pragma unroll
        for (int w = 0; w < 12; w++) t += warpsum[w];
        stot = t;
    }
    __syncthreads();
    float scale = rsqrtf(stot / (float)DINNER + 1e-5f);
    float4 nv = ((const float4*)nw)[tid];
    v.x *= scale * nv.x; v.y *= scale * nv.y;
    v.z *= scale * nv.z; v.w *= scale * nv.w;
    split4h_store(g_Yhi + (size_t)m * DINNER, g_Ylo + (size_t)m * DINNER, tid, v);
}

// ---------------------------------------------------------------------------
extern "C" void kernel_launch(void* const* d_in, const int* in_sizes, int n_in,
                              void* d_out, int out_size)
{
    const float* x    = (const float*)d_in[0];
    const float* wi   = (const float*)d_in[1];
    const float* cw   = (const float*)d_in[2];
    const float* cb   = (const float*)d_in[3];
    const float* dtb  = (const float*)d_in[4];
    const float* alog = (const float*)d_in[5];
    const float* Dv   = (const float*)d_in[6];
    const float* nw   = (const float*)d_in[7];
    const float* wo   = (const float*)d_in[8];
    float* out = (float*)d_out;

    float *zx;
    __half *xhi, *xlo, *wih, *yhi, *ylo, *woh;
    cudaGetSymbolAddress((void**)&zx,  g_zx);
    cudaGetSymbolAddress((void**)&xhi, g_Xhi);
    cudaGetSymbolAddress((void**)&xlo, g_Xlo);
    cudaGetSymbolAddress((void**)&wih, g_Wih);
    cudaGetSymbolAddress((void**)&yhi, g_Yhi);
    cudaGetSymbolAddress((void**)&ylo, g_Ylo);
    cudaGetSymbolAddress((void**)&woh, g_Woh);

    static const int smem_bytes = 2 * STAGE_B;  // 184320 B
    cudaFuncSetAttribute(mma_gemm, cudaFuncAttributeMaxDynamicSharedMemorySize, smem_bytes);

    dim3 blk(256);

    split_f16<<<(M_TOK * DMODEL / 4 + 255) / 256, blk>>>(x, xhi, xlo, M_TOK * DMODEL / 4);
    conv_hi16<<<(NPAD * DMODEL / 4 + 255) / 256, blk>>>(wi, wih,
                                                        NPROJ * DMODEL / 4, NPAD * DMODEL / 4);
    conv_hi16<<<(DMODEL * DINNER / 4 + 255) / 256, blk>>>(wo, woh,
                                                          DMODEL * DINNER / 4, DMODEL * DINNER / 4);

    // in_proj: [8192 x 3352(3456)] = X @ Wi^T  (fp16 2-pass, exact dt separately)
    mma_gemm<<<dim3(NPAD / 128, M_TOK / 256), blk, smem_bytes>>>(
        xhi, xlo, wih, nullptr, zx, NPROJ, DMODEL);

    dt_exact<<<M_TOK, blk>>>(x, wi, dtb, alog);
    conv_silu<<<(M_TOK * (CONVD / 4) + 255) / 256, blk>>>(cw, cb);
    scan_kernel<<<288, 256>>>(Dv);
    fixup_kernel<<<384, 512>>>();
    gate_norm<<<M_TOK, 384>>>(nw);

    // out_proj + residual
    mma_gemm<<<dim3(DMODEL / 128, M_TOK / 256), blk, smem_bytes>>>(
        yhi, ylo, woh, x, out, DMODEL, DINNER);
}

// round 12
// speedup vs baseline: 4.7439x; 1.1879x over previous
#include <cuda_runtime.h>
#include <cuda_fp16.h>
#include <cstdint>

#define M_TOK 8192
#define DMODEL 768
#define DINNER 1536
#define CONVD  1792
#define NH     24
#define HD     64
#define DST    128
#define NPROJ  3352
#define NPAD   3456
#define LSEQ   2048

// ---------------- device scratch (no allocation allowed) ----------------
__device__ float g_zx[M_TOK * NPROJ];    // in_proj output (z | xBC | dt-unused)
__device__ float g_xc[M_TOK * CONVD];    // conv+silu output (xh | B | C)
__device__ float2 g_dtdA[96 * LSEQ];     // packed (dt, dA) per (b*NH+h, l)
__device__ float g_y [M_TOK * DINNER];   // scan output + D skip
__device__ float g_cstate[96 * 2 * 64 * 128];
__device__ float g_pref[96 * LSEQ];

__device__ __half g_Xh[M_TOK * DMODEL];
__device__ __half g_Wih[NPAD * DMODEL];
__device__ __half g_Yh[M_TOK * DINNER];
__device__ __half g_Woh[DMODEL * DINNER];

typedef unsigned long long ull;

__device__ __forceinline__ uint32_t smem_u32(const void* p) {
    uint32_t a;
    asm("{ .reg .u64 t; cvta.to.shared.u64 t, %1; cvt.u32.u64 %0, t; }"
        : "=r"(a) : "l"(p));
    return a;
}

__device__ __forceinline__ void cp16(uint32_t dst, const void* src) {
    asm volatile("cp.async.cg.shared.global [%0], [%1], 16;"
                 :: "r"(dst), "l"(src) : "memory");
}
__device__ __forceinline__ void cp8(uint32_t dst, const void* src) {
    asm volatile("cp.async.ca.shared.global [%0], [%1], 8;"
                 :: "r"(dst), "l"(src) : "memory");
}
__device__ __forceinline__ void cp4(uint32_t dst, const void* src) {
    asm volatile("cp.async.ca.shared.global [%0], [%1], 4;"
                 :: "r"(dst), "l"(src) : "memory");
}
__device__ __forceinline__ void cp_commit() {
    asm volatile("cp.async.commit_group;" ::: "memory");
}
__device__ __forceinline__ void cp_wait0() {
    asm volatile("cp.async.wait_group 0;" ::: "memory");
}
__device__ __forceinline__ void cp_wait1() {
    asm volatile("cp.async.wait_group 1;" ::: "memory");
}
__device__ __forceinline__ void cp_wait2() {
    asm volatile("cp.async.wait_group 2;" ::: "memory");
}

__device__ __forceinline__ void ldmx4(uint32_t* r, uint32_t addr) {
    asm volatile("ldmatrix.sync.aligned.m8n8.x4.shared.b16 {%0,%1,%2,%3}, [%4];"
                 : "=r"(r[0]), "=r"(r[1]), "=r"(r[2]), "=r"(r[3]) : "r"(addr));
}

__device__ __forceinline__ void mma16816h(float* c, const uint32_t* a, const uint32_t* b) {
    asm volatile(
        "mma.sync.aligned.m16n8k16.row.col.f32.f16.f16.f32 "
        "{%0,%1,%2,%3}, {%4,%5,%6,%7}, {%8,%9}, {%0,%1,%2,%3};"
        : "+f"(c[0]), "+f"(c[1]), "+f"(c[2]), "+f"(c[3])
        : "r"(a[0]), "r"(a[1]), "r"(a[2]), "r"(a[3]), "r"(b[0]), "r"(b[1]));
}

// ---------------------------------------------------------------------------
// fp16 1-pass GEMM (NT): C = fp16(A) * fp16(B)^T, fp32 accumulate.
// CTA tile 256x128, 8 warps (4m x 2n, warp tile 64x64), K-chunk 64,
// 2-stage cp.async ring (110.6 KB smem).
// ---------------------------------------------------------------------------
#define BK      64
#define LDT_B   144
#define ROW_A   256
#define ROW_BT  128
#define STAGE_B ((ROW_A + ROW_BT) * LDT_B)   // 55296

__global__ __launch_bounds__(256, 1)
void mma_gemm(const __half* __restrict__ Ah_, const __half* __restrict__ Bh_,
              const float* __restrict__ R, float* __restrict__ C,
              int Nact, int K)
{
    extern __shared__ char smem[];
    uint32_t sb = smem_u32(smem);
    int tid  = threadIdx.x;
    int wid  = tid >> 5, lane = tid & 31;
    int wm   = wid & 3, wn = wid >> 2;        // warp tile 64x64
    int m0   = blockIdx.y * 256, n0 = blockIdx.x * 128;

    const size_t rowK = (size_t)K * 2;

    auto load_stage = [&](int s, int k0) {
        uint32_t d0 = sb + s * STAGE_B;
#pragma unroll
        for (int i = 0; i < 12; i++) {
            int idx = tid + i * 256;
            int row = idx >> 3, ch = idx & 7;
            const char* src;
            if (row < ROW_A)
                src = (const char*)Ah_ + (size_t)(m0 + row) * rowK + k0 * 2;
            else
                src = (const char*)Bh_ + (size_t)(n0 + row - ROW_A) * rowK + k0 * 2;
            cp16(d0 + row * LDT_B + ch * 16, src + ch * 16);
        }
        cp_commit();
    };

    float acc[4][8][4];
#pragma unroll
    for (int mt = 0; mt < 4; mt++)
#pragma unroll
        for (int nt = 0; nt < 8; nt++)
#pragma unroll
            for (int j = 0; j < 4; j++) acc[mt][nt][j] = 0.f;

    int nch = K / BK;
    load_stage(0, 0);

    int a_row = wm * 64 + (lane & 7) + ((lane >> 3) & 1) * 8;
    int a_cb  = ((lane >> 4) & 1) * 16;
    int b_row = wn * 64 + ((lane >> 4) & 1) * 8 + (lane & 7);
    int b_cb  = ((lane >> 3) & 1) * 16;

    for (int c = 0; c < nch; c++) {
        if (c + 1 < nch) { load_stage((c + 1) & 1, (c + 1) * BK); cp_wait1(); }
        else             { cp_wait0(); }
        __syncthreads();

        uint32_t st = sb + (c & 1) * STAGE_B;
        uint32_t Ah = st;
        uint32_t Bh = st + ROW_A * LDT_B;

#pragma unroll
        for (int kk = 0; kk < 4; kk++) {
            int kb = kk * 32;
            uint32_t ah[4][4];
#pragma unroll
            for (int mt = 0; mt < 4; mt++) {
                uint32_t off = (uint32_t)((a_row + mt * 16) * LDT_B + kb + a_cb);
                ldmx4(ah[mt], Ah + off);
            }
            uint32_t bh[8][2];
#pragma unroll
            for (int q = 0; q < 4; q++) {
                uint32_t off = (uint32_t)((b_row + q * 16) * LDT_B + kb + b_cb);
                uint32_t r[4];
                ldmx4(r, Bh + off);
                bh[2*q][0] = r[0]; bh[2*q][1] = r[1];
                bh[2*q+1][0] = r[2]; bh[2*q+1][1] = r[3];
            }
#pragma unroll
            for (int mt = 0; mt < 4; mt++)
#pragma unroll
                for (int nt = 0; nt < 8; nt++)
                    mma16816h(acc[mt][nt], ah[mt], bh[nt]);
        }
        __syncthreads();
    }

    int l4 = lane >> 2, l2 = (lane & 3) * 2;
#pragma unroll
    for (int mt = 0; mt < 4; mt++) {
        int gm = m0 + wm * 64 + mt * 16 + l4;
#pragma unroll
        for (int nt = 0; nt < 8; nt++) {
            int gn = n0 + wn * 64 + nt * 8 + l2;
            if (gn < Nact) {
                size_t o0 = (size_t)gm * Nact + gn;
                size_t o1 = (size_t)(gm + 8) * Nact + gn;
                float2 v0 = make_float2(acc[mt][nt][0], acc[mt][nt][1]);
                float2 v1 = make_float2(acc[mt][nt][2], acc[mt][nt][3]);
                if (R) {
                    const float2 r0 = *(const float2*)&R[o0];
                    const float2 r1 = *(const float2*)&R[o1];
                    v0.x += r0.x; v0.y += r0.y; v1.x += r1.x; v1.y += r1.y;
                }
                *(float2*)&C[o0] = v0;
                *(float2*)&C[o1] = v1;
            }
        }
    }
}

// ---------------------------------------------------------------------------
// fp32 -> fp16 convert (float4-vectorized, zero-padded)
// ---------------------------------------------------------------------------
__global__ void conv_hi16(const float* __restrict__ w, __half* __restrict__ hi,
                          int nsrc4, int ntot4)
{
    int i = blockIdx.x * blockDim.x + threadIdx.x;
    if (i >= ntot4) return;
    float4 v = make_float4(0.f, 0.f, 0.f, 0.f);
    if (i < nsrc4) v = ((const float4*)w)[i];
    __half2 h0 = __floats2half2_rn(v.x, v.y);
    __half2 h1 = __floats2half2_rn(v.z, v.w);
    ((uint2*)hi)[i] = make_uint2(*(uint32_t*)&h0, *(uint32_t*)&h1);
}

// ---------------------------------------------------------------------------
__device__ __forceinline__ ull pk2(float x, float y) {
    ull r; asm("mov.b64 %0,{%1,%2};" : "=l"(r) : "f"(x), "f"(y)); return r;
}
__device__ __forceinline__ float2 upk2(ull v) {
    float2 r; asm("mov.b64 {%0,%1},%2;" : "=f"(r.x), "=f"(r.y) : "l"(v)); return r;
}
__device__ __forceinline__ ull f2fma(ull a, ull b, ull c) {
    ull d; asm("fma.rn.f32x2 %0,%1,%2,%3;" : "=l"(d) : "l"(a), "l"(b), "l"(c)); return d;
}
__device__ __forceinline__ ull f2mul(ull a, ull b) {
    ull d; asm("mul.rn.f32x2 %0,%1,%2;" : "=l"(d) : "l"(a), "l"(b)); return d;
}

// ---------------------------------------------------------------------------
// Causal depthwise conv1d + SiLU, float4 over 4 channels
// ---------------------------------------------------------------------------
__global__ void conv_silu(const float* __restrict__ cw, const float* __restrict__ cb)
{
    int idx = blockIdx.x * blockDim.x + threadIdx.x;
    if (idx >= M_TOK * (CONVD / 4)) return;
    int c4 = idx % (CONVD / 4), m = idx / (CONVD / 4);
    int c = c4 * 4;
    int l = m & (LSEQ - 1);
    float4 acc = *(const float4*)&cb[c];
    float4 w0 = ((const float4*)cw)[c];
    float4 w1 = ((const float4*)cw)[c + 1];
    float4 w2 = ((const float4*)cw)[c + 2];
    float4 w3 = ((const float4*)cw)[c + 3];
    const float* wk0 = (const float*)&w0;
    const float* wk1 = (const float*)&w1;
    const float* wk2 = (const float*)&w2;
    const float* wk3 = (const float*)&w3;
#pragma unroll
    for (int k = 0; k < 4; k++) {
        int ll = l - 3 + k;
        if (ll >= 0) {
            float4 xv = *(const float4*)&g_zx[(size_t)(m - 3 + k) * NPROJ + DINNER + c];
            acc.x = fmaf(xv.x, wk0[k], acc.x);
            acc.y = fmaf(xv.y, wk1[k], acc.y);
            acc.z = fmaf(xv.z, wk2[k], acc.z);
            acc.w = fmaf(xv.w, wk3[k], acc.w);
        }
    }
    acc.x *= 1.f / (1.f + __expf(-acc.x));
    acc.y *= 1.f / (1.f + __expf(-acc.y));
    acc.z *= 1.f / (1.f + __expf(-acc.z));
    acc.w *= 1.f / (1.f + __expf(-acc.w));
    *(float4*)&g_xc[(size_t)m * CONVD + c] = acc;
}

// ---------------------------------------------------------------------------
// EXACT fp32 dt path (dt errors amplify exponentially in the scan).
// ---------------------------------------------------------------------------
__global__ __launch_bounds__(256)
void dt_exact(const float* __restrict__ x, const float* __restrict__ wi,
              const float* __restrict__ dtb, const float* __restrict__ alog)
{
    __shared__ __align__(16) float xrow[DMODEL];
    int m = blockIdx.x;
    int tid = threadIdx.x;
    if (tid < 192)
        ((float4*)xrow)[tid] = ((const float4*)(x + (size_t)m * DMODEL))[tid];
    __syncthreads();
    int w = tid >> 5, lane = tid & 31;
#pragma unroll
    for (int hh = 0; hh < 3; hh++) {
        int h = w + hh * 8;
        const float4* wr4 = (const float4*)(wi + (size_t)(DINNER + CONVD + h) * DMODEL);
        const float4* xr4 = (const float4*)xrow;
        float dot = 0.f;
#pragma unroll
        for (int j = 0; j < 6; j++) {
            int k = lane + j * 32;
            float4 a = xr4[k], b = wr4[k];
            dot = fmaf(a.x, b.x, fmaf(a.y, b.y, fmaf(a.z, b.z, fmaf(a.w, b.w, dot))));
        }
#pragma unroll
        for (int o = 16; o > 0; o >>= 1) dot += __shfl_xor_sync(0xffffffffu, dot, o);
        if (lane == 0) {
            float v = dot + dtb[h];
            float sp = fmaxf(v, 0.f) + log1pf(expf(-fabsf(v)));
            float A = -expf(alog[h]);
            int b = m / LSEQ, l = m % LSEQ;
            g_dtdA[(size_t)(b * NH + h) * LSEQ + l] = make_float2(sp, expf(sp * A));
        }
    }
}

// ---------------------------------------------------------------------------
// Chunked selective SSM scan (unchanged).
// ---------------------------------------------------------------------------
#define NSTG 16
#define STGF 336
#define LCH  688

__global__ __launch_bounds__(256, 2)
void scan_kernel(const float* __restrict__ Dv)
{
    __shared__ __align__(16) float sh[NSTG][STGF];
    __shared__ __align__(16) float yb[8][1024];
    uint32_t sb = smem_u32(sh);
    int bc = blockIdx.x;
    int bh = bc % 96;
    int c  = bc / 96;
    int t0 = c * LCH;
    int T  = (c < 2) ? LCH : (LSEQ - 2 * LCH);
    int b = bh / NH, h = bh % NH;
    int tid = threadIdx.x;
    int pg = tid >> 4, nq = tid & 15;
    int xorm = (pg & 1) * 16;
    float dh0 = (nq == 0) ? Dv[h] : 0.f;

    const char* src = nullptr;
    uint32_t dsto = 0;
    size_t stride = (size_t)CONVD * 4;
    const char* xcb = (const char*)(g_xc + ((size_t)b * LSEQ + t0) * CONVD);
    if (tid < 16) {
        src = xcb + (size_t)h * HD * 4 + tid * 16;
        dsto = tid * 16;
    } else if (tid < 48) {
        int t = tid - 16;
        src = xcb + (size_t)DINNER * 4 + t * 16;
        dsto = 256 + (uint32_t)((((t & 1) * 16) + (t >> 1)) * 16);
    } else if (tid < 80) {
        int t = tid - 48;
        src = xcb + (size_t)(DINNER + DST) * 4 + t * 16;
        dsto = 768 + (uint32_t)((((t & 1) * 16) + (t >> 1)) * 16);
    } else if (tid == 80) {
        src = (const char*)(g_dtdA + (size_t)bh * LSEQ + t0);
        dsto = 1280;
        stride = 8;
    }

    auto issue_group = [&](int gq) {
#pragma unroll
        for (int q = 0; q < 4; q++) {
            int step = 4 * gq + q;
            if (step < T && tid <= 80) {
                uint32_t d = sb + (uint32_t)((step & (NSTG - 1)) * (STGF * 4)) + dsto;
                if (tid < 80) cp16(d, src); else cp8(d, src);
                src += stride;
            }
        }
        cp_commit();
    };

    issue_group(0); issue_group(1); issue_group(2);

    ull st[4][4];
#pragma unroll
    for (int pi = 0; pi < 4; pi++)
#pragma unroll
        for (int k = 0; k < 4; k++) st[pi][k] = 0ull;

    float* ybase = g_y + ((size_t)b * LSEQ + t0) * DINNER + h * HD;
    float run = 1.f;
    float* prefp = g_pref + (size_t)bh * LSEQ + t0;

    for (int g = 0; g < T / 4; g++) {
        cp_wait2();
        __syncthreads();
        issue_group(g + 3);

#pragma unroll
        for (int q = 0; q < 4; q++) {
            int l = 4 * g + q;
            const float* bp = sh[l & (NSTG - 1)];
            float4 xv = *(const float4*)(bp + 4 * pg);
            float2 da = *(const float2*)(bp + 320);
            ull dA2 = pk2(da.y, da.y);
            float xs[4] = {xv.x, xv.y, xv.z, xv.w};
            ull dtx2[4];
#pragma unroll
            for (int pi = 0; pi < 4; pi++) {
                float d = da.x * xs[pi];
                dtx2[pi] = pk2(d, d);
            }
            const ulonglong2* B4 = (const ulonglong2*)(bp + 64);
            const ulonglong2* C4 = (const ulonglong2*)(bp + 192);
            ull bb[4], cc[4];
#pragma unroll
            for (int j = 0; j < 2; j++) {
                ulonglong2 bv = B4[j * 16 + nq];
                ulonglong2 cv = C4[j * 16 + nq];
                bb[2*j] = bv.x; bb[2*j+1] = bv.y;
                cc[2*j] = cv.x; cc[2*j+1] = cv.y;
            }
            float* yrow = yb[l & 7] + 64 * pg;
#pragma unroll
            for (int pi = 0; pi < 4; pi++) {
                ull acc2 = 0ull;
#pragma unroll
                for (int k = 0; k < 4; k++) {
                    st[pi][k] = f2fma(st[pi][k], dA2, f2mul(dtx2[pi], bb[k]));
                    acc2 = f2fma(st[pi][k], cc[k], acc2);
                }
                float2 av = upk2(acc2);
                yrow[(16 * pi + nq) ^ xorm] = fmaf(dh0, xs[pi], av.x + av.y);
            }
            if (tid == 255 && c > 0) {
                run *= da.y;
                prefp[l] = run;
            }
        }

        if (g & 1) {
            __syncthreads();
#pragma unroll
            for (int k = 0; k < 2; k++) {
                int o = tid + 256 * k;
                int s_ = o >> 6, p = o & 63;
                int rpg = p >> 2, rpi = p & 3;
                const float4* r4 = (const float4*)(yb[s_] + 64 * rpg
                                                   + (16 * (rpi ^ (rpg & 1))));
                float4 v0 = r4[0], v1 = r4[1], v2 = r4[2], v3 = r4[3];
                float acc = (((v0.x + v0.y) + (v0.z + v0.w))
                           + ((v1.x + v1.y) + (v1.z + v1.w)))
                          + (((v2.x + v2.y) + (v2.z + v2.w))
                           + ((v3.x + v3.y) + (v3.z + v3.w)));
                int l0 = 4 * (g - 1);
                ybase[(size_t)(l0 + s_) * DINNER + p] = acc;
            }
        }
    }

    if (c < 2) {
        float* cs = g_cstate + ((size_t)bh * 2 + c) * 8192;
#pragma unroll
        for (int pi = 0; pi < 4; pi++) {
            int p = 4 * pg + pi;
#pragma unroll
            for (int j = 0; j < 2; j++) {
                float2 a = upk2(st[pi][2*j]);
                float2 d = upk2(st[pi][2*j+1]);
                float4 v = make_float4(a.x, a.y, d.x, d.y);
                *(float4*)(cs + p * 128 + 8 * nq + 4 * j) = v;
            }
        }
    }
}

// ---------------------------------------------------------------------------
// Fix-up (unchanged).
// ---------------------------------------------------------------------------
#define FSTG 16
#define FSTGF 132

__global__ __launch_bounds__(512, 2)
void fixup_kernel()
{
    __shared__ __align__(16) float sh[FSTG][FSTGF];
    __shared__ __align__(16) float yb[8][512];
    uint32_t sb = smem_u32(sh);
    int bx = blockIdx.x;
    int bh = bx % 96;
    int r  = bx / 96;
    int c  = 1 + (r >> 1);
    int half = r & 1;
    int Tc = (c == 1) ? LCH : (LSEQ - 2 * LCH);
    int Th = Tc / 2;
    int t0 = c * LCH + half * Th;
    int b = bh / NH, h = bh % NH;
    int tid = threadIdx.x;
    int p = tid >> 3, nb = tid & 7;

    float q1 = (c == 2) ? g_pref[(size_t)bh * LSEQ + 2 * LCH - 1] : 0.f;
    ull sini[8];
    {
        const float4* s1 = (const float4*)(g_cstate + ((size_t)bh * 2 + (c - 1)) * 8192
                                           + p * 128 + nb * 16);
        const float4* s0 = (const float4*)(g_cstate + ((size_t)bh * 2) * 8192
                                           + p * 128 + nb * 16);
#pragma unroll
        for (int i = 0; i < 4; i++) {
            float4 v = s1[i];
            if (c == 2) {
                float4 w = s0[i];
                v.x = fmaf(q1, w.x, v.x); v.y = fmaf(q1, w.y, v.y);
                v.z = fmaf(q1, w.z, v.z); v.w = fmaf(q1, w.w, v.w);
            }
            sini[2*i]   = pk2(v.x, v.y);
            sini[2*i+1] = pk2(v.z, v.w);
        }
    }

    const char* src = nullptr;
    uint32_t dsto = 0;
    size_t stride = (size_t)CONVD * 4;
    if (tid < 32) {
        src = (const char*)(g_xc + ((size_t)b * LSEQ + t0) * CONVD + DINNER + DST) + tid * 16;
        dsto = (uint32_t)((((tid & 3) * 8) + (tid >> 2)) * 16);
    } else if (tid == 32) {
        src = (const char*)(g_pref + (size_t)bh * LSEQ + t0);
        dsto = 512;
        stride = 4;
    }

    auto issue_group = [&](int gq) {
#pragma unroll
        for (int q = 0; q < 4; q++) {
            int step = 4 * gq + q;
            if (step < Th && tid <= 32) {
                uint32_t d = sb + (uint32_t)((step & (FSTG - 1)) * (FSTGF * 4)) + dsto;
                if (tid < 32) cp16(d, src); else cp4(d, src);
                src += stride;
            }
        }
        cp_commit();
    };
    issue_group(0); issue_group(1); issue_group(2);

    float* ybase = g_y + ((size_t)b * LSEQ + t0) * DINNER + h * HD;
    int rs = tid >> 6, rp = tid & 63;

    for (int g = 0; g < Th / 4; g++) {
        cp_wait2();
        __syncthreads();
        issue_group(g + 3);

#pragma unroll
        for (int q = 0; q < 4; q++) {
            int l = 4 * g + q;
            const float* bp = sh[l & (FSTG - 1)];
            const ulonglong2* C4 = (const ulonglong2*)bp;
            ull cc[8];
#pragma unroll
            for (int j = 0; j < 4; j++) {
                ulonglong2 cv = C4[j * 8 + nb];
                cc[2*j] = cv.x; cc[2*j+1] = cv.y;
            }
            ull acc2 = 0ull;
#pragma unroll
            for (int i = 0; i < 8; i++) acc2 = f2fma(sini[i], cc[i], acc2);
            float2 av = upk2(acc2);
            yb[l & 7][tid] = (av.x + av.y) * bp[128];
        }

        if (g & 1) {
            __syncthreads();
            const float4* r4 = (const float4*)(yb[rs] + rp * 8);
            float4 v0 = r4[0], v1 = r4[1];
            float acc = ((v0.x + v0.y) + (v0.z + v0.w))
                      + ((v1.x + v1.y) + (v1.z + v1.w));
            int l0 = 4 * (g - 1);
            float* yp = ybase + (size_t)(l0 + rs) * DINNER + rp;
            *yp += acc;
        }
    }
}

// ---------------------------------------------------------------------------
// gate + rmsnorm, emits fp16 (hi only)
// ---------------------------------------------------------------------------
__global__ __launch_bounds__(384)
void gate_norm(const float* __restrict__ nw)
{
    __shared__ float warpsum[12];
    __shared__ float stot;
    int m = blockIdx.x;
    int tid = threadIdx.x;
    float4 yv = ((const float4*)(g_y + (size_t)m * DINNER))[tid];
    float4 zv = ((const float4*)(g_zx + (size_t)m * NPROJ))[tid];
    float4 v;
    v.x = yv.x * (zv.x / (1.f + __expf(-zv.x)));
    v.y = yv.y * (zv.y / (1.f + __expf(-zv.y)));
    v.z = yv.z * (zv.z / (1.f + __expf(-zv.z)));
    v.w = yv.w * (zv.w / (1.f + __expf(-zv.w)));
    float ss = fmaf(v.x, v.x, fmaf(v.y, v.y, fmaf(v.z, v.z, v.w * v.w)));
#pragma unroll
    for (int o = 16; o > 0; o >>= 1) ss += __shfl_xor_sync(0xffffffffu, ss, o);
    if ((tid & 31) == 0) warpsum[tid >> 5] = ss;
    __syncthreads();
    if (tid == 0) {
        float t = 0.f;
#pragma unroll
        for (int w = 0; w < 12; w++) t += warpsum[w];
        stot = t;
    }
    __syncthreads();
    float scale = rsqrtf(stot / (float)DINNER + 1e-5f);
    float4 nv = ((const float4*)nw)[tid];
    v.x *= scale * nv.x; v.y *= scale * nv.y;
    v.z *= scale * nv.z; v.w *= scale * nv.w;
    __half2 h0 = __floats2half2_rn(v.x, v.y);
    __half2 h1 = __floats2half2_rn(v.z, v.w);
    ((uint2*)(g_Yh + (size_t)m * DINNER))[tid] =
        make_uint2(*(uint32_t*)&h0, *(uint32_t*)&h1);
}

// ---------------------------------------------------------------------------
extern "C" void kernel_launch(void* const* d_in, const int* in_sizes, int n_in,
                              void* d_out, int out_size)
{
    const float* x    = (const float*)d_in[0];
    const float* wi   = (const float*)d_in[1];
    const float* cw   = (const float*)d_in[2];
    const float* cb   = (const float*)d_in[3];
    const float* dtb  = (const float*)d_in[4];
    const float* alog = (const float*)d_in[5];
    const float* Dv   = (const float*)d_in[6];
    const float* nw   = (const float*)d_in[7];
    const float* wo   = (const float*)d_in[8];
    float* out = (float*)d_out;

    float *zx;
    __half *xh, *wih, *yh, *woh;
    cudaGetSymbolAddress((void**)&zx,  g_zx);
    cudaGetSymbolAddress((void**)&xh,  g_Xh);
    cudaGetSymbolAddress((void**)&wih, g_Wih);
    cudaGetSymbolAddress((void**)&yh,  g_Yh);
    cudaGetSymbolAddress((void**)&woh, g_Woh);

    static const int smem_bytes = 2 * STAGE_B;  // 110592 B
    cudaFuncSetAttribute(mma_gemm, cudaFuncAttributeMaxDynamicSharedMemorySize, smem_bytes);

    dim3 blk(256);

    conv_hi16<<<(M_TOK * DMODEL / 4 + 255) / 256, blk>>>(x, xh,
                                                         M_TOK * DMODEL / 4, M_TOK * DMODEL / 4);
    conv_hi16<<<(NPAD * DMODEL / 4 + 255) / 256, blk>>>(wi, wih,
                                                        NPROJ * DMODEL / 4, NPAD * DMODEL / 4);
    conv_hi16<<<(DMODEL * DINNER / 4 + 255) / 256, blk>>>(wo, woh,
                                                          DMODEL * DINNER / 4, DMODEL * DINNER / 4);

    // in_proj (fp16 1-pass; dt recomputed exactly below)
    mma_gemm<<<dim3(NPAD / 128, M_TOK / 256), blk, smem_bytes>>>(
        xh, wih, nullptr, zx, NPROJ, DMODEL);

    dt_exact<<<M_TOK, blk>>>(x, wi, dtb, alog);
    conv_silu<<<(M_TOK * (CONVD / 4) + 255) / 256, blk>>>(cw, cb);
    scan_kernel<<<288, 256>>>(Dv);
    fixup_kernel<<<384, 512>>>();
    gate_norm<<<M_TOK, 384>>>(nw);

    // out_proj + residual (fp16 1-pass)
    mma_gemm<<<dim3(DMODEL / 128, M_TOK / 256), blk, smem_bytes>>>(
        yh, woh, x, out, DMODEL, DINNER);
}